// round 1
// baseline (speedup 1.0000x reference)
#include <cuda_runtime.h>
#include <math.h>

// Problem constants
constexpr int TT = 12;
constexpr int NN = 50000;
constexpr int FF = 32;
constexpr int HH = 64;
constexpr int EE = 1600000;
constexpr int ROWS = TT * NN;     // 600000

// ---------------- static device scratch (no allocations allowed) -----------
__device__ int    g_degi[NN];
__device__ int    g_cursor[NN];
__device__ float  g_dinv[NN];
__device__ float  g_invdeg[NN];
__device__ int    g_rowptr[NN + 1];
__device__ int    g_csrc[EE];
__device__ float  g_cw[EE];
__device__ float4 g_bufA4[(size_t)ROWS * HH / 4];        // 153.6 MB
__device__ float4 g_bufB4[(size_t)ROWS * HH / 4];        // 153.6 MB
__device__ float4 g_gi4[(size_t)ROWS * 3 * HH / 4];      // 460.8 MB
__device__ float4 g_h0_4[(size_t)NN * HH / 4];
__device__ float4 g_h1_4[(size_t)NN * HH / 4];

#define BUFA ((float*)g_bufA4)
#define BUFB ((float*)g_bufB4)
#define GIP  ((float*)g_gi4)
#define H0P  ((float*)g_h0_4)
#define H1P  ((float*)g_h1_4)

// ---------------- packed f32x2 FMA (sm_10x) --------------------------------
union F2U { float2 f; unsigned long long u; };
__device__ __forceinline__ float2 ffma2(float2 a, float2 b, float2 c) {
    F2U A, B, C, D; A.f = a; B.f = b; C.f = c;
    asm("fma.rn.f32x2 %0, %1, %2, %3;" : "=l"(D.u) : "l"(A.u), "l"(B.u), "l"(C.u));
    return D.f;
}
__device__ __forceinline__ float sigf(float x) { return 1.f / (1.f + expf(-x)); }

// ---------------- setup kernels --------------------------------------------
__global__ void k_init() {
    int i = blockIdx.x * blockDim.x + threadIdx.x;
    if (i < NN) { g_degi[i] = 0; g_cursor[i] = 0; }
    if (i < NN * HH / 4) g_h0_4[i] = make_float4(0.f, 0.f, 0.f, 0.f);
}

__global__ void k_count(const int* __restrict__ dst, int E) {
    int e = blockIdx.x * blockDim.x + threadIdx.x;
    if (e < E) atomicAdd(&g_degi[dst[e]], 1);
}

__global__ void k_norm() {
    int i = blockIdx.x * blockDim.x + threadIdx.x;
    if (i < NN) {
        float deg = (float)g_degi[i] + 1.0f;
        g_dinv[i] = 1.0f / sqrtf(deg);
        g_invdeg[i] = 1.0f / deg;
    }
}

__global__ void k_scan() {     // single-block exclusive scan of g_degi -> g_rowptr
    __shared__ int sh[1024];
    int t = threadIdx.x;
    const int C = (NN + 1023) / 1024;
    int base = t * C, s = 0;
    for (int i = 0; i < C; i++) { int idx = base + i; if (idx < NN) s += g_degi[idx]; }
    sh[t] = s; __syncthreads();
    for (int off = 1; off < 1024; off <<= 1) {
        int v = (t >= off) ? sh[t - off] : 0;
        __syncthreads();
        sh[t] += v;
        __syncthreads();
    }
    int excl = sh[t] - s;
    int run = excl;
    for (int i = 0; i < C; i++) {
        int idx = base + i;
        if (idx < NN) { g_rowptr[idx] = run; run += g_degi[idx]; }
    }
    if (t == 0) g_rowptr[NN] = sh[1023];
}

__global__ void k_fill(const int* __restrict__ src, const int* __restrict__ dst, int E) {
    int e = blockIdx.x * blockDim.x + threadIdx.x;
    if (e < E) {
        int s = src[e], d = dst[e];
        float w = g_dinv[s] * g_dinv[d];
        int pos = g_rowptr[d] + atomicAdd(&g_cursor[d], 1);
        g_csrc[pos] = s;
        g_cw[pos] = w;
    }
}

// ---------------- aggregation: out = Ahat * in ------------------------------
// 32-wide (layer-1 on raw x). warp per (t,n); lane = column.
__global__ __launch_bounds__(256) void k_agg32(const float* __restrict__ x) {
    int t = blockIdx.y;
    int lane = threadIdx.x & 31;
    int n = blockIdx.x * 8 + (threadIdx.x >> 5);
    if (n >= NN) return;
    const float* xin = x + (size_t)t * NN * FF;
    float* outp = BUFA + (size_t)t * NN * FF;
    int r0 = g_rowptr[n], r1 = g_rowptr[n + 1];
    float acc = 0.f;
    int base = r0;
    for (; base + 32 <= r1; base += 32) {
        int sv = g_csrc[base + lane];
        float wv = g_cw[base + lane];
        #pragma unroll
        for (int k = 0; k < 32; k++) {
            int ss = __shfl_sync(0xffffffffu, sv, k);
            float ww = __shfl_sync(0xffffffffu, wv, k);
            acc = fmaf(ww, xin[(size_t)ss * FF + lane], acc);
        }
    }
    if (base < r1) {
        int sv = 0; float wv = 0.f;
        if (base + lane < r1) { sv = g_csrc[base + lane]; wv = g_cw[base + lane]; }
        int cnt = r1 - base;
        for (int k = 0; k < cnt; k++) {
            int ss = __shfl_sync(0xffffffffu, sv, k);
            float ww = __shfl_sync(0xffffffffu, wv, k);
            acc = fmaf(ww, xin[(size_t)ss * FF + lane], acc);
        }
    }
    acc = fmaf(g_invdeg[n], xin[(size_t)n * FF + lane], acc);
    outp[(size_t)n * FF + lane] = acc;
}

// 64-wide (layer-2): reads BUFB, writes BUFA. lane handles float2 (2 cols).
__global__ __launch_bounds__(256) void k_agg64() {
    int t = blockIdx.y;
    int lane = threadIdx.x & 31;
    int n = blockIdx.x * 8 + (threadIdx.x >> 5);
    if (n >= NN) return;
    const float2* inT = (const float2*)(BUFB + (size_t)t * NN * HH);
    float2* outT = (float2*)(BUFA + (size_t)t * NN * HH);
    int r0 = g_rowptr[n], r1 = g_rowptr[n + 1];
    float2 acc = make_float2(0.f, 0.f);
    int base = r0;
    for (; base + 32 <= r1; base += 32) {
        int sv = g_csrc[base + lane];
        float wv = g_cw[base + lane];
        #pragma unroll
        for (int k = 0; k < 32; k++) {
            int ss = __shfl_sync(0xffffffffu, sv, k);
            float ww = __shfl_sync(0xffffffffu, wv, k);
            float2 v = inT[(size_t)ss * 32 + lane];
            acc = ffma2(make_float2(ww, ww), v, acc);
        }
    }
    if (base < r1) {
        int sv = 0; float wv = 0.f;
        if (base + lane < r1) { sv = g_csrc[base + lane]; wv = g_cw[base + lane]; }
        int cnt = r1 - base;
        for (int k = 0; k < cnt; k++) {
            int ss = __shfl_sync(0xffffffffu, sv, k);
            float ww = __shfl_sync(0xffffffffu, wv, k);
            float2 v = inT[(size_t)ss * 32 + lane];
            acc = ffma2(make_float2(ww, ww), v, acc);
        }
    }
    float2 hv = inT[(size_t)n * 32 + lane];
    float id = g_invdeg[n];
    acc = ffma2(make_float2(id, id), hv, acc);
    outT[(size_t)n * 32 + lane] = acc;
}

// ---------------- dense: out = relu(in @ W + b), BUFA -> BUFB ---------------
template <int FI>
__global__ __launch_bounds__(256) void k_gemm_relu(const float* __restrict__ W,
                                                   const float* __restrict__ b) {
    __shared__ float2 Wsm[FI * 32];
    __shared__ float2 Bsm[32];
    int tid = threadIdx.x;
    for (int i = tid; i < FI * 32; i += 256) {
        int f = i >> 5, p = i & 31;
        Wsm[i] = make_float2(W[f * 64 + p], W[f * 64 + p + 32]);
    }
    if (tid < 32) Bsm[tid] = make_float2(b[tid], b[tid + 32]);
    __syncthreads();
    int lane = tid & 31;
    for (int row = blockIdx.x * 8 + (tid >> 5); row < ROWS; row += gridDim.x * 8) {
        const float* xr = BUFA + (size_t)row * FI;
        float x0 = xr[lane];
        float x1 = (FI == 64) ? xr[lane + 32] : 0.f;
        float2 acc = Bsm[lane];
        #pragma unroll
        for (int f = 0; f < 32; f++) {
            float xv = __shfl_sync(0xffffffffu, x0, f);
            acc = ffma2(make_float2(xv, xv), Wsm[f * 32 + lane], acc);
        }
        if (FI == 64) {
            #pragma unroll
            for (int f = 0; f < 32; f++) {
                float xv = __shfl_sync(0xffffffffu, x1, f);
                acc = ffma2(make_float2(xv, xv), Wsm[(f + 32) * 32 + lane], acc);
            }
        }
        float* o = BUFB + (size_t)row * 64;
        o[lane] = fmaxf(acc.x, 0.f);
        o[lane + 32] = fmaxf(acc.y, 0.f);
    }
}

// ---------------- gi = BUFB @ W_ih^T + b_ih  -> GIP -------------------------
// warp handles 4 rows; lane computes gate outputs {lane,+32},{+64,+96},{+128,+160}
__global__ __launch_bounds__(256) void k_gi(const float* __restrict__ Wih,
                                            const float* __restrict__ bih) {
    __shared__ float2 Wsm[64 * 96];   // 48KB: Wsm[h*96 + p*32 + l] = (W[p*64+l][h], W[p*64+l+32][h])
    int tid = threadIdx.x;
    for (int i = tid; i < 64 * 96; i += 256) {
        int h = i / 96, m = i % 96, p = m >> 5, l = m & 31;
        Wsm[i] = make_float2(Wih[(p * 64 + l) * 64 + h], Wih[(p * 64 + l + 32) * 64 + h]);
    }
    __syncthreads();
    int lane = tid & 31;
    float2 bias[3];
    #pragma unroll
    for (int p = 0; p < 3; p++)
        bias[p] = make_float2(bih[p * 64 + lane], bih[p * 64 + lane + 32]);
    for (int tile = blockIdx.x * 8 + (tid >> 5); tile < ROWS / 4; tile += gridDim.x * 8) {
        int row0 = tile * 4;
        float xa[4], xb[4];
        #pragma unroll
        for (int r = 0; r < 4; r++) {
            xa[r] = BUFB[(size_t)(row0 + r) * 64 + lane];
            xb[r] = BUFB[(size_t)(row0 + r) * 64 + 32 + lane];
        }
        float2 acc[4][3];
        #pragma unroll
        for (int r = 0; r < 4; r++)
            #pragma unroll
            for (int p = 0; p < 3; p++) acc[r][p] = bias[p];
        #pragma unroll 8
        for (int h = 0; h < 32; h++) {
            float2 w0 = Wsm[h * 96 + lane], w1 = Wsm[h * 96 + 32 + lane], w2 = Wsm[h * 96 + 64 + lane];
            #pragma unroll
            for (int r = 0; r < 4; r++) {
                float xv = __shfl_sync(0xffffffffu, xa[r], h);
                float2 xv2 = make_float2(xv, xv);
                acc[r][0] = ffma2(xv2, w0, acc[r][0]);
                acc[r][1] = ffma2(xv2, w1, acc[r][1]);
                acc[r][2] = ffma2(xv2, w2, acc[r][2]);
            }
        }
        #pragma unroll 8
        for (int h = 0; h < 32; h++) {
            float2 w0 = Wsm[(h + 32) * 96 + lane], w1 = Wsm[(h + 32) * 96 + 32 + lane], w2 = Wsm[(h + 32) * 96 + 64 + lane];
            #pragma unroll
            for (int r = 0; r < 4; r++) {
                float xv = __shfl_sync(0xffffffffu, xb[r], h);
                float2 xv2 = make_float2(xv, xv);
                acc[r][0] = ffma2(xv2, w0, acc[r][0]);
                acc[r][1] = ffma2(xv2, w1, acc[r][1]);
                acc[r][2] = ffma2(xv2, w2, acc[r][2]);
            }
        }
        #pragma unroll
        for (int r = 0; r < 4; r++) {
            float* o = GIP + (size_t)(row0 + r) * 192;
            #pragma unroll
            for (int p = 0; p < 3; p++) {
                o[p * 64 + lane] = acc[r][p].x;
                o[p * 64 + 32 + lane] = acc[r][p].y;
            }
        }
    }
}

// ---------------- GRU step (gh half + gates) --------------------------------
__global__ __launch_bounds__(256) void k_gru(const float* __restrict__ Whh,
                                             const float* __restrict__ bhh,
                                             int t, int par) {
    const float* hprev = par ? H1P : H0P;
    float* hnext = par ? H0P : H1P;
    __shared__ float2 Wsm[64 * 96];
    int tid = threadIdx.x;
    for (int i = tid; i < 64 * 96; i += 256) {
        int h = i / 96, m = i % 96, p = m >> 5, l = m & 31;
        Wsm[i] = make_float2(Whh[(p * 64 + l) * 64 + h], Whh[(p * 64 + l + 32) * 64 + h]);
    }
    __syncthreads();
    int lane = tid & 31;
    const float* gi_base = GIP + (size_t)t * NN * 192;
    float2 bias[3];
    #pragma unroll
    for (int p = 0; p < 3; p++)
        bias[p] = make_float2(bhh[p * 64 + lane], bhh[p * 64 + lane + 32]);
    int nwarps = gridDim.x * 8;
    for (int tile = blockIdx.x * 8 + (tid >> 5); tile < NN / 4; tile += nwarps) {
        int n0 = tile * 4;
        float xa[4], xb[4];
        #pragma unroll
        for (int r = 0; r < 4; r++) {
            xa[r] = hprev[(size_t)(n0 + r) * 64 + lane];
            xb[r] = hprev[(size_t)(n0 + r) * 64 + 32 + lane];
        }
        float2 acc[4][3];
        #pragma unroll
        for (int r = 0; r < 4; r++)
            #pragma unroll
            for (int p = 0; p < 3; p++) acc[r][p] = bias[p];
        #pragma unroll 8
        for (int h = 0; h < 32; h++) {
            float2 w0 = Wsm[h * 96 + lane], w1 = Wsm[h * 96 + 32 + lane], w2 = Wsm[h * 96 + 64 + lane];
            #pragma unroll
            for (int r = 0; r < 4; r++) {
                float xv = __shfl_sync(0xffffffffu, xa[r], h);
                float2 xv2 = make_float2(xv, xv);
                acc[r][0] = ffma2(xv2, w0, acc[r][0]);
                acc[r][1] = ffma2(xv2, w1, acc[r][1]);
                acc[r][2] = ffma2(xv2, w2, acc[r][2]);
            }
        }
        #pragma unroll 8
        for (int h = 0; h < 32; h++) {
            float2 w0 = Wsm[(h + 32) * 96 + lane], w1 = Wsm[(h + 32) * 96 + 32 + lane], w2 = Wsm[(h + 32) * 96 + 64 + lane];
            #pragma unroll
            for (int r = 0; r < 4; r++) {
                float xv = __shfl_sync(0xffffffffu, xb[r], h);
                float2 xv2 = make_float2(xv, xv);
                acc[r][0] = ffma2(xv2, w0, acc[r][0]);
                acc[r][1] = ffma2(xv2, w1, acc[r][1]);
                acc[r][2] = ffma2(xv2, w2, acc[r][2]);
            }
        }
        #pragma unroll
        for (int r = 0; r < 4; r++) {
            const float* gir = gi_base + (size_t)(n0 + r) * 192;
            float2 i_r = make_float2(gir[lane], gir[32 + lane]);
            float2 i_z = make_float2(gir[64 + lane], gir[96 + lane]);
            float2 i_n = make_float2(gir[128 + lane], gir[160 + lane]);
            float2 rg, zg, ng, hn;
            rg.x = sigf(i_r.x + acc[r][0].x); rg.y = sigf(i_r.y + acc[r][0].y);
            zg.x = sigf(i_z.x + acc[r][1].x); zg.y = sigf(i_z.y + acc[r][1].y);
            ng.x = tanhf(i_n.x + rg.x * acc[r][2].x);
            ng.y = tanhf(i_n.y + rg.y * acc[r][2].y);
            hn.x = (1.f - zg.x) * ng.x + zg.x * xa[r];
            hn.y = (1.f - zg.y) * ng.y + zg.y * xb[r];
            hnext[(size_t)(n0 + r) * 64 + lane] = hn.x;
            hnext[(size_t)(n0 + r) * 64 + 32 + lane] = hn.y;
        }
    }
}

// ---------------- classifier head ------------------------------------------
__global__ __launch_bounds__(256) void k_cls(const float* __restrict__ Wc1,
                                             const float* __restrict__ bc1,
                                             const float* __restrict__ Wc2,
                                             const float* __restrict__ bc2,
                                             float* __restrict__ out) {
    __shared__ float W1s[64 * 32];
    __shared__ float w2s[32], b1s[32];
    int tid = threadIdx.x;
    for (int i = tid; i < 2048; i += 256) W1s[i] = Wc1[i];
    if (tid < 32) { w2s[tid] = Wc2[tid]; b1s[tid] = bc1[tid]; }
    __syncthreads();
    int lane = tid & 31;
    int n = blockIdx.x * 8 + (tid >> 5);
    if (n >= NN) return;
    float h0 = H0P[(size_t)n * 64 + lane];
    float h1 = H0P[(size_t)n * 64 + 32 + lane];
    float acc = b1s[lane];
    #pragma unroll
    for (int h = 0; h < 32; h++) {
        float xv = __shfl_sync(0xffffffffu, h0, h);
        acc = fmaf(xv, W1s[h * 32 + lane], acc);
    }
    #pragma unroll
    for (int h = 0; h < 32; h++) {
        float xv = __shfl_sync(0xffffffffu, h1, h);
        acc = fmaf(xv, W1s[(h + 32) * 32 + lane], acc);
    }
    acc = fmaxf(acc, 0.f);
    float p = acc * w2s[lane];
    #pragma unroll
    for (int off = 16; off; off >>= 1) p += __shfl_xor_sync(0xffffffffu, p, off);
    if (lane == 0) out[n] = p + bc2[0];
}

// ---------------- launch ----------------------------------------------------
extern "C" void kernel_launch(void* const* d_in, const int* in_sizes, int n_in,
                              void* d_out, int out_size) {
    const float* x   = (const float*)d_in[0];
    const int*   ei  = (const int*)d_in[1];
    const float* W1  = (const float*)d_in[2];
    const float* b1  = (const float*)d_in[3];
    const float* W2  = (const float*)d_in[4];
    const float* b2  = (const float*)d_in[5];
    const float* Wih = (const float*)d_in[6];
    const float* Whh = (const float*)d_in[7];
    const float* bih = (const float*)d_in[8];
    const float* bhh = (const float*)d_in[9];
    const float* Wc1 = (const float*)d_in[10];
    const float* bc1 = (const float*)d_in[11];
    const float* Wc2 = (const float*)d_in[12];
    const float* bc2 = (const float*)d_in[13];
    float* out = (float*)d_out;

    int E = in_sizes[1] / 2;
    const int* src = ei;
    const int* dst = ei + E;

    // graph preprocessing
    k_init<<<(NN * HH / 4 + 255) / 256, 256>>>();
    k_count<<<(E + 255) / 256, 256>>>(dst, E);
    k_norm<<<(NN + 255) / 256, 256>>>();
    k_scan<<<1, 1024>>>();
    k_fill<<<(E + 255) / 256, 256>>>(src, dst, E);

    // layer 1: P1 = Ahat * x  -> BUFA(32);  h1 = relu(P1 @ W1 + b1) -> BUFB
    k_agg32<<<dim3(NN / 8, TT), 256>>>(x);
    k_gemm_relu<32><<<4440, 256>>>(W1, b1);

    // layer 2: P2 = Ahat * h1 -> BUFA(64);  h2 = relu(P2 @ W2 + b2) -> BUFB
    k_agg64<<<dim3(NN / 8, TT), 256>>>();
    k_gemm_relu<64><<<4440, 256>>>(W2, b2);

    // gi = h2 @ W_ih^T + b_ih (all timesteps, parallel)
    k_gi<<<1184, 256>>>(Wih, bih);

    // GRU scan: h0 zeroed in k_init; 12 steps ping-pong H0/H1, final in H0
    for (int t = 0; t < TT; t++)
        k_gru<<<592, 256>>>(Whh, bhh, t, t & 1);

    // classifier head
    k_cls<<<(NN + 7) / 8, 256>>>(Wc1, bc1, Wc2, bc2, out);
}

// round 2
// speedup vs baseline: 1.0022x; 1.0022x over previous
#include <cuda_runtime.h>
#include <math.h>

// Problem constants
constexpr int TT = 12;
constexpr int NN = 50000;
constexpr int FF = 32;
constexpr int HH = 64;
constexpr int EE = 1600000;
constexpr int ROWS = TT * NN;     // 600000

// ---------------- static device scratch (no allocations allowed) -----------
__device__ int    g_degi[NN];
__device__ int    g_cursor[NN];
__device__ float  g_dinv[NN];
__device__ float  g_invdeg[NN];
__device__ int    g_rowptr[NN + 1];
__device__ int    g_csrc[EE];
__device__ float  g_cw[EE];
__device__ float4 g_bufA4[(size_t)ROWS * HH / 4];        // 153.6 MB
__device__ float4 g_bufB4[(size_t)ROWS * HH / 4];        // 153.6 MB
__device__ float4 g_gi4[(size_t)ROWS * 3 * HH / 4];      // 460.8 MB
__device__ float4 g_h0_4[(size_t)NN * HH / 4];
__device__ float4 g_h1_4[(size_t)NN * HH / 4];

#define BUFA ((float*)g_bufA4)
#define BUFB ((float*)g_bufB4)
#define GIP  ((float*)g_gi4)
#define H0P  ((float*)g_h0_4)
#define H1P  ((float*)g_h1_4)

// ---------------- packed f32x2 FMA (sm_10x) --------------------------------
union F2U { float2 f; unsigned long long u; };
__device__ __forceinline__ float2 ffma2(float2 a, float2 b, float2 c) {
    F2U A, B, C, D; A.f = a; B.f = b; C.f = c;
    asm("fma.rn.f32x2 %0, %1, %2, %3;" : "=l"(D.u) : "l"(A.u), "l"(B.u), "l"(C.u));
    return D.f;
}
__device__ __forceinline__ float sigf(float x) { return 1.f / (1.f + expf(-x)); }

// ---------------- setup kernels --------------------------------------------
__global__ void k_init() {
    int i = blockIdx.x * blockDim.x + threadIdx.x;
    if (i < NN) { g_degi[i] = 0; g_cursor[i] = 0; }
    if (i < NN * HH / 4) g_h0_4[i] = make_float4(0.f, 0.f, 0.f, 0.f);
}

__global__ void k_count(const int* __restrict__ dst, int E) {
    int e = blockIdx.x * blockDim.x + threadIdx.x;
    if (e < E) atomicAdd(&g_degi[dst[e]], 1);
}

__global__ void k_norm() {
    int i = blockIdx.x * blockDim.x + threadIdx.x;
    if (i < NN) {
        float deg = (float)g_degi[i] + 1.0f;
        g_dinv[i] = 1.0f / sqrtf(deg);
        g_invdeg[i] = 1.0f / deg;
    }
}

__global__ void k_scan() {     // single-block exclusive scan of g_degi -> g_rowptr
    __shared__ int sh[1024];
    int t = threadIdx.x;
    const int C = (NN + 1023) / 1024;
    int base = t * C, s = 0;
    for (int i = 0; i < C; i++) { int idx = base + i; if (idx < NN) s += g_degi[idx]; }
    sh[t] = s; __syncthreads();
    for (int off = 1; off < 1024; off <<= 1) {
        int v = (t >= off) ? sh[t - off] : 0;
        __syncthreads();
        sh[t] += v;
        __syncthreads();
    }
    int excl = sh[t] - s;
    int run = excl;
    for (int i = 0; i < C; i++) {
        int idx = base + i;
        if (idx < NN) { g_rowptr[idx] = run; run += g_degi[idx]; }
    }
    if (t == 0) g_rowptr[NN] = sh[1023];
}

__global__ void k_fill(const int* __restrict__ src, const int* __restrict__ dst, int E) {
    int e = blockIdx.x * blockDim.x + threadIdx.x;
    if (e < E) {
        int s = src[e], d = dst[e];
        float w = g_dinv[s] * g_dinv[d];
        int pos = g_rowptr[d] + atomicAdd(&g_cursor[d], 1);
        g_csrc[pos] = s;
        g_cw[pos] = w;
    }
}

// ---------------- aggregation: out = Ahat * in ------------------------------
// 32-wide (layer-1 on raw x). warp per (t,n); lane = column.
__global__ __launch_bounds__(256) void k_agg32(const float* __restrict__ x) {
    int t = blockIdx.y;
    int lane = threadIdx.x & 31;
    int n = blockIdx.x * 8 + (threadIdx.x >> 5);
    if (n >= NN) return;
    const float* xin = x + (size_t)t * NN * FF;
    float* outp = BUFA + (size_t)t * NN * FF;
    int r0 = g_rowptr[n], r1 = g_rowptr[n + 1];
    float acc = 0.f;
    int base = r0;
    for (; base + 32 <= r1; base += 32) {
        int sv = g_csrc[base + lane];
        float wv = g_cw[base + lane];
        #pragma unroll
        for (int k = 0; k < 32; k++) {
            int ss = __shfl_sync(0xffffffffu, sv, k);
            float ww = __shfl_sync(0xffffffffu, wv, k);
            acc = fmaf(ww, xin[(size_t)ss * FF + lane], acc);
        }
    }
    if (base < r1) {
        int sv = 0; float wv = 0.f;
        if (base + lane < r1) { sv = g_csrc[base + lane]; wv = g_cw[base + lane]; }
        int cnt = r1 - base;
        for (int k = 0; k < cnt; k++) {
            int ss = __shfl_sync(0xffffffffu, sv, k);
            float ww = __shfl_sync(0xffffffffu, wv, k);
            acc = fmaf(ww, xin[(size_t)ss * FF + lane], acc);
        }
    }
    acc = fmaf(g_invdeg[n], xin[(size_t)n * FF + lane], acc);
    outp[(size_t)n * FF + lane] = acc;
}

// 64-wide (layer-2): reads BUFB, writes BUFA. lane handles float2 (2 cols).
__global__ __launch_bounds__(256) void k_agg64() {
    int t = blockIdx.y;
    int lane = threadIdx.x & 31;
    int n = blockIdx.x * 8 + (threadIdx.x >> 5);
    if (n >= NN) return;
    const float2* inT = (const float2*)(BUFB + (size_t)t * NN * HH);
    float2* outT = (float2*)(BUFA + (size_t)t * NN * HH);
    int r0 = g_rowptr[n], r1 = g_rowptr[n + 1];
    float2 acc = make_float2(0.f, 0.f);
    int base = r0;
    for (; base + 32 <= r1; base += 32) {
        int sv = g_csrc[base + lane];
        float wv = g_cw[base + lane];
        #pragma unroll
        for (int k = 0; k < 32; k++) {
            int ss = __shfl_sync(0xffffffffu, sv, k);
            float ww = __shfl_sync(0xffffffffu, wv, k);
            float2 v = inT[(size_t)ss * 32 + lane];
            acc = ffma2(make_float2(ww, ww), v, acc);
        }
    }
    if (base < r1) {
        int sv = 0; float wv = 0.f;
        if (base + lane < r1) { sv = g_csrc[base + lane]; wv = g_cw[base + lane]; }
        int cnt = r1 - base;
        for (int k = 0; k < cnt; k++) {
            int ss = __shfl_sync(0xffffffffu, sv, k);
            float ww = __shfl_sync(0xffffffffu, wv, k);
            float2 v = inT[(size_t)ss * 32 + lane];
            acc = ffma2(make_float2(ww, ww), v, acc);
        }
    }
    float2 hv = inT[(size_t)n * 32 + lane];
    float id = g_invdeg[n];
    acc = ffma2(make_float2(id, id), hv, acc);
    outT[(size_t)n * 32 + lane] = acc;
}

// ---------------- dense: out = relu(in @ W + b), BUFA -> BUFB ---------------
template <int FI>
__global__ __launch_bounds__(256) void k_gemm_relu(const float* __restrict__ W,
                                                   const float* __restrict__ b) {
    __shared__ float2 Wsm[FI * 32];
    __shared__ float2 Bsm[32];
    int tid = threadIdx.x;
    for (int i = tid; i < FI * 32; i += 256) {
        int f = i >> 5, p = i & 31;
        Wsm[i] = make_float2(W[f * 64 + p], W[f * 64 + p + 32]);
    }
    if (tid < 32) Bsm[tid] = make_float2(b[tid], b[tid + 32]);
    __syncthreads();
    int lane = tid & 31;
    for (int row = blockIdx.x * 8 + (tid >> 5); row < ROWS; row += gridDim.x * 8) {
        const float* xr = BUFA + (size_t)row * FI;
        float x0 = xr[lane];
        float x1 = (FI == 64) ? xr[lane + 32] : 0.f;
        float2 acc = Bsm[lane];
        #pragma unroll
        for (int f = 0; f < 32; f++) {
            float xv = __shfl_sync(0xffffffffu, x0, f);
            acc = ffma2(make_float2(xv, xv), Wsm[f * 32 + lane], acc);
        }
        if (FI == 64) {
            #pragma unroll
            for (int f = 0; f < 32; f++) {
                float xv = __shfl_sync(0xffffffffu, x1, f);
                acc = ffma2(make_float2(xv, xv), Wsm[(f + 32) * 32 + lane], acc);
            }
        }
        float* o = BUFB + (size_t)row * 64;
        o[lane] = fmaxf(acc.x, 0.f);
        o[lane + 32] = fmaxf(acc.y, 0.f);
    }
}

// ---------------- gi = BUFB @ W_ih^T + b_ih  -> GIP -------------------------
// warp handles 4 rows; lane computes gate outputs {lane,+32},{+64,+96},{+128,+160}
__global__ __launch_bounds__(256) void k_gi(const float* __restrict__ Wih,
                                            const float* __restrict__ bih) {
    __shared__ float2 Wsm[64 * 96];   // 48KB: Wsm[h*96 + p*32 + l] = (W[p*64+l][h], W[p*64+l+32][h])
    int tid = threadIdx.x;
    for (int i = tid; i < 64 * 96; i += 256) {
        int h = i / 96, m = i % 96, p = m >> 5, l = m & 31;
        Wsm[i] = make_float2(Wih[(p * 64 + l) * 64 + h], Wih[(p * 64 + l + 32) * 64 + h]);
    }
    __syncthreads();
    int lane = tid & 31;
    float2 bias[3];
    #pragma unroll
    for (int p = 0; p < 3; p++)
        bias[p] = make_float2(bih[p * 64 + lane], bih[p * 64 + lane + 32]);
    for (int tile = blockIdx.x * 8 + (tid >> 5); tile < ROWS / 4; tile += gridDim.x * 8) {
        int row0 = tile * 4;
        float xa[4], xb[4];
        #pragma unroll
        for (int r = 0; r < 4; r++) {
            xa[r] = BUFB[(size_t)(row0 + r) * 64 + lane];
            xb[r] = BUFB[(size_t)(row0 + r) * 64 + 32 + lane];
        }
        float2 acc[4][3];
        #pragma unroll
        for (int r = 0; r < 4; r++)
            #pragma unroll
            for (int p = 0; p < 3; p++) acc[r][p] = bias[p];
        #pragma unroll 8
        for (int h = 0; h < 32; h++) {
            float2 w0 = Wsm[h * 96 + lane], w1 = Wsm[h * 96 + 32 + lane], w2 = Wsm[h * 96 + 64 + lane];
            #pragma unroll
            for (int r = 0; r < 4; r++) {
                float xv = __shfl_sync(0xffffffffu, xa[r], h);
                float2 xv2 = make_float2(xv, xv);
                acc[r][0] = ffma2(xv2, w0, acc[r][0]);
                acc[r][1] = ffma2(xv2, w1, acc[r][1]);
                acc[r][2] = ffma2(xv2, w2, acc[r][2]);
            }
        }
        #pragma unroll 8
        for (int h = 0; h < 32; h++) {
            float2 w0 = Wsm[(h + 32) * 96 + lane], w1 = Wsm[(h + 32) * 96 + 32 + lane], w2 = Wsm[(h + 32) * 96 + 64 + lane];
            #pragma unroll
            for (int r = 0; r < 4; r++) {
                float xv = __shfl_sync(0xffffffffu, xb[r], h);
                float2 xv2 = make_float2(xv, xv);
                acc[r][0] = ffma2(xv2, w0, acc[r][0]);
                acc[r][1] = ffma2(xv2, w1, acc[r][1]);
                acc[r][2] = ffma2(xv2, w2, acc[r][2]);
            }
        }
        #pragma unroll
        for (int r = 0; r < 4; r++) {
            float* o = GIP + (size_t)(row0 + r) * 192;
            #pragma unroll
            for (int p = 0; p < 3; p++) {
                o[p * 64 + lane] = acc[r][p].x;
                o[p * 64 + 32 + lane] = acc[r][p].y;
            }
        }
    }
}

// ---------------- GRU step (gh half + gates) --------------------------------
__global__ __launch_bounds__(256) void k_gru(const float* __restrict__ Whh,
                                             const float* __restrict__ bhh,
                                             int t, int par) {
    const float* hprev = par ? H1P : H0P;
    float* hnext = par ? H0P : H1P;
    __shared__ float2 Wsm[64 * 96];
    int tid = threadIdx.x;
    for (int i = tid; i < 64 * 96; i += 256) {
        int h = i / 96, m = i % 96, p = m >> 5, l = m & 31;
        Wsm[i] = make_float2(Whh[(p * 64 + l) * 64 + h], Whh[(p * 64 + l + 32) * 64 + h]);
    }
    __syncthreads();
    int lane = tid & 31;
    const float* gi_base = GIP + (size_t)t * NN * 192;
    float2 bias[3];
    #pragma unroll
    for (int p = 0; p < 3; p++)
        bias[p] = make_float2(bhh[p * 64 + lane], bhh[p * 64 + lane + 32]);
    int nwarps = gridDim.x * 8;
    for (int tile = blockIdx.x * 8 + (tid >> 5); tile < NN / 4; tile += nwarps) {
        int n0 = tile * 4;
        float xa[4], xb[4];
        #pragma unroll
        for (int r = 0; r < 4; r++) {
            xa[r] = hprev[(size_t)(n0 + r) * 64 + lane];
            xb[r] = hprev[(size_t)(n0 + r) * 64 + 32 + lane];
        }
        float2 acc[4][3];
        #pragma unroll
        for (int r = 0; r < 4; r++)
            #pragma unroll
            for (int p = 0; p < 3; p++) acc[r][p] = bias[p];
        #pragma unroll 8
        for (int h = 0; h < 32; h++) {
            float2 w0 = Wsm[h * 96 + lane], w1 = Wsm[h * 96 + 32 + lane], w2 = Wsm[h * 96 + 64 + lane];
            #pragma unroll
            for (int r = 0; r < 4; r++) {
                float xv = __shfl_sync(0xffffffffu, xa[r], h);
                float2 xv2 = make_float2(xv, xv);
                acc[r][0] = ffma2(xv2, w0, acc[r][0]);
                acc[r][1] = ffma2(xv2, w1, acc[r][1]);
                acc[r][2] = ffma2(xv2, w2, acc[r][2]);
            }
        }
        #pragma unroll 8
        for (int h = 0; h < 32; h++) {
            float2 w0 = Wsm[(h + 32) * 96 + lane], w1 = Wsm[(h + 32) * 96 + 32 + lane], w2 = Wsm[(h + 32) * 96 + 64 + lane];
            #pragma unroll
            for (int r = 0; r < 4; r++) {
                float xv = __shfl_sync(0xffffffffu, xb[r], h);
                float2 xv2 = make_float2(xv, xv);
                acc[r][0] = ffma2(xv2, w0, acc[r][0]);
                acc[r][1] = ffma2(xv2, w1, acc[r][1]);
                acc[r][2] = ffma2(xv2, w2, acc[r][2]);
            }
        }
        #pragma unroll
        for (int r = 0; r < 4; r++) {
            const float* gir = gi_base + (size_t)(n0 + r) * 192;
            float2 i_r = make_float2(gir[lane], gir[32 + lane]);
            float2 i_z = make_float2(gir[64 + lane], gir[96 + lane]);
            float2 i_n = make_float2(gir[128 + lane], gir[160 + lane]);
            float2 rg, zg, ng, hn;
            rg.x = sigf(i_r.x + acc[r][0].x); rg.y = sigf(i_r.y + acc[r][0].y);
            zg.x = sigf(i_z.x + acc[r][1].x); zg.y = sigf(i_z.y + acc[r][1].y);
            ng.x = tanhf(i_n.x + rg.x * acc[r][2].x);
            ng.y = tanhf(i_n.y + rg.y * acc[r][2].y);
            hn.x = (1.f - zg.x) * ng.x + zg.x * xa[r];
            hn.y = (1.f - zg.y) * ng.y + zg.y * xb[r];
            hnext[(size_t)(n0 + r) * 64 + lane] = hn.x;
            hnext[(size_t)(n0 + r) * 64 + 32 + lane] = hn.y;
        }
    }
}

// ---------------- classifier head ------------------------------------------
__global__ __launch_bounds__(256) void k_cls(const float* __restrict__ Wc1,
                                             const float* __restrict__ bc1,
                                             const float* __restrict__ Wc2,
                                             const float* __restrict__ bc2,
                                             float* __restrict__ out) {
    __shared__ float W1s[64 * 32];
    __shared__ float w2s[32], b1s[32];
    int tid = threadIdx.x;
    for (int i = tid; i < 2048; i += 256) W1s[i] = Wc1[i];
    if (tid < 32) { w2s[tid] = Wc2[tid]; b1s[tid] = bc1[tid]; }
    __syncthreads();
    int lane = tid & 31;
    int n = blockIdx.x * 8 + (tid >> 5);
    if (n >= NN) return;
    float h0 = H0P[(size_t)n * 64 + lane];
    float h1 = H0P[(size_t)n * 64 + 32 + lane];
    float acc = b1s[lane];
    #pragma unroll
    for (int h = 0; h < 32; h++) {
        float xv = __shfl_sync(0xffffffffu, h0, h);
        acc = fmaf(xv, W1s[h * 32 + lane], acc);
    }
    #pragma unroll
    for (int h = 0; h < 32; h++) {
        float xv = __shfl_sync(0xffffffffu, h1, h);
        acc = fmaf(xv, W1s[(h + 32) * 32 + lane], acc);
    }
    acc = fmaxf(acc, 0.f);
    float p = acc * w2s[lane];
    #pragma unroll
    for (int off = 16; off; off >>= 1) p += __shfl_xor_sync(0xffffffffu, p, off);
    if (lane == 0) out[n] = p + bc2[0];
}

// ---------------- launch ----------------------------------------------------
extern "C" void kernel_launch(void* const* d_in, const int* in_sizes, int n_in,
                              void* d_out, int out_size) {
    const float* x   = (const float*)d_in[0];
    const int*   ei  = (const int*)d_in[1];
    const float* W1  = (const float*)d_in[2];
    const float* b1  = (const float*)d_in[3];
    const float* W2  = (const float*)d_in[4];
    const float* b2  = (const float*)d_in[5];
    const float* Wih = (const float*)d_in[6];
    const float* Whh = (const float*)d_in[7];
    const float* bih = (const float*)d_in[8];
    const float* bhh = (const float*)d_in[9];
    const float* Wc1 = (const float*)d_in[10];
    const float* bc1 = (const float*)d_in[11];
    const float* Wc2 = (const float*)d_in[12];
    const float* bc2 = (const float*)d_in[13];
    float* out = (float*)d_out;

    int E = in_sizes[1] / 2;
    const int* src = ei;
    const int* dst = ei + E;

    // graph preprocessing
    k_init<<<(NN * HH / 4 + 255) / 256, 256>>>();
    k_count<<<(E + 255) / 256, 256>>>(dst, E);
    k_norm<<<(NN + 255) / 256, 256>>>();
    k_scan<<<1, 1024>>>();
    k_fill<<<(E + 255) / 256, 256>>>(src, dst, E);

    // layer 1: P1 = Ahat * x  -> BUFA(32);  h1 = relu(P1 @ W1 + b1) -> BUFB
    k_agg32<<<dim3(NN / 8, TT), 256>>>(x);
    k_gemm_relu<32><<<4440, 256>>>(W1, b1);

    // layer 2: P2 = Ahat * h1 -> BUFA(64);  h2 = relu(P2 @ W2 + b2) -> BUFB
    k_agg64<<<dim3(NN / 8, TT), 256>>>();
    k_gemm_relu<64><<<4440, 256>>>(W2, b2);

    // gi = h2 @ W_ih^T + b_ih (all timesteps, parallel)
    k_gi<<<1184, 256>>>(Wih, bih);

    // GRU scan: h0 zeroed in k_init; 12 steps ping-pong H0/H1, final in H0
    for (int t = 0; t < TT; t++)
        k_gru<<<592, 256>>>(Whh, bhh, t, t & 1);

    // classifier head
    k_cls<<<(NN + 7) / 8, 256>>>(Wc1, bc1, Wc2, bc2, out);
}

// round 3
// speedup vs baseline: 1.0274x; 1.0251x over previous
#include <cuda_runtime.h>
#include <cuda_fp16.h>
#include <math.h>

// Problem constants
constexpr int TT = 12;
constexpr int NN = 50000;
constexpr int FF = 32;
constexpr int HH = 64;
constexpr int EE = 1600000;
constexpr int ROWS = TT * NN;     // 600000

// ---------------- static device scratch (zero-initialized at load) ---------
__device__ int     g_degi[NN];        // zeroed at end of each call (and at load)
__device__ int     g_cursor[NN];      // same
__device__ float   g_dinv[NN];
__device__ float   g_invdeg[NN];
__device__ int     g_rowptr[NN + 1];
__device__ int2    g_epk[EE];                              // packed (src, w)
__device__ float4  g_bufA4[(size_t)ROWS * HH / 4];         // 153.6 MB fp32
__device__ __half2 g_h1h2[(size_t)ROWS * HH / 2];          // 76.8 MB  h1 fp16
__device__ float4  g_bufB4[(size_t)ROWS * HH / 4];         // 153.6 MB h2 fp32
__device__ __half2 g_gih2[(size_t)ROWS * 3 * HH / 2];      // 230.4 MB gi fp16
__device__ float4  g_h0_4[(size_t)NN * HH / 4];
__device__ float4  g_h1_4[(size_t)NN * HH / 4];

#define BUFA ((float*)g_bufA4)
#define BUFB ((float*)g_bufB4)
#define H1H  ((__half*)g_h1h2)
#define GIH  ((__half*)g_gih2)
#define H0P  ((float*)g_h0_4)
#define H1P  ((float*)g_h1_4)

// ---------------- packed f32x2 FMA (sm_10x) --------------------------------
union F2U { float2 f; unsigned long long u; };
__device__ __forceinline__ float2 ffma2(float2 a, float2 b, float2 c) {
    F2U A, B, C, D; A.f = a; B.f = b; C.f = c;
    asm("fma.rn.f32x2 %0, %1, %2, %3;" : "=l"(D.u) : "l"(A.u), "l"(B.u), "l"(C.u));
    return D.f;
}
__device__ __forceinline__ float sigf(float x) { return 1.f / (1.f + expf(-x)); }

// ---------------- preprocessing --------------------------------------------
__global__ void k_count(const int* __restrict__ dst, int E) {
    int e = blockIdx.x * blockDim.x + threadIdx.x;
    if (e < E) atomicAdd(&g_degi[dst[e]], 1);
}

// single block, 1024 threads: coalesced tile-wise exclusive scan + norm
__global__ void k_scan_norm() {
    __shared__ int wsum[32];
    __shared__ int s_base;
    int t = threadIdx.x, lane = t & 31, wid = t >> 5;
    if (t == 0) s_base = 0;
    __syncthreads();
    for (int base = 0; base < NN; base += 1024) {
        int idx = base + t;
        int v = (idx < NN) ? g_degi[idx] : 0;
        int x = v;
        #pragma unroll
        for (int o = 1; o < 32; o <<= 1) {
            int y = __shfl_up_sync(0xffffffffu, x, o);
            if (lane >= o) x += y;
        }
        if (lane == 31) wsum[wid] = x;
        __syncthreads();
        if (wid == 0) {
            int w = wsum[lane];
            int xw = w;
            #pragma unroll
            for (int o = 1; o < 32; o <<= 1) {
                int y = __shfl_up_sync(0xffffffffu, xw, o);
                if (lane >= o) xw += y;
            }
            wsum[lane] = xw - w;   // exclusive warp offsets
        }
        __syncthreads();
        int excl = s_base + wsum[wid] + x - v;
        if (idx < NN) {
            g_rowptr[idx] = excl;
            float deg = (float)v + 1.0f;
            g_dinv[idx] = rsqrtf(deg);
            g_invdeg[idx] = 1.0f / deg;
        }
        __syncthreads();
        if (t == 1023) s_base = excl + v;
        __syncthreads();
    }
    if (t == 0) g_rowptr[NN] = s_base;
}

__global__ void k_fill(const int* __restrict__ src, const int* __restrict__ dst, int E) {
    int e = blockIdx.x * blockDim.x + threadIdx.x;
    if (e < E) {
        int s = src[e], d = dst[e];
        float w = g_dinv[s] * g_dinv[d];
        int pos = g_rowptr[d] + atomicAdd(&g_cursor[d], 1);
        g_epk[pos] = make_int2(s, __float_as_int(w));
    }
}

// ---------------- aggregation: out = Ahat * in ------------------------------
// 32-wide (layer-1 on raw x). warp per (t,n); lane = column.
__global__ __launch_bounds__(256) void k_agg32(const float* __restrict__ x) {
    int t = blockIdx.y;
    int lane = threadIdx.x & 31;
    int n = blockIdx.x * 8 + (threadIdx.x >> 5);
    if (n >= NN) return;
    const float* xin = x + (size_t)t * NN * FF;
    float* outp = BUFA + (size_t)t * NN * FF;
    int r0 = g_rowptr[n], r1 = g_rowptr[n + 1];
    float acc = 0.f;
    int base = r0;
    for (; base + 32 <= r1; base += 32) {
        int2 ep = g_epk[base + lane];
        #pragma unroll
        for (int k = 0; k < 32; k++) {
            int ss = __shfl_sync(0xffffffffu, ep.x, k);
            float ww = __int_as_float(__shfl_sync(0xffffffffu, ep.y, k));
            acc = fmaf(ww, xin[(size_t)ss * FF + lane], acc);
        }
    }
    if (base < r1) {
        int2 ep = make_int2(0, 0);
        if (base + lane < r1) ep = g_epk[base + lane];
        int cnt = r1 - base;
        for (int k = 0; k < cnt; k++) {
            int ss = __shfl_sync(0xffffffffu, ep.x, k);
            float ww = __int_as_float(__shfl_sync(0xffffffffu, ep.y, k));
            acc = fmaf(ww, xin[(size_t)ss * FF + lane], acc);
        }
    }
    acc = fmaf(g_invdeg[n], xin[(size_t)n * FF + lane], acc);
    outp[(size_t)n * FF + lane] = acc;
}

// 64-wide (layer-2): reads fp16 h1, writes fp32 BUFA. lane handles 2 cols.
__global__ __launch_bounds__(256) void k_agg64() {
    int t = blockIdx.y;
    int lane = threadIdx.x & 31;
    int n = blockIdx.x * 8 + (threadIdx.x >> 5);
    if (n >= NN) return;
    const __half2* inH = g_h1h2 + (size_t)t * NN * 32;
    float2* outT = (float2*)(BUFA + (size_t)t * NN * HH);
    int r0 = g_rowptr[n], r1 = g_rowptr[n + 1];
    float2 acc = make_float2(0.f, 0.f);
    int base = r0;
    for (; base + 32 <= r1; base += 32) {
        int2 ep = g_epk[base + lane];
        #pragma unroll
        for (int k = 0; k < 32; k++) {
            int ss = __shfl_sync(0xffffffffu, ep.x, k);
            float ww = __int_as_float(__shfl_sync(0xffffffffu, ep.y, k));
            float2 v = __half22float2(inH[(size_t)ss * 32 + lane]);
            acc = ffma2(make_float2(ww, ww), v, acc);
        }
    }
    if (base < r1) {
        int2 ep = make_int2(0, 0);
        if (base + lane < r1) ep = g_epk[base + lane];
        int cnt = r1 - base;
        for (int k = 0; k < cnt; k++) {
            int ss = __shfl_sync(0xffffffffu, ep.x, k);
            float ww = __int_as_float(__shfl_sync(0xffffffffu, ep.y, k));
            float2 v = __half22float2(inH[(size_t)ss * 32 + lane]);
            acc = ffma2(make_float2(ww, ww), v, acc);
        }
    }
    float2 hv = __half22float2(inH[(size_t)n * 32 + lane]);
    float id = g_invdeg[n];
    acc = ffma2(make_float2(id, id), hv, acc);
    outT[(size_t)n * 32 + lane] = acc;
}

// ---------------- dense layer 1: h1 = relu(BUFA(32) @ W1 + b1) -> fp16 ------
__global__ __launch_bounds__(256) void k_gemm1(const float* __restrict__ W,
                                               const float* __restrict__ b) {
    __shared__ float2 Wsm[32 * 32];
    __shared__ float2 Bsm[32];
    int tid = threadIdx.x;
    for (int i = tid; i < 32 * 32; i += 256) {
        int f = i >> 5, p = i & 31;
        Wsm[i] = make_float2(W[f * 64 + p], W[f * 64 + p + 32]);
    }
    if (tid < 32) Bsm[tid] = make_float2(b[tid], b[tid + 32]);
    __syncthreads();
    int lane = tid & 31;
    for (int row = blockIdx.x * 8 + (tid >> 5); row < ROWS; row += gridDim.x * 8) {
        const float* xr = BUFA + (size_t)row * FF;
        float x0 = xr[lane];
        float2 acc = Bsm[lane];
        #pragma unroll
        for (int f = 0; f < 32; f++) {
            float xv = __shfl_sync(0xffffffffu, x0, f);
            acc = ffma2(make_float2(xv, xv), Wsm[f * 32 + lane], acc);
        }
        __half* o = H1H + (size_t)row * 64;
        o[lane] = __float2half_rn(fmaxf(acc.x, 0.f));
        o[lane + 32] = __float2half_rn(fmaxf(acc.y, 0.f));
    }
}

// ---------------- dense layer 2: h2 = relu(BUFA(64) @ W2 + b2) -> fp32 ------
__global__ __launch_bounds__(256) void k_gemm2(const float* __restrict__ W,
                                               const float* __restrict__ b) {
    __shared__ float2 Wsm[64 * 32];
    __shared__ float2 Bsm[32];
    int tid = threadIdx.x;
    for (int i = tid; i < 64 * 32; i += 256) {
        int f = i >> 5, p = i & 31;
        Wsm[i] = make_float2(W[f * 64 + p], W[f * 64 + p + 32]);
    }
    if (tid < 32) Bsm[tid] = make_float2(b[tid], b[tid + 32]);
    __syncthreads();
    int lane = tid & 31;
    for (int row = blockIdx.x * 8 + (tid >> 5); row < ROWS; row += gridDim.x * 8) {
        const float* xr = BUFA + (size_t)row * HH;
        float x0 = xr[lane];
        float x1 = xr[lane + 32];
        float2 acc = Bsm[lane];
        #pragma unroll
        for (int f = 0; f < 32; f++) {
            float xv = __shfl_sync(0xffffffffu, x0, f);
            acc = ffma2(make_float2(xv, xv), Wsm[f * 32 + lane], acc);
        }
        #pragma unroll
        for (int f = 0; f < 32; f++) {
            float xv = __shfl_sync(0xffffffffu, x1, f);
            acc = ffma2(make_float2(xv, xv), Wsm[(f + 32) * 32 + lane], acc);
        }
        float* o = BUFB + (size_t)row * 64;
        o[lane] = fmaxf(acc.x, 0.f);
        o[lane + 32] = fmaxf(acc.y, 0.f);
    }
}

// ---------------- gi = BUFB @ W_ih^T + b_ih  -> GIH (fp16) ------------------
__global__ __launch_bounds__(256) void k_gi(const float* __restrict__ Wih,
                                            const float* __restrict__ bih) {
    __shared__ float2 Wsm[64 * 96];   // 48KB
    int tid = threadIdx.x;
    for (int i = tid; i < 64 * 96; i += 256) {
        int h = i / 96, m = i % 96, p = m >> 5, l = m & 31;
        Wsm[i] = make_float2(Wih[(p * 64 + l) * 64 + h], Wih[(p * 64 + l + 32) * 64 + h]);
    }
    __syncthreads();
    int lane = tid & 31;
    float2 bias[3];
    #pragma unroll
    for (int p = 0; p < 3; p++)
        bias[p] = make_float2(bih[p * 64 + lane], bih[p * 64 + lane + 32]);
    for (int tile = blockIdx.x * 8 + (tid >> 5); tile < ROWS / 4; tile += gridDim.x * 8) {
        int row0 = tile * 4;
        float xa[4], xb[4];
        #pragma unroll
        for (int r = 0; r < 4; r++) {
            xa[r] = BUFB[(size_t)(row0 + r) * 64 + lane];
            xb[r] = BUFB[(size_t)(row0 + r) * 64 + 32 + lane];
        }
        float2 acc[4][3];
        #pragma unroll
        for (int r = 0; r < 4; r++)
            #pragma unroll
            for (int p = 0; p < 3; p++) acc[r][p] = bias[p];
        #pragma unroll 8
        for (int h = 0; h < 32; h++) {
            float2 w0 = Wsm[h * 96 + lane], w1 = Wsm[h * 96 + 32 + lane], w2 = Wsm[h * 96 + 64 + lane];
            #pragma unroll
            for (int r = 0; r < 4; r++) {
                float xv = __shfl_sync(0xffffffffu, xa[r], h);
                float2 xv2 = make_float2(xv, xv);
                acc[r][0] = ffma2(xv2, w0, acc[r][0]);
                acc[r][1] = ffma2(xv2, w1, acc[r][1]);
                acc[r][2] = ffma2(xv2, w2, acc[r][2]);
            }
        }
        #pragma unroll 8
        for (int h = 0; h < 32; h++) {
            float2 w0 = Wsm[(h + 32) * 96 + lane], w1 = Wsm[(h + 32) * 96 + 32 + lane], w2 = Wsm[(h + 32) * 96 + 64 + lane];
            #pragma unroll
            for (int r = 0; r < 4; r++) {
                float xv = __shfl_sync(0xffffffffu, xb[r], h);
                float2 xv2 = make_float2(xv, xv);
                acc[r][0] = ffma2(xv2, w0, acc[r][0]);
                acc[r][1] = ffma2(xv2, w1, acc[r][1]);
                acc[r][2] = ffma2(xv2, w2, acc[r][2]);
            }
        }
        #pragma unroll
        for (int r = 0; r < 4; r++) {
            __half* o = GIH + (size_t)(row0 + r) * 192;
            #pragma unroll
            for (int p = 0; p < 3; p++) {
                o[p * 64 + lane] = __float2half_rn(acc[r][p].x);
                o[p * 64 + 32 + lane] = __float2half_rn(acc[r][p].y);
            }
        }
    }
}

// ---------------- GRU step (gh half + gates) --------------------------------
__global__ __launch_bounds__(256) void k_gru(const float* __restrict__ Whh,
                                             const float* __restrict__ bhh,
                                             int t, int par, int zero) {
    const float* hprev = par ? H1P : H0P;
    float* hnext = par ? H0P : H1P;
    __shared__ float2 Wsm[64 * 96];
    int tid = threadIdx.x;
    if (!zero) {
        for (int i = tid; i < 64 * 96; i += 256) {
            int h = i / 96, m = i % 96, p = m >> 5, l = m & 31;
            Wsm[i] = make_float2(Whh[(p * 64 + l) * 64 + h], Whh[(p * 64 + l + 32) * 64 + h]);
        }
        __syncthreads();
    }
    int lane = tid & 31;
    const __half* gi_base = GIH + (size_t)t * NN * 192;
    float2 bias[3];
    #pragma unroll
    for (int p = 0; p < 3; p++)
        bias[p] = make_float2(bhh[p * 64 + lane], bhh[p * 64 + lane + 32]);
    int nwarps = gridDim.x * 8;
    for (int tile = blockIdx.x * 8 + (tid >> 5); tile < NN / 4; tile += nwarps) {
        int n0 = tile * 4;
        float xa[4], xb[4];
        float2 acc[4][3];
        #pragma unroll
        for (int r = 0; r < 4; r++)
            #pragma unroll
            for (int p = 0; p < 3; p++) acc[r][p] = bias[p];
        if (!zero) {
            #pragma unroll
            for (int r = 0; r < 4; r++) {
                xa[r] = hprev[(size_t)(n0 + r) * 64 + lane];
                xb[r] = hprev[(size_t)(n0 + r) * 64 + 32 + lane];
            }
            #pragma unroll 8
            for (int h = 0; h < 32; h++) {
                float2 w0 = Wsm[h * 96 + lane], w1 = Wsm[h * 96 + 32 + lane], w2 = Wsm[h * 96 + 64 + lane];
                #pragma unroll
                for (int r = 0; r < 4; r++) {
                    float xv = __shfl_sync(0xffffffffu, xa[r], h);
                    float2 xv2 = make_float2(xv, xv);
                    acc[r][0] = ffma2(xv2, w0, acc[r][0]);
                    acc[r][1] = ffma2(xv2, w1, acc[r][1]);
                    acc[r][2] = ffma2(xv2, w2, acc[r][2]);
                }
            }
            #pragma unroll 8
            for (int h = 0; h < 32; h++) {
                float2 w0 = Wsm[(h + 32) * 96 + lane], w1 = Wsm[(h + 32) * 96 + 32 + lane], w2 = Wsm[(h + 32) * 96 + 64 + lane];
                #pragma unroll
                for (int r = 0; r < 4; r++) {
                    float xv = __shfl_sync(0xffffffffu, xb[r], h);
                    float2 xv2 = make_float2(xv, xv);
                    acc[r][0] = ffma2(xv2, w0, acc[r][0]);
                    acc[r][1] = ffma2(xv2, w1, acc[r][1]);
                    acc[r][2] = ffma2(xv2, w2, acc[r][2]);
                }
            }
        } else {
            #pragma unroll
            for (int r = 0; r < 4; r++) { xa[r] = 0.f; xb[r] = 0.f; }
        }
        #pragma unroll
        for (int r = 0; r < 4; r++) {
            const __half* gir = gi_base + (size_t)(n0 + r) * 192;
            float2 i_r = make_float2(__half2float(gir[lane]), __half2float(gir[32 + lane]));
            float2 i_z = make_float2(__half2float(gir[64 + lane]), __half2float(gir[96 + lane]));
            float2 i_n = make_float2(__half2float(gir[128 + lane]), __half2float(gir[160 + lane]));
            float2 rg, zg, ng, hn;
            rg.x = sigf(i_r.x + acc[r][0].x); rg.y = sigf(i_r.y + acc[r][0].y);
            zg.x = sigf(i_z.x + acc[r][1].x); zg.y = sigf(i_z.y + acc[r][1].y);
            ng.x = tanhf(i_n.x + rg.x * acc[r][2].x);
            ng.y = tanhf(i_n.y + rg.y * acc[r][2].y);
            hn.x = (1.f - zg.x) * ng.x + zg.x * xa[r];
            hn.y = (1.f - zg.y) * ng.y + zg.y * xb[r];
            hnext[(size_t)(n0 + r) * 64 + lane] = hn.x;
            hnext[(size_t)(n0 + r) * 64 + 32 + lane] = hn.y;
        }
    }
}

// ---------------- classifier head + state cleanup ---------------------------
__global__ __launch_bounds__(256) void k_cls(const float* __restrict__ Wc1,
                                             const float* __restrict__ bc1,
                                             const float* __restrict__ Wc2,
                                             const float* __restrict__ bc2,
                                             float* __restrict__ out) {
    // cleanup for next call (deterministic: every call starts from zeros)
    int gid = blockIdx.x * blockDim.x + threadIdx.x;
    if (gid < NN) { g_degi[gid] = 0; g_cursor[gid] = 0; }

    __shared__ float W1s[64 * 32];
    __shared__ float w2s[32], b1s[32];
    int tid = threadIdx.x;
    for (int i = tid; i < 2048; i += 256) W1s[i] = Wc1[i];
    if (tid < 32) { w2s[tid] = Wc2[tid]; b1s[tid] = bc1[tid]; }
    __syncthreads();
    int lane = tid & 31;
    int n = blockIdx.x * 8 + (tid >> 5);
    if (n >= NN) return;
    float h0 = H0P[(size_t)n * 64 + lane];
    float h1 = H0P[(size_t)n * 64 + 32 + lane];
    float acc = b1s[lane];
    #pragma unroll
    for (int h = 0; h < 32; h++) {
        float xv = __shfl_sync(0xffffffffu, h0, h);
        acc = fmaf(xv, W1s[h * 32 + lane], acc);
    }
    #pragma unroll
    for (int h = 0; h < 32; h++) {
        float xv = __shfl_sync(0xffffffffu, h1, h);
        acc = fmaf(xv, W1s[(h + 32) * 32 + lane], acc);
    }
    acc = fmaxf(acc, 0.f);
    float p = acc * w2s[lane];
    #pragma unroll
    for (int off = 16; off; off >>= 1) p += __shfl_xor_sync(0xffffffffu, p, off);
    if (lane == 0) out[n] = p + bc2[0];
}

// ---------------- launch ----------------------------------------------------
extern "C" void kernel_launch(void* const* d_in, const int* in_sizes, int n_in,
                              void* d_out, int out_size) {
    const float* x   = (const float*)d_in[0];
    const int*   ei  = (const int*)d_in[1];
    const float* W1  = (const float*)d_in[2];
    const float* b1  = (const float*)d_in[3];
    const float* W2  = (const float*)d_in[4];
    const float* b2  = (const float*)d_in[5];
    const float* Wih = (const float*)d_in[6];
    const float* Whh = (const float*)d_in[7];
    const float* bih = (const float*)d_in[8];
    const float* bhh = (const float*)d_in[9];
    const float* Wc1 = (const float*)d_in[10];
    const float* bc1 = (const float*)d_in[11];
    const float* Wc2 = (const float*)d_in[12];
    const float* bc2 = (const float*)d_in[13];
    float* out = (float*)d_out;

    int E = in_sizes[1] / 2;
    const int* src = ei;
    const int* dst = ei + E;

    // graph preprocessing (degi/cursor arrive zeroed: static init or prior cleanup)
    k_count<<<(E + 255) / 256, 256>>>(dst, E);
    k_scan_norm<<<1, 1024>>>();
    k_fill<<<(E + 255) / 256, 256>>>(src, dst, E);

    // layer 1: P1 = Ahat * x -> BUFA(32);  h1 = relu(P1 @ W1 + b1) -> fp16 H1H
    k_agg32<<<dim3(NN / 8, TT), 256>>>(x);
    k_gemm1<<<4440, 256>>>(W1, b1);

    // layer 2: P2 = Ahat * h1 -> BUFA(64); h2 = relu(P2 @ W2 + b2) -> BUFB
    k_agg64<<<dim3(NN / 8, TT), 256>>>();
    k_gemm2<<<4440, 256>>>(W2, b2);

    // gi = h2 @ W_ih^T + b_ih (all timesteps, parallel) -> fp16 GIH
    k_gi<<<1184, 256>>>(Wih, bih);

    // GRU scan: 12 steps ping-pong H0/H1, t=0 from h=0, final in H0
    for (int t = 0; t < TT; t++)
        k_gru<<<592, 256>>>(Whh, bhh, t, t & 1, t == 0 ? 1 : 0);

    // classifier head (+ zero degi/cursor for next call)
    k_cls<<<(NN + 7) / 8, 256>>>(Wc1, bc1, Wc2, bc2, out);
}

// round 4
// speedup vs baseline: 1.1848x; 1.1532x over previous
#include <cuda_runtime.h>
#include <cuda_fp16.h>
#include <math.h>

// Problem constants
constexpr int TT = 12;
constexpr int NN = 50000;
constexpr int FF = 32;
constexpr int HH = 64;
constexpr int EE = 1600000;
constexpr int ROWS = TT * NN;     // 600000

// ---------------- static device scratch (zero-initialized at load) ---------
__device__ int     g_degi[NN];        // zeroed at end of each call (and at load)
__device__ int     g_cursor[NN];      // same
__device__ float   g_dinv[NN];
__device__ float   g_invdeg[NN];
__device__ int     g_rowptr[NN + 1];
__device__ int2    g_epk[EE];                              // packed (src, w)
__device__ float4  g_bufA4[(size_t)ROWS * HH / 4];         // 153.6 MB fp32
__device__ uint4   g_h1u4[(size_t)ROWS * HH / 8];          // 76.8 MB h1 fp16 (16B aligned)
__device__ __half2 g_gih2[(size_t)ROWS * 3 * HH / 2];      // 230.4 MB gi fp16
__device__ float4  g_h0_4[(size_t)NN * HH / 4];
__device__ float4  g_h1_4[(size_t)NN * HH / 4];

#define BUFA ((float*)g_bufA4)
#define H1H  ((__half*)g_h1u4)
#define GIH  ((__half*)g_gih2)
#define H0P  ((float*)g_h0_4)
#define H1P  ((float*)g_h1_4)

// ---------------- packed f32x2 FMA (sm_10x) --------------------------------
union F2U { float2 f; unsigned long long u; };
__device__ __forceinline__ float2 ffma2(float2 a, float2 b, float2 c) {
    F2U A, B, C, D; A.f = a; B.f = b; C.f = c;
    asm("fma.rn.f32x2 %0, %1, %2, %3;" : "=l"(D.u) : "l"(A.u), "l"(B.u), "l"(C.u));
    return D.f;
}
__device__ __forceinline__ float2 h2f2(unsigned int u) {
    __half2 h = *reinterpret_cast<const __half2*>(&u);
    return __half22float2(h);
}
__device__ __forceinline__ float sigf(float x) { return 1.f / (1.f + expf(-x)); }

// ---------------- preprocessing --------------------------------------------
__global__ void k_count(const int* __restrict__ dst, int E) {
    int e = blockIdx.x * blockDim.x + threadIdx.x;
    if (e < E) atomicAdd(&g_degi[dst[e]], 1);
}

// single block, 1024 threads: coalesced tile-wise exclusive scan + norm
__global__ void k_scan_norm() {
    __shared__ int wsum[32];
    __shared__ int s_base;
    int t = threadIdx.x, lane = t & 31, wid = t >> 5;
    if (t == 0) s_base = 0;
    __syncthreads();
    for (int base = 0; base < NN; base += 1024) {
        int idx = base + t;
        int v = (idx < NN) ? g_degi[idx] : 0;
        int x = v;
        #pragma unroll
        for (int o = 1; o < 32; o <<= 1) {
            int y = __shfl_up_sync(0xffffffffu, x, o);
            if (lane >= o) x += y;
        }
        if (lane == 31) wsum[wid] = x;
        __syncthreads();
        if (wid == 0) {
            int w = wsum[lane];
            int xw = w;
            #pragma unroll
            for (int o = 1; o < 32; o <<= 1) {
                int y = __shfl_up_sync(0xffffffffu, xw, o);
                if (lane >= o) xw += y;
            }
            wsum[lane] = xw - w;
        }
        __syncthreads();
        int excl = s_base + wsum[wid] + x - v;
        if (idx < NN) {
            g_rowptr[idx] = excl;
            float deg = (float)v + 1.0f;
            g_dinv[idx] = rsqrtf(deg);
            g_invdeg[idx] = 1.0f / deg;
        }
        __syncthreads();
        if (t == 1023) s_base = excl + v;
        __syncthreads();
    }
    if (t == 0) g_rowptr[NN] = s_base;
}

__global__ void k_fill(const int* __restrict__ src, const int* __restrict__ dst, int E) {
    int e = blockIdx.x * blockDim.x + threadIdx.x;
    if (e < E) {
        int s = src[e], d = dst[e];
        float w = g_dinv[s] * g_dinv[d];
        int pos = g_rowptr[d] + atomicAdd(&g_cursor[d], 1);
        g_epk[pos] = make_int2(s, __float_as_int(w));
    }
}

// ---------------- aggregation layer 1: all 12 t, vectorized gather ----------
// warp per node. groups of 8 lanes (g=lane>>3) each own one edge per batch;
// lane's float4 (sub=lane&7) covers 4 of the 32 features. 4 edges / LDG.128.
__global__ __launch_bounds__(256) void k_agg32(const float* __restrict__ x) {
    int lane = threadIdx.x & 31;
    int n = blockIdx.x * 8 + (threadIdx.x >> 5);
    if (n >= NN) return;
    int g = lane >> 3, sub = lane & 7;
    const float4* __restrict__ x4 = (const float4*)x;   // [T][N][8]
    int r0 = g_rowptr[n], r1 = g_rowptr[n + 1];
    float2 acc[TT][2];
    #pragma unroll
    for (int t = 0; t < TT; t++) { acc[t][0] = make_float2(0.f, 0.f); acc[t][1] = make_float2(0.f, 0.f); }
    for (int tile = r0; tile < r1; tile += 32) {
        int2 ep = (tile + lane < r1) ? g_epk[tile + lane] : make_int2(0, 0);
        int nb = r1 - tile; if (nb > 32) nb = 32;
        for (int b = 0; b * 4 < nb; b++) {
            int ss = __shfl_sync(0xffffffffu, ep.x, b * 4 + g);
            float ww = __int_as_float(__shfl_sync(0xffffffffu, ep.y, b * 4 + g));
            float2 w2 = make_float2(ww, ww);
            const float4* p = x4 + (size_t)ss * 8 + sub;
            #pragma unroll
            for (int t = 0; t < TT; t++) {
                float4 v = p[(size_t)t * (NN * 8)];
                acc[t][0] = ffma2(w2, make_float2(v.x, v.y), acc[t][0]);
                acc[t][1] = ffma2(w2, make_float2(v.z, v.w), acc[t][1]);
            }
        }
    }
    if (g == 0) {   // self-loop contribution (added once, pre-reduction)
        float id = g_invdeg[n];
        float2 w2 = make_float2(id, id);
        const float4* p = x4 + (size_t)n * 8 + sub;
        #pragma unroll
        for (int t = 0; t < TT; t++) {
            float4 v = p[(size_t)t * (NN * 8)];
            acc[t][0] = ffma2(w2, make_float2(v.x, v.y), acc[t][0]);
            acc[t][1] = ffma2(w2, make_float2(v.z, v.w), acc[t][1]);
        }
    }
    float4* o4 = (float4*)BUFA;
    #pragma unroll
    for (int t = 0; t < TT; t++) {
        float2 a0 = acc[t][0], a1 = acc[t][1];
        #pragma unroll
        for (int off = 8; off <= 16; off <<= 1) {
            a0.x += __shfl_xor_sync(0xffffffffu, a0.x, off);
            a0.y += __shfl_xor_sync(0xffffffffu, a0.y, off);
            a1.x += __shfl_xor_sync(0xffffffffu, a1.x, off);
            a1.y += __shfl_xor_sync(0xffffffffu, a1.y, off);
        }
        if (g == t / 3)
            o4[(size_t)t * (NN * 8) + (size_t)n * 8 + sub] = make_float4(a0.x, a0.y, a1.x, a1.y);
    }
}

// ---------------- aggregation layer 2: fp16 rows, 2 chunks of 6 t ----------
__global__ __launch_bounds__(256) void k_agg64() {
    int lane = threadIdx.x & 31;
    int n = blockIdx.x * 8 + (threadIdx.x >> 5);
    if (n >= NN) return;
    int g = lane >> 3, sub = lane & 7;
    int r0 = g_rowptr[n], r1 = g_rowptr[n + 1];
    float id = g_invdeg[n];
    float4* o4 = (float4*)BUFA;
    #pragma unroll 1
    for (int c = 0; c < 2; c++) {
        const uint4* __restrict__ hb = g_h1u4 + (size_t)(c * 6) * NN * 8;
        float2 acc[6][4];
        #pragma unroll
        for (int t = 0; t < 6; t++)
            #pragma unroll
            for (int j = 0; j < 4; j++) acc[t][j] = make_float2(0.f, 0.f);
        for (int tile = r0; tile < r1; tile += 32) {
            int2 ep = (tile + lane < r1) ? g_epk[tile + lane] : make_int2(0, 0);
            int nb = r1 - tile; if (nb > 32) nb = 32;
            for (int b = 0; b * 4 < nb; b++) {
                int ss = __shfl_sync(0xffffffffu, ep.x, b * 4 + g);
                float ww = __int_as_float(__shfl_sync(0xffffffffu, ep.y, b * 4 + g));
                float2 w2 = make_float2(ww, ww);
                const uint4* p = hb + (size_t)ss * 8 + sub;
                #pragma unroll
                for (int t = 0; t < 6; t++) {
                    uint4 hv = p[(size_t)t * (NN * 8)];
                    acc[t][0] = ffma2(w2, h2f2(hv.x), acc[t][0]);
                    acc[t][1] = ffma2(w2, h2f2(hv.y), acc[t][1]);
                    acc[t][2] = ffma2(w2, h2f2(hv.z), acc[t][2]);
                    acc[t][3] = ffma2(w2, h2f2(hv.w), acc[t][3]);
                }
            }
        }
        if (g == 0) {
            float2 w2 = make_float2(id, id);
            const uint4* p = hb + (size_t)n * 8 + sub;
            #pragma unroll
            for (int t = 0; t < 6; t++) {
                uint4 hv = p[(size_t)t * (NN * 8)];
                acc[t][0] = ffma2(w2, h2f2(hv.x), acc[t][0]);
                acc[t][1] = ffma2(w2, h2f2(hv.y), acc[t][1]);
                acc[t][2] = ffma2(w2, h2f2(hv.z), acc[t][2]);
                acc[t][3] = ffma2(w2, h2f2(hv.w), acc[t][3]);
            }
        }
        #pragma unroll
        for (int t = 0; t < 6; t++) {
            #pragma unroll
            for (int j = 0; j < 4; j++) {
                float2 a = acc[t][j];
                #pragma unroll
                for (int off = 8; off <= 16; off <<= 1) {
                    a.x += __shfl_xor_sync(0xffffffffu, a.x, off);
                    a.y += __shfl_xor_sync(0xffffffffu, a.y, off);
                }
                acc[t][j] = a;
            }
            if (g == (t & 3)) {
                size_t base = ((size_t)(c * 6 + t) * NN + n) * 16 + sub * 2;
                o4[base]     = make_float4(acc[t][0].x, acc[t][0].y, acc[t][1].x, acc[t][1].y);
                o4[base + 1] = make_float4(acc[t][2].x, acc[t][2].y, acc[t][3].x, acc[t][3].y);
            }
        }
    }
}

// ---------------- dense layer 1: h1 = relu(BUFA(32) @ W1 + b1) -> fp16 ------
// 8-row tiles per warp to amortize LDS.
__global__ __launch_bounds__(256) void k_gemm1(const float* __restrict__ W,
                                               const float* __restrict__ b) {
    __shared__ float2 Wsm[32 * 32];
    int tid = threadIdx.x;
    for (int i = tid; i < 32 * 32; i += 256) {
        int f = i >> 5, p = i & 31;
        Wsm[i] = make_float2(W[f * 64 + p], W[f * 64 + p + 32]);
    }
    __syncthreads();
    int lane = tid & 31;
    float2 bias = make_float2(b[lane], b[lane + 32]);
    for (int tile = blockIdx.x * 8 + (tid >> 5); tile < ROWS / 8; tile += gridDim.x * 8) {
        int row0 = tile * 8;
        float xv[8];
        #pragma unroll
        for (int r = 0; r < 8; r++) xv[r] = BUFA[(size_t)(row0 + r) * FF + lane];
        float2 acc[8];
        #pragma unroll
        for (int r = 0; r < 8; r++) acc[r] = bias;
        #pragma unroll 8
        for (int f = 0; f < 32; f++) {
            float2 w = Wsm[f * 32 + lane];
            #pragma unroll
            for (int r = 0; r < 8; r++) {
                float s = __shfl_sync(0xffffffffu, xv[r], f);
                acc[r] = ffma2(make_float2(s, s), w, acc[r]);
            }
        }
        #pragma unroll
        for (int r = 0; r < 8; r++) {
            __half* o = H1H + (size_t)(row0 + r) * 64;
            o[lane] = __float2half_rn(fmaxf(acc[r].x, 0.f));
            o[lane + 32] = __float2half_rn(fmaxf(acc[r].y, 0.f));
        }
    }
}

// ---------------- fused: h2 = relu(BUFA(64)@W2+b2); gi = h2@Wih^T+bih -------
// 4-row tiles; 64KB dynamic smem (W2 pairs 16KB + Wih-T 48KB)
__global__ __launch_bounds__(256) void k_h2gi(const float* __restrict__ W2,
                                              const float* __restrict__ b2,
                                              const float* __restrict__ Wih,
                                              const float* __restrict__ bih) {
    extern __shared__ float2 sm[];
    float2* W2s = sm;            // [64*32]
    float2* Ws  = sm + 2048;     // [64*96]
    int tid = threadIdx.x;
    for (int i = tid; i < 2048; i += 256) {
        int f = i >> 5, p = i & 31;
        W2s[i] = make_float2(W2[f * 64 + p], W2[f * 64 + p + 32]);
    }
    for (int i = tid; i < 6144; i += 256) {
        int h = i / 96, m = i % 96, p = m >> 5, l = m & 31;
        Ws[i] = make_float2(Wih[(p * 64 + l) * 64 + h], Wih[(p * 64 + l + 32) * 64 + h]);
    }
    __syncthreads();
    int lane = tid & 31;
    float2 bias1 = make_float2(b2[lane], b2[lane + 32]);
    float2 bias2[3];
    #pragma unroll
    for (int p = 0; p < 3; p++)
        bias2[p] = make_float2(bih[p * 64 + lane], bih[p * 64 + lane + 32]);
    for (int tile = blockIdx.x * 8 + (tid >> 5); tile < ROWS / 4; tile += gridDim.x * 8) {
        int row0 = tile * 4;
        float x0[4], x1[4];
        #pragma unroll
        for (int r = 0; r < 4; r++) {
            x0[r] = BUFA[(size_t)(row0 + r) * 64 + lane];
            x1[r] = BUFA[(size_t)(row0 + r) * 64 + 32 + lane];
        }
        float2 a1[4];
        #pragma unroll
        for (int r = 0; r < 4; r++) a1[r] = bias1;
        #pragma unroll 8
        for (int h = 0; h < 32; h++) {
            float2 w = W2s[h * 32 + lane];
            #pragma unroll
            for (int r = 0; r < 4; r++) {
                float s = __shfl_sync(0xffffffffu, x0[r], h);
                a1[r] = ffma2(make_float2(s, s), w, a1[r]);
            }
        }
        #pragma unroll 8
        for (int h = 0; h < 32; h++) {
            float2 w = W2s[(h + 32) * 32 + lane];
            #pragma unroll
            for (int r = 0; r < 4; r++) {
                float s = __shfl_sync(0xffffffffu, x1[r], h);
                a1[r] = ffma2(make_float2(s, s), w, a1[r]);
            }
        }
        float y0[4], y1[4];
        #pragma unroll
        for (int r = 0; r < 4; r++) {
            y0[r] = fmaxf(a1[r].x, 0.f);
            y1[r] = fmaxf(a1[r].y, 0.f);
        }
        float2 a2[4][3];
        #pragma unroll
        for (int r = 0; r < 4; r++)
            #pragma unroll
            for (int p = 0; p < 3; p++) a2[r][p] = bias2[p];
        #pragma unroll 8
        for (int h = 0; h < 32; h++) {
            float2 w0 = Ws[h * 96 + lane], w1 = Ws[h * 96 + 32 + lane], w2 = Ws[h * 96 + 64 + lane];
            #pragma unroll
            for (int r = 0; r < 4; r++) {
                float s = __shfl_sync(0xffffffffu, y0[r], h);
                float2 s2 = make_float2(s, s);
                a2[r][0] = ffma2(s2, w0, a2[r][0]);
                a2[r][1] = ffma2(s2, w1, a2[r][1]);
                a2[r][2] = ffma2(s2, w2, a2[r][2]);
            }
        }
        #pragma unroll 8
        for (int h = 0; h < 32; h++) {
            float2 w0 = Ws[(h + 32) * 96 + lane], w1 = Ws[(h + 32) * 96 + 32 + lane], w2 = Ws[(h + 32) * 96 + 64 + lane];
            #pragma unroll
            for (int r = 0; r < 4; r++) {
                float s = __shfl_sync(0xffffffffu, y1[r], h);
                float2 s2 = make_float2(s, s);
                a2[r][0] = ffma2(s2, w0, a2[r][0]);
                a2[r][1] = ffma2(s2, w1, a2[r][1]);
                a2[r][2] = ffma2(s2, w2, a2[r][2]);
            }
        }
        #pragma unroll
        for (int r = 0; r < 4; r++) {
            __half* o = GIH + (size_t)(row0 + r) * 192;
            #pragma unroll
            for (int p = 0; p < 3; p++) {
                o[p * 64 + lane] = __float2half_rn(a2[r][p].x);
                o[p * 64 + 32 + lane] = __float2half_rn(a2[r][p].y);
            }
        }
    }
}

// ---------------- GRU step (gh half + gates) --------------------------------
__global__ __launch_bounds__(256) void k_gru(const float* __restrict__ Whh,
                                             const float* __restrict__ bhh,
                                             int t, int par, int zero) {
    const float* hprev = par ? H1P : H0P;
    float* hnext = par ? H0P : H1P;
    __shared__ float2 Wsm[64 * 96];
    int tid = threadIdx.x;
    if (!zero) {
        for (int i = tid; i < 64 * 96; i += 256) {
            int h = i / 96, m = i % 96, p = m >> 5, l = m & 31;
            Wsm[i] = make_float2(Whh[(p * 64 + l) * 64 + h], Whh[(p * 64 + l + 32) * 64 + h]);
        }
        __syncthreads();
    }
    int lane = tid & 31;
    const __half* gi_base = GIH + (size_t)t * NN * 192;
    float2 bias[3];
    #pragma unroll
    for (int p = 0; p < 3; p++)
        bias[p] = make_float2(bhh[p * 64 + lane], bhh[p * 64 + lane + 32]);
    int nwarps = gridDim.x * 8;
    for (int tile = blockIdx.x * 8 + (tid >> 5); tile < NN / 4; tile += nwarps) {
        int n0 = tile * 4;
        float xa[4], xb[4];
        float2 acc[4][3];
        #pragma unroll
        for (int r = 0; r < 4; r++)
            #pragma unroll
            for (int p = 0; p < 3; p++) acc[r][p] = bias[p];
        if (!zero) {
            #pragma unroll
            for (int r = 0; r < 4; r++) {
                xa[r] = hprev[(size_t)(n0 + r) * 64 + lane];
                xb[r] = hprev[(size_t)(n0 + r) * 64 + 32 + lane];
            }
            #pragma unroll 8
            for (int h = 0; h < 32; h++) {
                float2 w0 = Wsm[h * 96 + lane], w1 = Wsm[h * 96 + 32 + lane], w2 = Wsm[h * 96 + 64 + lane];
                #pragma unroll
                for (int r = 0; r < 4; r++) {
                    float xv = __shfl_sync(0xffffffffu, xa[r], h);
                    float2 xv2 = make_float2(xv, xv);
                    acc[r][0] = ffma2(xv2, w0, acc[r][0]);
                    acc[r][1] = ffma2(xv2, w1, acc[r][1]);
                    acc[r][2] = ffma2(xv2, w2, acc[r][2]);
                }
            }
            #pragma unroll 8
            for (int h = 0; h < 32; h++) {
                float2 w0 = Wsm[(h + 32) * 96 + lane], w1 = Wsm[(h + 32) * 96 + 32 + lane], w2 = Wsm[(h + 32) * 96 + 64 + lane];
                #pragma unroll
                for (int r = 0; r < 4; r++) {
                    float xv = __shfl_sync(0xffffffffu, xb[r], h);
                    float2 xv2 = make_float2(xv, xv);
                    acc[r][0] = ffma2(xv2, w0, acc[r][0]);
                    acc[r][1] = ffma2(xv2, w1, acc[r][1]);
                    acc[r][2] = ffma2(xv2, w2, acc[r][2]);
                }
            }
        } else {
            #pragma unroll
            for (int r = 0; r < 4; r++) { xa[r] = 0.f; xb[r] = 0.f; }
        }
        #pragma unroll
        for (int r = 0; r < 4; r++) {
            const __half* gir = gi_base + (size_t)(n0 + r) * 192;
            float2 i_r = make_float2(__half2float(gir[lane]), __half2float(gir[32 + lane]));
            float2 i_z = make_float2(__half2float(gir[64 + lane]), __half2float(gir[96 + lane]));
            float2 i_n = make_float2(__half2float(gir[128 + lane]), __half2float(gir[160 + lane]));
            float2 rg, zg, ng, hn;
            rg.x = sigf(i_r.x + acc[r][0].x); rg.y = sigf(i_r.y + acc[r][0].y);
            zg.x = sigf(i_z.x + acc[r][1].x); zg.y = sigf(i_z.y + acc[r][1].y);
            ng.x = tanhf(i_n.x + rg.x * acc[r][2].x);
            ng.y = tanhf(i_n.y + rg.y * acc[r][2].y);
            hn.x = (1.f - zg.x) * ng.x + zg.x * xa[r];
            hn.y = (1.f - zg.y) * ng.y + zg.y * xb[r];
            hnext[(size_t)(n0 + r) * 64 + lane] = hn.x;
            hnext[(size_t)(n0 + r) * 64 + 32 + lane] = hn.y;
        }
    }
}

// ---------------- classifier head + state cleanup ---------------------------
__global__ __launch_bounds__(256) void k_cls(const float* __restrict__ Wc1,
                                             const float* __restrict__ bc1,
                                             const float* __restrict__ Wc2,
                                             const float* __restrict__ bc2,
                                             float* __restrict__ out) {
    int gid = blockIdx.x * blockDim.x + threadIdx.x;
    if (gid < NN) { g_degi[gid] = 0; g_cursor[gid] = 0; }

    __shared__ float W1s[64 * 32];
    __shared__ float w2s[32], b1s[32];
    int tid = threadIdx.x;
    for (int i = tid; i < 2048; i += 256) W1s[i] = Wc1[i];
    if (tid < 32) { w2s[tid] = Wc2[tid]; b1s[tid] = bc1[tid]; }
    __syncthreads();
    int lane = tid & 31;
    int n = blockIdx.x * 8 + (tid >> 5);
    if (n >= NN) return;
    float h0 = H0P[(size_t)n * 64 + lane];
    float h1 = H0P[(size_t)n * 64 + 32 + lane];
    float acc = b1s[lane];
    #pragma unroll
    for (int h = 0; h < 32; h++) {
        float xv = __shfl_sync(0xffffffffu, h0, h);
        acc = fmaf(xv, W1s[h * 32 + lane], acc);
    }
    #pragma unroll
    for (int h = 0; h < 32; h++) {
        float xv = __shfl_sync(0xffffffffu, h1, h);
        acc = fmaf(xv, W1s[(h + 32) * 32 + lane], acc);
    }
    acc = fmaxf(acc, 0.f);
    float p = acc * w2s[lane];
    #pragma unroll
    for (int off = 16; off; off >>= 1) p += __shfl_xor_sync(0xffffffffu, p, off);
    if (lane == 0) out[n] = p + bc2[0];
}

// ---------------- launch ----------------------------------------------------
extern "C" void kernel_launch(void* const* d_in, const int* in_sizes, int n_in,
                              void* d_out, int out_size) {
    const float* x   = (const float*)d_in[0];
    const int*   ei  = (const int*)d_in[1];
    const float* W1  = (const float*)d_in[2];
    const float* b1  = (const float*)d_in[3];
    const float* W2  = (const float*)d_in[4];
    const float* b2  = (const float*)d_in[5];
    const float* Wih = (const float*)d_in[6];
    const float* Whh = (const float*)d_in[7];
    const float* bih = (const float*)d_in[8];
    const float* bhh = (const float*)d_in[9];
    const float* Wc1 = (const float*)d_in[10];
    const float* bc1 = (const float*)d_in[11];
    const float* Wc2 = (const float*)d_in[12];
    const float* bc2 = (const float*)d_in[13];
    float* out = (float*)d_out;

    int E = in_sizes[1] / 2;
    const int* src = ei;
    const int* dst = ei + E;

    // h2gi needs 64KB dynamic smem (opt-in); host-side attribute set, not captured
    cudaFuncSetAttribute(k_h2gi, cudaFuncAttributeMaxDynamicSharedMemorySize, 65536);

    // graph preprocessing (degi/cursor arrive zeroed: static init or prior cleanup)
    k_count<<<(E + 255) / 256, 256>>>(dst, E);
    k_scan_norm<<<1, 1024>>>();
    k_fill<<<(E + 255) / 256, 256>>>(src, dst, E);

    // layer 1: P1 = Ahat * x (all t) -> BUFA(32);  h1 = relu(P1 @ W1 + b1) -> fp16
    k_agg32<<<NN / 8, 256>>>(x);
    k_gemm1<<<1184, 256>>>(W1, b1);

    // layer 2: P2 = Ahat * h1 (all t) -> BUFA(64)
    k_agg64<<<NN / 8, 256>>>();

    // fused h2 = relu(P2 @ W2 + b2); gi = h2 @ W_ih^T + b_ih -> fp16 GIH
    k_h2gi<<<444, 256, 65536>>>(W2, b2, Wih, bih);

    // GRU scan: 12 steps ping-pong H0/H1, t=0 from h=0, final in H0
    for (int t = 0; t < TT; t++)
        k_gru<<<592, 256>>>(Whh, bhh, t, t & 1, t == 0 ? 1 : 0);

    // classifier head (+ zero degi/cursor for next call)
    k_cls<<<(NN + 7) / 8, 256>>>(Wc1, bc1, Wc2, bc2, out);
}

// round 5
// speedup vs baseline: 1.4988x; 1.2651x over previous
#include <cuda_runtime.h>
#include <cuda_fp16.h>
#include <math.h>

// Problem constants
constexpr int TT = 12;
constexpr int NN = 50000;
constexpr int FF = 32;
constexpr int HH = 64;
constexpr int EE = 1600000;
constexpr int ROWS = TT * NN;     // 600000

// ---------------- static device scratch (zero-initialized at load) ---------
__device__ int     g_degi[NN];        // zeroed at end of each call (and at load)
__device__ int     g_cursor[NN];      // same
__device__ float   g_dinv[NN];
__device__ float   g_invdeg[NN];
__device__ int     g_rowptr[NN + 1];
__device__ int2    g_epk[EE];                              // packed (src, w)
__device__ float4  g_bufA4[(size_t)ROWS * HH / 4];         // 153.6 MB fp32
__device__ uint4   g_h1u4[(size_t)ROWS * HH / 8];          // 76.8 MB h1 fp16
__device__ __half2 g_gih2[(size_t)ROWS * 3 * HH / 2];      // 230.4 MB gi fp16
__device__ float4  g_h0_4[(size_t)NN * HH / 4];

#define BUFA ((float*)g_bufA4)
#define H1H  ((__half*)g_h1u4)
#define GIH  ((__half*)g_gih2)
#define H0P  ((float*)g_h0_4)

// ---------------- packed f32x2 FMA (sm_10x) --------------------------------
union F2U { float2 f; unsigned long long u; };
__device__ __forceinline__ float2 ffma2(float2 a, float2 b, float2 c) {
    F2U A, B, C, D; A.f = a; B.f = b; C.f = c;
    asm("fma.rn.f32x2 %0, %1, %2, %3;" : "=l"(D.u) : "l"(A.u), "l"(B.u), "l"(C.u));
    return D.f;
}
__device__ __forceinline__ float2 h2f2(unsigned int u) {
    __half2 h = *reinterpret_cast<const __half2*>(&u);
    return __half22float2(h);
}
__device__ __forceinline__ float sigf(float x) { return 1.f / (1.f + expf(-x)); }

// ---------------- preprocessing --------------------------------------------
__global__ void k_count(const int* __restrict__ dst, int E) {
    int e = blockIdx.x * blockDim.x + threadIdx.x;
    if (e < E) atomicAdd(&g_degi[dst[e]], 1);
}

__global__ void k_scan_norm() {
    __shared__ int wsum[32];
    __shared__ int s_base;
    int t = threadIdx.x, lane = t & 31, wid = t >> 5;
    if (t == 0) s_base = 0;
    __syncthreads();
    for (int base = 0; base < NN; base += 1024) {
        int idx = base + t;
        int v = (idx < NN) ? g_degi[idx] : 0;
        int x = v;
        #pragma unroll
        for (int o = 1; o < 32; o <<= 1) {
            int y = __shfl_up_sync(0xffffffffu, x, o);
            if (lane >= o) x += y;
        }
        if (lane == 31) wsum[wid] = x;
        __syncthreads();
        if (wid == 0) {
            int w = wsum[lane];
            int xw = w;
            #pragma unroll
            for (int o = 1; o < 32; o <<= 1) {
                int y = __shfl_up_sync(0xffffffffu, xw, o);
                if (lane >= o) xw += y;
            }
            wsum[lane] = xw - w;
        }
        __syncthreads();
        int excl = s_base + wsum[wid] + x - v;
        if (idx < NN) {
            g_rowptr[idx] = excl;
            float deg = (float)v + 1.0f;
            g_dinv[idx] = rsqrtf(deg);
            g_invdeg[idx] = 1.0f / deg;
        }
        __syncthreads();
        if (t == 1023) s_base = excl + v;
        __syncthreads();
    }
    if (t == 0) g_rowptr[NN] = s_base;
}

__global__ void k_fill(const int* __restrict__ src, const int* __restrict__ dst, int E) {
    int e = blockIdx.x * blockDim.x + threadIdx.x;
    if (e < E) {
        int s = src[e], d = dst[e];
        float w = g_dinv[s] * g_dinv[d];
        int pos = g_rowptr[d] + atomicAdd(&g_cursor[d], 1);
        g_epk[pos] = make_int2(s, __float_as_int(w));
    }
}

// ---------------- aggregation layer 1: 6 t per launch slice -----------------
// warp per node; blockIdx.y selects t-chunk. 8 lanes per edge row, float4/lane.
__global__ __launch_bounds__(256) void k_agg32(const float* __restrict__ x) {
    int lane = threadIdx.x & 31;
    int n = blockIdx.x * 8 + (threadIdx.x >> 5);
    if (n >= NN) return;
    int c = blockIdx.y;                                  // 0 or 1
    int g = lane >> 3, sub = lane & 7;
    const float4* __restrict__ x4 = (const float4*)x + (size_t)(c * 6) * NN * 8 + sub;
    int r0 = g_rowptr[n], r1 = g_rowptr[n + 1];
    float2 acc[6][2];
    #pragma unroll
    for (int t = 0; t < 6; t++) { acc[t][0] = make_float2(0.f, 0.f); acc[t][1] = make_float2(0.f, 0.f); }
    int2 ep = (r0 + lane < r1) ? g_epk[r0 + lane] : make_int2(0, 0);
    for (int tile = r0; tile < r1; tile += 32) {
        int2 epc = ep;
        int nxt = tile + 32;
        if (nxt < r1) ep = (nxt + lane < r1) ? g_epk[nxt + lane] : make_int2(0, 0);
        int nb = r1 - tile; if (nb > 32) nb = 32;
        for (int b = 0; b * 4 < nb; b++) {
            int ss = __shfl_sync(0xffffffffu, epc.x, b * 4 + g);
            float ww = __int_as_float(__shfl_sync(0xffffffffu, epc.y, b * 4 + g));
            float2 w2 = make_float2(ww, ww);
            const float4* p = x4 + (size_t)ss * 8;
            #pragma unroll
            for (int t = 0; t < 6; t++) {
                float4 v = p[(size_t)t * (NN * 8)];
                acc[t][0] = ffma2(w2, make_float2(v.x, v.y), acc[t][0]);
                acc[t][1] = ffma2(w2, make_float2(v.z, v.w), acc[t][1]);
            }
        }
    }
    if (g == 0) {   // self-loop, added once pre-reduction
        float id = g_invdeg[n];
        float2 w2 = make_float2(id, id);
        const float4* p = x4 + (size_t)n * 8;
        #pragma unroll
        for (int t = 0; t < 6; t++) {
            float4 v = p[(size_t)t * (NN * 8)];
            acc[t][0] = ffma2(w2, make_float2(v.x, v.y), acc[t][0]);
            acc[t][1] = ffma2(w2, make_float2(v.z, v.w), acc[t][1]);
        }
    }
    float4* o4 = (float4*)BUFA + (size_t)(c * 6) * NN * 8;
    #pragma unroll
    for (int t = 0; t < 6; t++) {
        float2 a0 = acc[t][0], a1 = acc[t][1];
        #pragma unroll
        for (int off = 8; off <= 16; off <<= 1) {
            a0.x += __shfl_xor_sync(0xffffffffu, a0.x, off);
            a0.y += __shfl_xor_sync(0xffffffffu, a0.y, off);
            a1.x += __shfl_xor_sync(0xffffffffu, a1.x, off);
            a1.y += __shfl_xor_sync(0xffffffffu, a1.y, off);
        }
        if (g == (t & 3))
            o4[(size_t)t * (NN * 8) + (size_t)n * 8 + sub] = make_float4(a0.x, a0.y, a1.x, a1.y);
    }
}

// ---------------- aggregation layer 2: fp16 rows, 6 t per launch slice ------
__global__ __launch_bounds__(256) void k_agg64() {
    int lane = threadIdx.x & 31;
    int n = blockIdx.x * 8 + (threadIdx.x >> 5);
    if (n >= NN) return;
    int c = blockIdx.y;
    int g = lane >> 3, sub = lane & 7;
    int r0 = g_rowptr[n], r1 = g_rowptr[n + 1];
    const uint4* __restrict__ hb = g_h1u4 + (size_t)(c * 6) * NN * 8 + sub;
    float2 acc[6][4];
    #pragma unroll
    for (int t = 0; t < 6; t++)
        #pragma unroll
        for (int j = 0; j < 4; j++) acc[t][j] = make_float2(0.f, 0.f);
    int2 ep = (r0 + lane < r1) ? g_epk[r0 + lane] : make_int2(0, 0);
    for (int tile = r0; tile < r1; tile += 32) {
        int2 epc = ep;
        int nxt = tile + 32;
        if (nxt < r1) ep = (nxt + lane < r1) ? g_epk[nxt + lane] : make_int2(0, 0);
        int nb = r1 - tile; if (nb > 32) nb = 32;
        for (int b = 0; b * 4 < nb; b++) {
            int ss = __shfl_sync(0xffffffffu, epc.x, b * 4 + g);
            float ww = __int_as_float(__shfl_sync(0xffffffffu, epc.y, b * 4 + g));
            float2 w2 = make_float2(ww, ww);
            const uint4* p = hb + (size_t)ss * 8;
            #pragma unroll
            for (int t = 0; t < 6; t++) {
                uint4 hv = p[(size_t)t * (NN * 8)];
                acc[t][0] = ffma2(w2, h2f2(hv.x), acc[t][0]);
                acc[t][1] = ffma2(w2, h2f2(hv.y), acc[t][1]);
                acc[t][2] = ffma2(w2, h2f2(hv.z), acc[t][2]);
                acc[t][3] = ffma2(w2, h2f2(hv.w), acc[t][3]);
            }
        }
    }
    if (g == 0) {
        float id = g_invdeg[n];
        float2 w2 = make_float2(id, id);
        const uint4* p = hb + (size_t)n * 8;
        #pragma unroll
        for (int t = 0; t < 6; t++) {
            uint4 hv = p[(size_t)t * (NN * 8)];
            acc[t][0] = ffma2(w2, h2f2(hv.x), acc[t][0]);
            acc[t][1] = ffma2(w2, h2f2(hv.y), acc[t][1]);
            acc[t][2] = ffma2(w2, h2f2(hv.z), acc[t][2]);
            acc[t][3] = ffma2(w2, h2f2(hv.w), acc[t][3]);
        }
    }
    float4* o4 = (float4*)BUFA;
    #pragma unroll
    for (int t = 0; t < 6; t++) {
        #pragma unroll
        for (int j = 0; j < 4; j++) {
            float2 a = acc[t][j];
            #pragma unroll
            for (int off = 8; off <= 16; off <<= 1) {
                a.x += __shfl_xor_sync(0xffffffffu, a.x, off);
                a.y += __shfl_xor_sync(0xffffffffu, a.y, off);
            }
            acc[t][j] = a;
        }
        if (g == (t & 3)) {
            size_t base = ((size_t)(c * 6 + t) * NN + n) * 16 + sub * 2;
            o4[base]     = make_float4(acc[t][0].x, acc[t][0].y, acc[t][1].x, acc[t][1].y);
            o4[base + 1] = make_float4(acc[t][2].x, acc[t][2].y, acc[t][3].x, acc[t][3].y);
        }
    }
}

// ---------------- dense layer 1: h1 = relu(BUFA(32) @ W1 + b1) -> fp16 ------
__global__ __launch_bounds__(256) void k_gemm1(const float* __restrict__ W,
                                               const float* __restrict__ b) {
    __shared__ float2 Wsm[32 * 32];
    int tid = threadIdx.x;
    for (int i = tid; i < 32 * 32; i += 256) {
        int f = i >> 5, p = i & 31;
        Wsm[i] = make_float2(W[f * 64 + p], W[f * 64 + p + 32]);
    }
    __syncthreads();
    int lane = tid & 31;
    float2 bias = make_float2(b[lane], b[lane + 32]);
    for (int tile = blockIdx.x * 8 + (tid >> 5); tile < ROWS / 8; tile += gridDim.x * 8) {
        int row0 = tile * 8;
        float xv[8];
        #pragma unroll
        for (int r = 0; r < 8; r++) xv[r] = BUFA[(size_t)(row0 + r) * FF + lane];
        float2 acc[8];
        #pragma unroll
        for (int r = 0; r < 8; r++) acc[r] = bias;
        #pragma unroll 8
        for (int f = 0; f < 32; f++) {
            float2 w = Wsm[f * 32 + lane];
            #pragma unroll
            for (int r = 0; r < 8; r++) {
                float s = __shfl_sync(0xffffffffu, xv[r], f);
                acc[r] = ffma2(make_float2(s, s), w, acc[r]);
            }
        }
        #pragma unroll
        for (int r = 0; r < 8; r++) {
            __half* o = H1H + (size_t)(row0 + r) * 64;
            o[lane] = __float2half_rn(fmaxf(acc[r].x, 0.f));
            o[lane + 32] = __float2half_rn(fmaxf(acc[r].y, 0.f));
        }
    }
}

// ---------------- fused: h2 = relu(BUFA(64)@W2+b2); gi = h2@Wih^T+bih -------
__global__ __launch_bounds__(256) void k_h2gi(const float* __restrict__ W2,
                                              const float* __restrict__ b2,
                                              const float* __restrict__ Wih,
                                              const float* __restrict__ bih) {
    extern __shared__ float2 sm[];
    float2* W2s = sm;            // [64*32]
    float2* Ws  = sm + 2048;     // [64*96]
    int tid = threadIdx.x;
    for (int i = tid; i < 2048; i += 256) {
        int f = i >> 5, p = i & 31;
        W2s[i] = make_float2(W2[f * 64 + p], W2[f * 64 + p + 32]);
    }
    for (int i = tid; i < 6144; i += 256) {
        int h = i / 96, m = i % 96, p = m >> 5, l = m & 31;
        Ws[i] = make_float2(Wih[(p * 64 + l) * 64 + h], Wih[(p * 64 + l + 32) * 64 + h]);
    }
    __syncthreads();
    int lane = tid & 31;
    float2 bias1 = make_float2(b2[lane], b2[lane + 32]);
    float2 bias2[3];
    #pragma unroll
    for (int p = 0; p < 3; p++)
        bias2[p] = make_float2(bih[p * 64 + lane], bih[p * 64 + lane + 32]);
    for (int tile = blockIdx.x * 8 + (tid >> 5); tile < ROWS / 4; tile += gridDim.x * 8) {
        int row0 = tile * 4;
        float x0[4], x1[4];
        #pragma unroll
        for (int r = 0; r < 4; r++) {
            x0[r] = BUFA[(size_t)(row0 + r) * 64 + lane];
            x1[r] = BUFA[(size_t)(row0 + r) * 64 + 32 + lane];
        }
        float2 a1[4];
        #pragma unroll
        for (int r = 0; r < 4; r++) a1[r] = bias1;
        #pragma unroll 8
        for (int h = 0; h < 32; h++) {
            float2 w = W2s[h * 32 + lane];
            #pragma unroll
            for (int r = 0; r < 4; r++) {
                float s = __shfl_sync(0xffffffffu, x0[r], h);
                a1[r] = ffma2(make_float2(s, s), w, a1[r]);
            }
        }
        #pragma unroll 8
        for (int h = 0; h < 32; h++) {
            float2 w = W2s[(h + 32) * 32 + lane];
            #pragma unroll
            for (int r = 0; r < 4; r++) {
                float s = __shfl_sync(0xffffffffu, x1[r], h);
                a1[r] = ffma2(make_float2(s, s), w, a1[r]);
            }
        }
        float y0[4], y1[4];
        #pragma unroll
        for (int r = 0; r < 4; r++) {
            y0[r] = fmaxf(a1[r].x, 0.f);
            y1[r] = fmaxf(a1[r].y, 0.f);
        }
        float2 a2[4][3];
        #pragma unroll
        for (int r = 0; r < 4; r++)
            #pragma unroll
            for (int p = 0; p < 3; p++) a2[r][p] = bias2[p];
        #pragma unroll 8
        for (int h = 0; h < 32; h++) {
            float2 w0 = Ws[h * 96 + lane], w1 = Ws[h * 96 + 32 + lane], w2 = Ws[h * 96 + 64 + lane];
            #pragma unroll
            for (int r = 0; r < 4; r++) {
                float s = __shfl_sync(0xffffffffu, y0[r], h);
                float2 s2 = make_float2(s, s);
                a2[r][0] = ffma2(s2, w0, a2[r][0]);
                a2[r][1] = ffma2(s2, w1, a2[r][1]);
                a2[r][2] = ffma2(s2, w2, a2[r][2]);
            }
        }
        #pragma unroll 8
        for (int h = 0; h < 32; h++) {
            float2 w0 = Ws[(h + 32) * 96 + lane], w1 = Ws[(h + 32) * 96 + 32 + lane], w2 = Ws[(h + 32) * 96 + 64 + lane];
            #pragma unroll
            for (int r = 0; r < 4; r++) {
                float s = __shfl_sync(0xffffffffu, y1[r], h);
                float2 s2 = make_float2(s, s);
                a2[r][0] = ffma2(s2, w0, a2[r][0]);
                a2[r][1] = ffma2(s2, w1, a2[r][1]);
                a2[r][2] = ffma2(s2, w2, a2[r][2]);
            }
        }
        #pragma unroll
        for (int r = 0; r < 4; r++) {
            __half* o = GIH + (size_t)(row0 + r) * 192;
            #pragma unroll
            for (int p = 0; p < 3; p++) {
                o[p * 64 + lane] = __float2half_rn(a2[r][p].x);
                o[p * 64 + 32 + lane] = __float2half_rn(a2[r][p].y);
            }
        }
    }
}

// ---------------- fused GRU: all 12 steps, h resident in registers ----------
// Node-parallel: no cross-node deps, so each warp scans t locally.
__global__ __launch_bounds__(256) void k_gru_all(const float* __restrict__ Whh,
                                                 const float* __restrict__ bhh) {
    __shared__ float2 Wsm[64 * 96];
    int tid = threadIdx.x;
    for (int i = tid; i < 64 * 96; i += 256) {
        int h = i / 96, m = i % 96, p = m >> 5, l = m & 31;
        Wsm[i] = make_float2(Whh[(p * 64 + l) * 64 + h], Whh[(p * 64 + l + 32) * 64 + h]);
    }
    __syncthreads();
    int lane = tid & 31;
    float2 bias[3];
    #pragma unroll
    for (int p = 0; p < 3; p++)
        bias[p] = make_float2(bhh[p * 64 + lane], bhh[p * 64 + lane + 32]);
    int tile = blockIdx.x * 8 + (tid >> 5);
    if (tile >= NN / 4) return;
    int n0 = tile * 4;
    float xa[4] = {0.f, 0.f, 0.f, 0.f};     // h state, cols [lane]
    float xb[4] = {0.f, 0.f, 0.f, 0.f};     // h state, cols [lane+32]
    for (int t = 0; t < TT; t++) {
        float2 acc[4][3];
        #pragma unroll
        for (int r = 0; r < 4; r++)
            #pragma unroll
            for (int p = 0; p < 3; p++) acc[r][p] = bias[p];
        if (t) {
            #pragma unroll 8
            for (int h = 0; h < 32; h++) {
                float2 w0 = Wsm[h * 96 + lane], w1 = Wsm[h * 96 + 32 + lane], w2 = Wsm[h * 96 + 64 + lane];
                #pragma unroll
                for (int r = 0; r < 4; r++) {
                    float xv = __shfl_sync(0xffffffffu, xa[r], h);
                    float2 xv2 = make_float2(xv, xv);
                    acc[r][0] = ffma2(xv2, w0, acc[r][0]);
                    acc[r][1] = ffma2(xv2, w1, acc[r][1]);
                    acc[r][2] = ffma2(xv2, w2, acc[r][2]);
                }
            }
            #pragma unroll 8
            for (int h = 0; h < 32; h++) {
                float2 w0 = Wsm[(h + 32) * 96 + lane], w1 = Wsm[(h + 32) * 96 + 32 + lane], w2 = Wsm[(h + 32) * 96 + 64 + lane];
                #pragma unroll
                for (int r = 0; r < 4; r++) {
                    float xv = __shfl_sync(0xffffffffu, xb[r], h);
                    float2 xv2 = make_float2(xv, xv);
                    acc[r][0] = ffma2(xv2, w0, acc[r][0]);
                    acc[r][1] = ffma2(xv2, w1, acc[r][1]);
                    acc[r][2] = ffma2(xv2, w2, acc[r][2]);
                }
            }
        }
        const __half* gi_base = GIH + (size_t)t * NN * 192;
        #pragma unroll
        for (int r = 0; r < 4; r++) {
            const __half* gir = gi_base + (size_t)(n0 + r) * 192;
            float2 i_r = make_float2(__half2float(gir[lane]), __half2float(gir[32 + lane]));
            float2 i_z = make_float2(__half2float(gir[64 + lane]), __half2float(gir[96 + lane]));
            float2 i_n = make_float2(__half2float(gir[128 + lane]), __half2float(gir[160 + lane]));
            float2 rg, zg, ng;
            rg.x = sigf(i_r.x + acc[r][0].x); rg.y = sigf(i_r.y + acc[r][0].y);
            zg.x = sigf(i_z.x + acc[r][1].x); zg.y = sigf(i_z.y + acc[r][1].y);
            ng.x = tanhf(i_n.x + rg.x * acc[r][2].x);
            ng.y = tanhf(i_n.y + rg.y * acc[r][2].y);
            xa[r] = (1.f - zg.x) * ng.x + zg.x * xa[r];
            xb[r] = (1.f - zg.y) * ng.y + zg.y * xb[r];
        }
    }
    #pragma unroll
    for (int r = 0; r < 4; r++) {
        H0P[(size_t)(n0 + r) * 64 + lane] = xa[r];
        H0P[(size_t)(n0 + r) * 64 + 32 + lane] = xb[r];
    }
}

// ---------------- classifier head + state cleanup ---------------------------
__global__ __launch_bounds__(256) void k_cls(const float* __restrict__ Wc1,
                                             const float* __restrict__ bc1,
                                             const float* __restrict__ Wc2,
                                             const float* __restrict__ bc2,
                                             float* __restrict__ out) {
    int gid = blockIdx.x * blockDim.x + threadIdx.x;
    if (gid < NN) { g_degi[gid] = 0; g_cursor[gid] = 0; }

    __shared__ float W1s[64 * 32];
    __shared__ float w2s[32], b1s[32];
    int tid = threadIdx.x;
    for (int i = tid; i < 2048; i += 256) W1s[i] = Wc1[i];
    if (tid < 32) { w2s[tid] = Wc2[tid]; b1s[tid] = bc1[tid]; }
    __syncthreads();
    int lane = tid & 31;
    int n = blockIdx.x * 8 + (tid >> 5);
    if (n >= NN) return;
    float h0 = H0P[(size_t)n * 64 + lane];
    float h1 = H0P[(size_t)n * 64 + 32 + lane];
    float acc = b1s[lane];
    #pragma unroll
    for (int h = 0; h < 32; h++) {
        float xv = __shfl_sync(0xffffffffu, h0, h);
        acc = fmaf(xv, W1s[h * 32 + lane], acc);
    }
    #pragma unroll
    for (int h = 0; h < 32; h++) {
        float xv = __shfl_sync(0xffffffffu, h1, h);
        acc = fmaf(xv, W1s[(h + 32) * 32 + lane], acc);
    }
    acc = fmaxf(acc, 0.f);
    float p = acc * w2s[lane];
    #pragma unroll
    for (int off = 16; off; off >>= 1) p += __shfl_xor_sync(0xffffffffu, p, off);
    if (lane == 0) out[n] = p + bc2[0];
}

// ---------------- launch ----------------------------------------------------
extern "C" void kernel_launch(void* const* d_in, const int* in_sizes, int n_in,
                              void* d_out, int out_size) {
    const float* x   = (const float*)d_in[0];
    const int*   ei  = (const int*)d_in[1];
    const float* W1  = (const float*)d_in[2];
    const float* b1  = (const float*)d_in[3];
    const float* W2  = (const float*)d_in[4];
    const float* b2  = (const float*)d_in[5];
    const float* Wih = (const float*)d_in[6];
    const float* Whh = (const float*)d_in[7];
    const float* bih = (const float*)d_in[8];
    const float* bhh = (const float*)d_in[9];
    const float* Wc1 = (const float*)d_in[10];
    const float* bc1 = (const float*)d_in[11];
    const float* Wc2 = (const float*)d_in[12];
    const float* bc2 = (const float*)d_in[13];
    float* out = (float*)d_out;

    int E = in_sizes[1] / 2;
    const int* src = ei;
    const int* dst = ei + E;

    cudaFuncSetAttribute(k_h2gi, cudaFuncAttributeMaxDynamicSharedMemorySize, 65536);

    // graph preprocessing
    k_count<<<(E + 255) / 256, 256>>>(dst, E);
    k_scan_norm<<<1, 1024>>>();
    k_fill<<<(E + 255) / 256, 256>>>(src, dst, E);

    // layer 1: P1 = Ahat * x (2 t-chunks) -> BUFA(32); h1 = relu(P1@W1+b1) -> fp16
    k_agg32<<<dim3(NN / 8, 2), 256>>>(x);
    k_gemm1<<<1184, 256>>>(W1, b1);

    // layer 2: P2 = Ahat * h1 (2 t-chunks) -> BUFA(64)
    k_agg64<<<dim3(NN / 8, 2), 256>>>();

    // fused h2 = relu(P2 @ W2 + b2); gi = h2 @ W_ih^T + b_ih -> fp16 GIH
    k_h2gi<<<444, 256, 65536>>>(W2, b2, Wih, bih);

    // fused GRU: all 12 steps in one kernel, h in registers
    k_gru_all<<<(NN / 4 + 7) / 8, 256>>>(Whh, bhh);

    // classifier head (+ zero degi/cursor for next call)
    k_cls<<<(NN + 7) / 8, 256>>>(Wc1, bc1, Wc2, bc2, out);
}

// round 6
// speedup vs baseline: 2.0761x; 1.3851x over previous
#include <cuda_runtime.h>
#include <cuda_fp16.h>
#include <math.h>

// Problem constants
constexpr int TT = 12;
constexpr int NN = 50000;
constexpr int FF = 32;
constexpr int HH = 64;
constexpr int EE = 1600000;
constexpr int ROWS = TT * NN;     // 600000

// ---------------- static device scratch (zero-initialized at load) ---------
__device__ int     g_degi[NN];
__device__ int     g_cursor[NN];
__device__ float   g_dinv[NN];
__device__ float   g_invdeg[NN];
__device__ int     g_rowptr[NN + 1];
__device__ int2    g_epk[EE];                              // packed (src, w)
__device__ float4  g_bufA4[(size_t)ROWS * FF / 4];         // 76.8 MB fp32 (P1)
__device__ uint4   g_h1u4[(size_t)ROWS * HH / 8];          // 76.8 MB h1 fp16
__device__ uint4   g_p2u4[(size_t)ROWS * HH / 8];          // 76.8 MB P2 fp16
__device__ __half2 g_gih2[(size_t)ROWS * 3 * HH / 2];      // 230.4 MB gi fp16
__device__ float4  g_h0_4[(size_t)NN * HH / 4];

#define BUFA ((float*)g_bufA4)
#define H1H  ((__half*)g_h1u4)
#define P2H  ((__half*)g_p2u4)
#define GIH  ((__half*)g_gih2)
#define H0P  ((float*)g_h0_4)

// ---------------- helpers ---------------------------------------------------
union F2U { float2 f; unsigned long long u; };
__device__ __forceinline__ float2 ffma2(float2 a, float2 b, float2 c) {
    F2U A, B, C, D; A.f = a; B.f = b; C.f = c;
    asm("fma.rn.f32x2 %0, %1, %2, %3;" : "=l"(D.u) : "l"(A.u), "l"(B.u), "l"(C.u));
    return D.f;
}
__device__ __forceinline__ float2 h2f2(unsigned int u) {
    __half2 h = *reinterpret_cast<const __half2*>(&u);
    return __half22float2(h);
}
__device__ __forceinline__ unsigned int pack2h(float a, float b) {
    __half2 h = __floats2half2_rn(a, b);
    return *reinterpret_cast<unsigned int*>(&h);
}
__device__ __forceinline__ float sigf(float x) { return 1.f / (1.f + expf(-x)); }

// m16n8k16 fp16 MMA, fp32 accumulate (A row-major, B col-major)
__device__ __forceinline__ void mma16816(float* c, const unsigned int* a, const unsigned int* b) {
    asm volatile(
        "mma.sync.aligned.m16n8k16.row.col.f32.f16.f16.f32 "
        "{%0,%1,%2,%3}, {%4,%5,%6,%7}, {%8,%9}, {%0,%1,%2,%3};\n"
        : "+f"(c[0]), "+f"(c[1]), "+f"(c[2]), "+f"(c[3])
        : "r"(a[0]), "r"(a[1]), "r"(a[2]), "r"(a[3]), "r"(b[0]), "r"(b[1]));
}

// ---------------- preprocessing --------------------------------------------
__global__ void k_count(const int* __restrict__ dst, int E) {
    int e = blockIdx.x * blockDim.x + threadIdx.x;
    if (e < E) atomicAdd(&g_degi[dst[e]], 1);
}

__global__ void k_scan_norm() {
    __shared__ int wsum[32];
    __shared__ int s_base;
    int t = threadIdx.x, lane = t & 31, wid = t >> 5;
    if (t == 0) s_base = 0;
    __syncthreads();
    for (int base = 0; base < NN; base += 1024) {
        int idx = base + t;
        int v = (idx < NN) ? g_degi[idx] : 0;
        int x = v;
        #pragma unroll
        for (int o = 1; o < 32; o <<= 1) {
            int y = __shfl_up_sync(0xffffffffu, x, o);
            if (lane >= o) x += y;
        }
        if (lane == 31) wsum[wid] = x;
        __syncthreads();
        if (wid == 0) {
            int w = wsum[lane];
            int xw = w;
            #pragma unroll
            for (int o = 1; o < 32; o <<= 1) {
                int y = __shfl_up_sync(0xffffffffu, xw, o);
                if (lane >= o) xw += y;
            }
            wsum[lane] = xw - w;
        }
        __syncthreads();
        int excl = s_base + wsum[wid] + x - v;
        if (idx < NN) {
            g_rowptr[idx] = excl;
            float deg = (float)v + 1.0f;
            g_dinv[idx] = rsqrtf(deg);
            g_invdeg[idx] = 1.0f / deg;
        }
        __syncthreads();
        if (t == 1023) s_base = excl + v;
        __syncthreads();
    }
    if (t == 0) g_rowptr[NN] = s_base;
}

__global__ void k_fill(const int* __restrict__ src, const int* __restrict__ dst, int E) {
    int e = blockIdx.x * blockDim.x + threadIdx.x;
    if (e < E) {
        int s = src[e], d = dst[e];
        float w = g_dinv[s] * g_dinv[d];
        int pos = g_rowptr[d] + atomicAdd(&g_cursor[d], 1);
        g_epk[pos] = make_int2(s, __float_as_int(w));
    }
}

// ---------------- aggregation layer 1: 4 t per launch slice -----------------
__global__ __launch_bounds__(256) void k_agg32(const float* __restrict__ x) {
    int lane = threadIdx.x & 31;
    int n = blockIdx.x * 8 + (threadIdx.x >> 5);
    if (n >= NN) return;
    int c = blockIdx.y;                                  // 0..2
    int g = lane >> 3, sub = lane & 7;
    const float4* __restrict__ x4 = (const float4*)x + (size_t)(c * 4) * NN * 8 + sub;
    int r0 = g_rowptr[n], r1 = g_rowptr[n + 1];
    float2 acc[4][2];
    #pragma unroll
    for (int t = 0; t < 4; t++) { acc[t][0] = make_float2(0.f, 0.f); acc[t][1] = make_float2(0.f, 0.f); }
    int2 ep = (r0 + lane < r1) ? g_epk[r0 + lane] : make_int2(0, 0);
    for (int tile = r0; tile < r1; tile += 32) {
        int2 epc = ep;
        int nxt = tile + 32;
        if (nxt < r1) ep = (nxt + lane < r1) ? g_epk[nxt + lane] : make_int2(0, 0);
        int nb = r1 - tile; if (nb > 32) nb = 32;
        for (int b = 0; b * 4 < nb; b++) {
            int ss = __shfl_sync(0xffffffffu, epc.x, b * 4 + g);
            float ww = __int_as_float(__shfl_sync(0xffffffffu, epc.y, b * 4 + g));
            float2 w2 = make_float2(ww, ww);
            const float4* p = x4 + (size_t)ss * 8;
            #pragma unroll
            for (int t = 0; t < 4; t++) {
                float4 v = p[(size_t)t * (NN * 8)];
                acc[t][0] = ffma2(w2, make_float2(v.x, v.y), acc[t][0]);
                acc[t][1] = ffma2(w2, make_float2(v.z, v.w), acc[t][1]);
            }
        }
    }
    if (g == 0) {
        float id = g_invdeg[n];
        float2 w2 = make_float2(id, id);
        const float4* p = x4 + (size_t)n * 8;
        #pragma unroll
        for (int t = 0; t < 4; t++) {
            float4 v = p[(size_t)t * (NN * 8)];
            acc[t][0] = ffma2(w2, make_float2(v.x, v.y), acc[t][0]);
            acc[t][1] = ffma2(w2, make_float2(v.z, v.w), acc[t][1]);
        }
    }
    float4* o4 = (float4*)BUFA + (size_t)(c * 4) * NN * 8;
    #pragma unroll
    for (int t = 0; t < 4; t++) {
        float2 a0 = acc[t][0], a1 = acc[t][1];
        #pragma unroll
        for (int off = 8; off <= 16; off <<= 1) {
            a0.x += __shfl_xor_sync(0xffffffffu, a0.x, off);
            a0.y += __shfl_xor_sync(0xffffffffu, a0.y, off);
            a1.x += __shfl_xor_sync(0xffffffffu, a1.x, off);
            a1.y += __shfl_xor_sync(0xffffffffu, a1.y, off);
        }
        if (g == t)
            o4[(size_t)t * (NN * 8) + (size_t)n * 8 + sub] = make_float4(a0.x, a0.y, a1.x, a1.y);
    }
}

// ---------------- aggregation layer 2: fp16 in/out, 4 t per slice -----------
__global__ __launch_bounds__(256) void k_agg64() {
    int lane = threadIdx.x & 31;
    int n = blockIdx.x * 8 + (threadIdx.x >> 5);
    if (n >= NN) return;
    int c = blockIdx.y;                                  // 0..2
    int g = lane >> 3, sub = lane & 7;
    int r0 = g_rowptr[n], r1 = g_rowptr[n + 1];
    const uint4* __restrict__ hb = g_h1u4 + (size_t)(c * 4) * NN * 8 + sub;
    float2 acc[4][4];
    #pragma unroll
    for (int t = 0; t < 4; t++)
        #pragma unroll
        for (int j = 0; j < 4; j++) acc[t][j] = make_float2(0.f, 0.f);
    int2 ep = (r0 + lane < r1) ? g_epk[r0 + lane] : make_int2(0, 0);
    for (int tile = r0; tile < r1; tile += 32) {
        int2 epc = ep;
        int nxt = tile + 32;
        if (nxt < r1) ep = (nxt + lane < r1) ? g_epk[nxt + lane] : make_int2(0, 0);
        int nb = r1 - tile; if (nb > 32) nb = 32;
        for (int b = 0; b * 4 < nb; b++) {
            int ss = __shfl_sync(0xffffffffu, epc.x, b * 4 + g);
            float ww = __int_as_float(__shfl_sync(0xffffffffu, epc.y, b * 4 + g));
            float2 w2 = make_float2(ww, ww);
            const uint4* p = hb + (size_t)ss * 8;
            #pragma unroll
            for (int t = 0; t < 4; t++) {
                uint4 hv = p[(size_t)t * (NN * 8)];
                acc[t][0] = ffma2(w2, h2f2(hv.x), acc[t][0]);
                acc[t][1] = ffma2(w2, h2f2(hv.y), acc[t][1]);
                acc[t][2] = ffma2(w2, h2f2(hv.z), acc[t][2]);
                acc[t][3] = ffma2(w2, h2f2(hv.w), acc[t][3]);
            }
        }
    }
    if (g == 0) {
        float id = g_invdeg[n];
        float2 w2 = make_float2(id, id);
        const uint4* p = hb + (size_t)n * 8;
        #pragma unroll
        for (int t = 0; t < 4; t++) {
            uint4 hv = p[(size_t)t * (NN * 8)];
            acc[t][0] = ffma2(w2, h2f2(hv.x), acc[t][0]);
            acc[t][1] = ffma2(w2, h2f2(hv.y), acc[t][1]);
            acc[t][2] = ffma2(w2, h2f2(hv.z), acc[t][2]);
            acc[t][3] = ffma2(w2, h2f2(hv.w), acc[t][3]);
        }
    }
    #pragma unroll
    for (int t = 0; t < 4; t++) {
        #pragma unroll
        for (int j = 0; j < 4; j++) {
            float2 a = acc[t][j];
            #pragma unroll
            for (int off = 8; off <= 16; off <<= 1) {
                a.x += __shfl_xor_sync(0xffffffffu, a.x, off);
                a.y += __shfl_xor_sync(0xffffffffu, a.y, off);
            }
            acc[t][j] = a;
        }
        if (g == t) {
            uint4 pk;
            pk.x = pack2h(acc[t][0].x, acc[t][0].y);
            pk.y = pack2h(acc[t][1].x, acc[t][1].y);
            pk.z = pack2h(acc[t][2].x, acc[t][2].y);
            pk.w = pack2h(acc[t][3].x, acc[t][3].y);
            g_p2u4[((size_t)(c * 4 + t) * NN + n) * 8 + sub] = pk;
        }
    }
}

// ---------------- dense layer 1: h1 = relu(BUFA(32) @ W1 + b1) -> fp16 ------
__global__ __launch_bounds__(256) void k_gemm1(const float* __restrict__ W,
                                               const float* __restrict__ b) {
    __shared__ float2 Wsm[32 * 32];
    int tid = threadIdx.x;
    for (int i = tid; i < 32 * 32; i += 256) {
        int f = i >> 5, p = i & 31;
        Wsm[i] = make_float2(W[f * 64 + p], W[f * 64 + p + 32]);
    }
    __syncthreads();
    int lane = tid & 31;
    float2 bias = make_float2(b[lane], b[lane + 32]);
    for (int tile = blockIdx.x * 8 + (tid >> 5); tile < ROWS / 8; tile += gridDim.x * 8) {
        int row0 = tile * 8;
        float xv[8];
        #pragma unroll
        for (int r = 0; r < 8; r++) xv[r] = BUFA[(size_t)(row0 + r) * FF + lane];
        float2 acc[8];
        #pragma unroll
        for (int r = 0; r < 8; r++) acc[r] = bias;
        #pragma unroll 8
        for (int f = 0; f < 32; f++) {
            float2 w = Wsm[f * 32 + lane];
            #pragma unroll
            for (int r = 0; r < 8; r++) {
                float s = __shfl_sync(0xffffffffu, xv[r], f);
                acc[r] = ffma2(make_float2(s, s), w, acc[r]);
            }
        }
        #pragma unroll
        for (int r = 0; r < 8; r++) {
            __half* o = H1H + (size_t)(row0 + r) * 64;
            o[lane] = __float2half_rn(fmaxf(acc[r].x, 0.f));
            o[lane + 32] = __float2half_rn(fmaxf(acc[r].y, 0.f));
        }
    }
}

// ---------------- fused HMMA: h2 = relu(P2@W2+b2); gi = h2@Wih^T+bih --------
// warp = 16 rows. A frags from fp16 P2 (LDG.32). Weights as fragment-ordered
// fp16 smem tables. relu(h2) C-frags ARE the A-frags of the 2nd GEMM.
__global__ __launch_bounds__(256) void k_h2gi_mma(const float* __restrict__ W2,
                                                  const float* __restrict__ b2,
                                                  const float* __restrict__ Wih,
                                                  const float* __restrict__ bih) {
    __shared__ unsigned int W2f[4 * 8 * 32 * 2];    //  8 KB
    __shared__ unsigned int Wihf[4 * 24 * 32 * 2];  // 24 KB
    __shared__ float2 B2f[8 * 32];                  //  2 KB
    __shared__ float2 Bihf[24 * 32];                //  6 KB
    int tid = threadIdx.x;
    // build B-fragment tables (b0:k=tq*2, b1:k+1, b2:k+8, b3:k+9 at col n=nt*8+gq)
    for (int i = tid; i < 4 * 8 * 32; i += 256) {
        int lane = i & 31, nt = (i >> 5) & 7, kt = i >> 8;
        int gq = lane >> 2, tq = lane & 3;
        int n = nt * 8 + gq, ks = kt * 16 + tq * 2;
        W2f[i * 2 + 0] = pack2h(W2[ks * 64 + n], W2[(ks + 1) * 64 + n]);
        W2f[i * 2 + 1] = pack2h(W2[(ks + 8) * 64 + n], W2[(ks + 9) * 64 + n]);
    }
    for (int i = tid; i < 4 * 24 * 32; i += 256) {
        int lane = i & 31, nt = (i >> 5) % 24, kt = i / (24 * 32);
        int gq = lane >> 2, tq = lane & 3;
        int gcol = nt * 8 + gq, ks = kt * 16 + tq * 2;
        // gi = h2 @ Wih^T  =>  B[k][g] = Wih[g*64 + k]
        Wihf[i * 2 + 0] = pack2h(Wih[gcol * 64 + ks], Wih[gcol * 64 + ks + 1]);
        Wihf[i * 2 + 1] = pack2h(Wih[gcol * 64 + ks + 8], Wih[gcol * 64 + ks + 9]);
    }
    for (int i = tid; i < 8 * 32; i += 256) {
        int lane = i & 31, nt = i >> 5, tq = lane & 3;
        B2f[i] = make_float2(b2[nt * 8 + tq * 2], b2[nt * 8 + tq * 2 + 1]);
    }
    for (int i = tid; i < 24 * 32; i += 256) {
        int lane = i & 31, nt = i >> 5, tq = lane & 3;
        Bihf[i] = make_float2(bih[nt * 8 + tq * 2], bih[nt * 8 + tq * 2 + 1]);
    }
    __syncthreads();

    int lane = tid & 31;
    int tile = blockIdx.x * 8 + (tid >> 5);
    if (tile >= ROWS / 16) return;
    int row0 = tile * 16;
    int gq = lane >> 2, tq = lane & 3;

    // A fragments: 16 rows x 64 k of fp16 P2
    unsigned int A[4][4];
    const unsigned int* base0 = (const unsigned int*)(P2H + (size_t)(row0 + gq) * 64);
    const unsigned int* base8 = (const unsigned int*)(P2H + (size_t)(row0 + gq + 8) * 64);
    #pragma unroll
    for (int kt = 0; kt < 4; kt++) {
        A[kt][0] = base0[kt * 8 + tq];
        A[kt][1] = base8[kt * 8 + tq];
        A[kt][2] = base0[kt * 8 + tq + 4];
        A[kt][3] = base8[kt * 8 + tq + 4];
    }

    // GEMM 1: h2 = relu(P2 @ W2 + b2)
    float c[8][4];
    #pragma unroll
    for (int nt = 0; nt < 8; nt++) {
        float2 bb = B2f[nt * 32 + lane];
        c[nt][0] = bb.x; c[nt][1] = bb.y; c[nt][2] = bb.x; c[nt][3] = bb.y;
    }
    #pragma unroll
    for (int kt = 0; kt < 4; kt++)
        #pragma unroll
        for (int nt = 0; nt < 8; nt++)
            mma16816(c[nt], A[kt], &W2f[((kt * 8 + nt) * 32 + lane) * 2]);
    #pragma unroll
    for (int nt = 0; nt < 8; nt++)
        #pragma unroll
        for (int j = 0; j < 4; j++) c[nt][j] = fmaxf(c[nt][j], 0.f);

    // C-frag -> A-frag (layouts coincide; ktile kt2 = ntiles 2kt2, 2kt2+1)
    unsigned int A2[4][4];
    #pragma unroll
    for (int kt = 0; kt < 4; kt++) {
        A2[kt][0] = pack2h(c[2 * kt][0], c[2 * kt][1]);
        A2[kt][1] = pack2h(c[2 * kt][2], c[2 * kt][3]);
        A2[kt][2] = pack2h(c[2 * kt + 1][0], c[2 * kt + 1][1]);
        A2[kt][3] = pack2h(c[2 * kt + 1][2], c[2 * kt + 1][3]);
    }

    // GEMM 2: gi = h2 @ Wih^T + bih  -> fp16 GIH
    unsigned int* gi0 = (unsigned int*)(GIH + (size_t)(row0 + gq) * 192);
    unsigned int* gi8 = (unsigned int*)(GIH + (size_t)(row0 + gq + 8) * 192);
    #pragma unroll
    for (int nt = 0; nt < 24; nt++) {
        float2 bb = Bihf[nt * 32 + lane];
        float d[4] = {bb.x, bb.y, bb.x, bb.y};
        #pragma unroll
        for (int kt = 0; kt < 4; kt++)
            mma16816(d, A2[kt], &Wihf[((kt * 24 + nt) * 32 + lane) * 2]);
        gi0[nt * 4 + tq] = pack2h(d[0], d[1]);
        gi8[nt * 4 + tq] = pack2h(d[2], d[3]);
    }
}

// ---------------- fused GRU: all 12 steps, h resident in registers ----------
__global__ __launch_bounds__(256) void k_gru_all(const float* __restrict__ Whh,
                                                 const float* __restrict__ bhh) {
    __shared__ float2 Wsm[64 * 96];
    int tid = threadIdx.x;
    for (int i = tid; i < 64 * 96; i += 256) {
        int h = i / 96, m = i % 96, p = m >> 5, l = m & 31;
        Wsm[i] = make_float2(Whh[(p * 64 + l) * 64 + h], Whh[(p * 64 + l + 32) * 64 + h]);
    }
    __syncthreads();
    int lane = tid & 31;
    float2 bias[3];
    #pragma unroll
    for (int p = 0; p < 3; p++)
        bias[p] = make_float2(bhh[p * 64 + lane], bhh[p * 64 + lane + 32]);
    int tile = blockIdx.x * 8 + (tid >> 5);
    if (tile >= NN / 4) return;
    int n0 = tile * 4;
    float xa[4] = {0.f, 0.f, 0.f, 0.f};
    float xb[4] = {0.f, 0.f, 0.f, 0.f};
    for (int t = 0; t < TT; t++) {
        float2 acc[4][3];
        #pragma unroll
        for (int r = 0; r < 4; r++)
            #pragma unroll
            for (int p = 0; p < 3; p++) acc[r][p] = bias[p];
        if (t) {
            #pragma unroll 8
            for (int h = 0; h < 32; h++) {
                float2 w0 = Wsm[h * 96 + lane], w1 = Wsm[h * 96 + 32 + lane], w2 = Wsm[h * 96 + 64 + lane];
                #pragma unroll
                for (int r = 0; r < 4; r++) {
                    float xv = __shfl_sync(0xffffffffu, xa[r], h);
                    float2 xv2 = make_float2(xv, xv);
                    acc[r][0] = ffma2(xv2, w0, acc[r][0]);
                    acc[r][1] = ffma2(xv2, w1, acc[r][1]);
                    acc[r][2] = ffma2(xv2, w2, acc[r][2]);
                }
            }
            #pragma unroll 8
            for (int h = 0; h < 32; h++) {
                float2 w0 = Wsm[(h + 32) * 96 + lane], w1 = Wsm[(h + 32) * 96 + 32 + lane], w2 = Wsm[(h + 32) * 96 + 64 + lane];
                #pragma unroll
                for (int r = 0; r < 4; r++) {
                    float xv = __shfl_sync(0xffffffffu, xb[r], h);
                    float2 xv2 = make_float2(xv, xv);
                    acc[r][0] = ffma2(xv2, w0, acc[r][0]);
                    acc[r][1] = ffma2(xv2, w1, acc[r][1]);
                    acc[r][2] = ffma2(xv2, w2, acc[r][2]);
                }
            }
        }
        const __half* gi_base = GIH + (size_t)t * NN * 192;
        #pragma unroll
        for (int r = 0; r < 4; r++) {
            const __half* gir = gi_base + (size_t)(n0 + r) * 192;
            float2 i_r = make_float2(__half2float(gir[lane]), __half2float(gir[32 + lane]));
            float2 i_z = make_float2(__half2float(gir[64 + lane]), __half2float(gir[96 + lane]));
            float2 i_n = make_float2(__half2float(gir[128 + lane]), __half2float(gir[160 + lane]));
            float2 rg, zg, ng;
            rg.x = sigf(i_r.x + acc[r][0].x); rg.y = sigf(i_r.y + acc[r][0].y);
            zg.x = sigf(i_z.x + acc[r][1].x); zg.y = sigf(i_z.y + acc[r][1].y);
            ng.x = tanhf(i_n.x + rg.x * acc[r][2].x);
            ng.y = tanhf(i_n.y + rg.y * acc[r][2].y);
            xa[r] = (1.f - zg.x) * ng.x + zg.x * xa[r];
            xb[r] = (1.f - zg.y) * ng.y + zg.y * xb[r];
        }
    }
    #pragma unroll
    for (int r = 0; r < 4; r++) {
        H0P[(size_t)(n0 + r) * 64 + lane] = xa[r];
        H0P[(size_t)(n0 + r) * 64 + 32 + lane] = xb[r];
    }
}

// ---------------- classifier head + state cleanup ---------------------------
__global__ __launch_bounds__(256) void k_cls(const float* __restrict__ Wc1,
                                             const float* __restrict__ bc1,
                                             const float* __restrict__ Wc2,
                                             const float* __restrict__ bc2,
                                             float* __restrict__ out) {
    int gid = blockIdx.x * blockDim.x + threadIdx.x;
    if (gid < NN) { g_degi[gid] = 0; g_cursor[gid] = 0; }

    __shared__ float W1s[64 * 32];
    __shared__ float w2s[32], b1s[32];
    int tid = threadIdx.x;
    for (int i = tid; i < 2048; i += 256) W1s[i] = Wc1[i];
    if (tid < 32) { w2s[tid] = Wc2[tid]; b1s[tid] = bc1[tid]; }
    __syncthreads();
    int lane = tid & 31;
    int n = blockIdx.x * 8 + (tid >> 5);
    if (n >= NN) return;
    float h0 = H0P[(size_t)n * 64 + lane];
    float h1 = H0P[(size_t)n * 64 + 32 + lane];
    float acc = b1s[lane];
    #pragma unroll
    for (int h = 0; h < 32; h++) {
        float xv = __shfl_sync(0xffffffffu, h0, h);
        acc = fmaf(xv, W1s[h * 32 + lane], acc);
    }
    #pragma unroll
    for (int h = 0; h < 32; h++) {
        float xv = __shfl_sync(0xffffffffu, h1, h);
        acc = fmaf(xv, W1s[(h + 32) * 32 + lane], acc);
    }
    acc = fmaxf(acc, 0.f);
    float p = acc * w2s[lane];
    #pragma unroll
    for (int off = 16; off; off >>= 1) p += __shfl_xor_sync(0xffffffffu, p, off);
    if (lane == 0) out[n] = p + bc2[0];
}

// ---------------- launch ----------------------------------------------------
extern "C" void kernel_launch(void* const* d_in, const int* in_sizes, int n_in,
                              void* d_out, int out_size) {
    const float* x   = (const float*)d_in[0];
    const int*   ei  = (const int*)d_in[1];
    const float* W1  = (const float*)d_in[2];
    const float* b1  = (const float*)d_in[3];
    const float* W2  = (const float*)d_in[4];
    const float* b2  = (const float*)d_in[5];
    const float* Wih = (const float*)d_in[6];
    const float* Whh = (const float*)d_in[7];
    const float* bih = (const float*)d_in[8];
    const float* bhh = (const float*)d_in[9];
    const float* Wc1 = (const float*)d_in[10];
    const float* bc1 = (const float*)d_in[11];
    const float* Wc2 = (const float*)d_in[12];
    const float* bc2 = (const float*)d_in[13];
    float* out = (float*)d_out;

    int E = in_sizes[1] / 2;
    const int* src = ei;
    const int* dst = ei + E;

    // graph preprocessing
    k_count<<<(E + 255) / 256, 256>>>(dst, E);
    k_scan_norm<<<1, 1024>>>();
    k_fill<<<(E + 255) / 256, 256>>>(src, dst, E);

    // layer 1: P1 = Ahat * x (3 t-chunks) -> BUFA(32); h1 = relu(P1@W1+b1) -> fp16
    k_agg32<<<dim3(NN / 8, 3), 256>>>(x);
    k_gemm1<<<1184, 256>>>(W1, b1);

    // layer 2: P2 = Ahat * h1 (3 t-chunks) -> fp16 P2H
    k_agg64<<<dim3(NN / 8, 3), 256>>>();

    // HMMA fused: h2 = relu(P2 @ W2 + b2); gi = h2 @ W_ih^T + b_ih -> fp16 GIH
    k_h2gi_mma<<<(ROWS / 16 + 7) / 8, 256>>>(W2, b2, Wih, bih);

    // fused GRU: all 12 steps in one kernel, h in registers
    k_gru_all<<<(NN / 4 + 7) / 8, 256>>>(Whh, bhh);

    // classifier head (+ zero degi/cursor for next call)
    k_cls<<<(NN + 7) / 8, 256>>>(Wc1, bc1, Wc2, bc2, out);
}

// round 7
// speedup vs baseline: 2.4642x; 1.1869x over previous
#include <cuda_runtime.h>
#include <cuda_fp16.h>
#include <math.h>

// Problem constants
constexpr int TT = 12;
constexpr int NN = 50000;
constexpr int FF = 32;
constexpr int HH = 64;
constexpr int EE = 1600000;
constexpr int ROWS = TT * NN;     // 600000

// ---------------- static device scratch (zero-initialized at load) ---------
__device__ int     g_degi[NN];
__device__ int     g_cursor[NN];
__device__ float   g_dinv[NN];
__device__ float   g_invdeg[NN];
__device__ int     g_rowptr[NN + 1];
__device__ int2    g_epk[EE];                              // packed (src, w)
__device__ float4  g_bufA4[(size_t)ROWS * FF / 4];         // 76.8 MB fp32 (P1)
__device__ uint4   g_h1u4[(size_t)ROWS * HH / 8];          // 76.8 MB h1 fp16
__device__ uint4   g_p2u4[(size_t)ROWS * HH / 8];          // 76.8 MB P2 fp16
__device__ __half2 g_gih2[(size_t)ROWS * 3 * HH / 2];      // 230.4 MB gi fp16
__device__ float4  g_h0_4[(size_t)NN * HH / 4];

#define BUFA ((float*)g_bufA4)
#define H1H  ((__half*)g_h1u4)
#define P2H  ((__half*)g_p2u4)
#define GIH  ((__half*)g_gih2)
#define H0P  ((float*)g_h0_4)

// ---------------- helpers ---------------------------------------------------
union F2U { float2 f; unsigned long long u; };
__device__ __forceinline__ float2 ffma2(float2 a, float2 b, float2 c) {
    F2U A, B, C, D; A.f = a; B.f = b; C.f = c;
    asm("fma.rn.f32x2 %0, %1, %2, %3;" : "=l"(D.u) : "l"(A.u), "l"(B.u), "l"(C.u));
    return D.f;
}
__device__ __forceinline__ float2 h2f2(unsigned int u) {
    __half2 h = *reinterpret_cast<const __half2*>(&u);
    return __half22float2(h);
}
__device__ __forceinline__ unsigned int pack2h(float a, float b) {
    __half2 h = __floats2half2_rn(a, b);
    return *reinterpret_cast<unsigned int*>(&h);
}
__device__ __forceinline__ float sigf(float x) { return 1.f / (1.f + expf(-x)); }

// m16n8k16 fp16 MMA, fp32 accumulate (A row-major, B col-major)
__device__ __forceinline__ void mma16816(float* c, const unsigned int* a, const unsigned int* b) {
    asm volatile(
        "mma.sync.aligned.m16n8k16.row.col.f32.f16.f16.f32 "
        "{%0,%1,%2,%3}, {%4,%5,%6,%7}, {%8,%9}, {%0,%1,%2,%3};\n"
        : "+f"(c[0]), "+f"(c[1]), "+f"(c[2]), "+f"(c[3])
        : "r"(a[0]), "r"(a[1]), "r"(a[2]), "r"(a[3]), "r"(b[0]), "r"(b[1]));
}

// ---------------- preprocessing --------------------------------------------
__global__ void k_count(const int* __restrict__ dst, int E) {
    int e = blockIdx.x * blockDim.x + threadIdx.x;
    if (e < E) atomicAdd(&g_degi[dst[e]], 1);
}

__global__ void k_scan_norm() {
    __shared__ int wsum[32];
    __shared__ int s_base;
    int t = threadIdx.x, lane = t & 31, wid = t >> 5;
    if (t == 0) s_base = 0;
    __syncthreads();
    for (int base = 0; base < NN; base += 1024) {
        int idx = base + t;
        int v = (idx < NN) ? g_degi[idx] : 0;
        int x = v;
        #pragma unroll
        for (int o = 1; o < 32; o <<= 1) {
            int y = __shfl_up_sync(0xffffffffu, x, o);
            if (lane >= o) x += y;
        }
        if (lane == 31) wsum[wid] = x;
        __syncthreads();
        if (wid == 0) {
            int w = wsum[lane];
            int xw = w;
            #pragma unroll
            for (int o = 1; o < 32; o <<= 1) {
                int y = __shfl_up_sync(0xffffffffu, xw, o);
                if (lane >= o) xw += y;
            }
            wsum[lane] = xw - w;
        }
        __syncthreads();
        int excl = s_base + wsum[wid] + x - v;
        if (idx < NN) {
            g_rowptr[idx] = excl;
            float deg = (float)v + 1.0f;
            g_dinv[idx] = rsqrtf(deg);
            g_invdeg[idx] = 1.0f / deg;
        }
        __syncthreads();
        if (t == 1023) s_base = excl + v;
        __syncthreads();
    }
    if (t == 0) g_rowptr[NN] = s_base;
}

__global__ void k_fill(const int* __restrict__ src, const int* __restrict__ dst, int E) {
    int e = blockIdx.x * blockDim.x + threadIdx.x;
    if (e < E) {
        int s = src[e], d = dst[e];
        float w = g_dinv[s] * g_dinv[d];
        int pos = g_rowptr[d] + atomicAdd(&g_cursor[d], 1);
        g_epk[pos] = make_int2(s, __float_as_int(w));
    }
}

// ---------------- aggregation layer 1: 4 t per launch slice -----------------
__global__ __launch_bounds__(256) void k_agg32(const float* __restrict__ x) {
    int lane = threadIdx.x & 31;
    int n = blockIdx.x * 8 + (threadIdx.x >> 5);
    if (n >= NN) return;
    int c = blockIdx.y;                                  // 0..2
    int g = lane >> 3, sub = lane & 7;
    const float4* __restrict__ x4 = (const float4*)x + (size_t)(c * 4) * NN * 8 + sub;
    int r0 = g_rowptr[n], r1 = g_rowptr[n + 1];
    float2 acc[4][2];
    #pragma unroll
    for (int t = 0; t < 4; t++) { acc[t][0] = make_float2(0.f, 0.f); acc[t][1] = make_float2(0.f, 0.f); }
    int2 ep = (r0 + lane < r1) ? g_epk[r0 + lane] : make_int2(0, 0);
    for (int tile = r0; tile < r1; tile += 32) {
        int2 epc = ep;
        int nxt = tile + 32;
        if (nxt < r1) ep = (nxt + lane < r1) ? g_epk[nxt + lane] : make_int2(0, 0);
        int nb = r1 - tile; if (nb > 32) nb = 32;
        for (int b = 0; b * 4 < nb; b++) {
            int ss = __shfl_sync(0xffffffffu, epc.x, b * 4 + g);
            float ww = __int_as_float(__shfl_sync(0xffffffffu, epc.y, b * 4 + g));
            float2 w2 = make_float2(ww, ww);
            const float4* p = x4 + (size_t)ss * 8;
            #pragma unroll
            for (int t = 0; t < 4; t++) {
                float4 v = p[(size_t)t * (NN * 8)];
                acc[t][0] = ffma2(w2, make_float2(v.x, v.y), acc[t][0]);
                acc[t][1] = ffma2(w2, make_float2(v.z, v.w), acc[t][1]);
            }
        }
    }
    if (g == 0) {
        float id = g_invdeg[n];
        float2 w2 = make_float2(id, id);
        const float4* p = x4 + (size_t)n * 8;
        #pragma unroll
        for (int t = 0; t < 4; t++) {
            float4 v = p[(size_t)t * (NN * 8)];
            acc[t][0] = ffma2(w2, make_float2(v.x, v.y), acc[t][0]);
            acc[t][1] = ffma2(w2, make_float2(v.z, v.w), acc[t][1]);
        }
    }
    float4* o4 = (float4*)BUFA + (size_t)(c * 4) * NN * 8;
    #pragma unroll
    for (int t = 0; t < 4; t++) {
        float2 a0 = acc[t][0], a1 = acc[t][1];
        #pragma unroll
        for (int off = 8; off <= 16; off <<= 1) {
            a0.x += __shfl_xor_sync(0xffffffffu, a0.x, off);
            a0.y += __shfl_xor_sync(0xffffffffu, a0.y, off);
            a1.x += __shfl_xor_sync(0xffffffffu, a1.x, off);
            a1.y += __shfl_xor_sync(0xffffffffu, a1.y, off);
        }
        if (g == t)
            o4[(size_t)t * (NN * 8) + (size_t)n * 8 + sub] = make_float4(a0.x, a0.y, a1.x, a1.y);
    }
}

// ---------------- aggregation layer 2: fp16 in/out, 4 t per slice -----------
__global__ __launch_bounds__(256) void k_agg64() {
    int lane = threadIdx.x & 31;
    int n = blockIdx.x * 8 + (threadIdx.x >> 5);
    if (n >= NN) return;
    int c = blockIdx.y;                                  // 0..2
    int g = lane >> 3, sub = lane & 7;
    int r0 = g_rowptr[n], r1 = g_rowptr[n + 1];
    const uint4* __restrict__ hb = g_h1u4 + (size_t)(c * 4) * NN * 8 + sub;
    float2 acc[4][4];
    #pragma unroll
    for (int t = 0; t < 4; t++)
        #pragma unroll
        for (int j = 0; j < 4; j++) acc[t][j] = make_float2(0.f, 0.f);
    int2 ep = (r0 + lane < r1) ? g_epk[r0 + lane] : make_int2(0, 0);
    for (int tile = r0; tile < r1; tile += 32) {
        int2 epc = ep;
        int nxt = tile + 32;
        if (nxt < r1) ep = (nxt + lane < r1) ? g_epk[nxt + lane] : make_int2(0, 0);
        int nb = r1 - tile; if (nb > 32) nb = 32;
        for (int b = 0; b * 4 < nb; b++) {
            int ss = __shfl_sync(0xffffffffu, epc.x, b * 4 + g);
            float ww = __int_as_float(__shfl_sync(0xffffffffu, epc.y, b * 4 + g));
            float2 w2 = make_float2(ww, ww);
            const uint4* p = hb + (size_t)ss * 8;
            #pragma unroll
            for (int t = 0; t < 4; t++) {
                uint4 hv = p[(size_t)t * (NN * 8)];
                acc[t][0] = ffma2(w2, h2f2(hv.x), acc[t][0]);
                acc[t][1] = ffma2(w2, h2f2(hv.y), acc[t][1]);
                acc[t][2] = ffma2(w2, h2f2(hv.z), acc[t][2]);
                acc[t][3] = ffma2(w2, h2f2(hv.w), acc[t][3]);
            }
        }
    }
    if (g == 0) {
        float id = g_invdeg[n];
        float2 w2 = make_float2(id, id);
        const uint4* p = hb + (size_t)n * 8;
        #pragma unroll
        for (int t = 0; t < 4; t++) {
            uint4 hv = p[(size_t)t * (NN * 8)];
            acc[t][0] = ffma2(w2, h2f2(hv.x), acc[t][0]);
            acc[t][1] = ffma2(w2, h2f2(hv.y), acc[t][1]);
            acc[t][2] = ffma2(w2, h2f2(hv.z), acc[t][2]);
            acc[t][3] = ffma2(w2, h2f2(hv.w), acc[t][3]);
        }
    }
    #pragma unroll
    for (int t = 0; t < 4; t++) {
        #pragma unroll
        for (int j = 0; j < 4; j++) {
            float2 a = acc[t][j];
            #pragma unroll
            for (int off = 8; off <= 16; off <<= 1) {
                a.x += __shfl_xor_sync(0xffffffffu, a.x, off);
                a.y += __shfl_xor_sync(0xffffffffu, a.y, off);
            }
            acc[t][j] = a;
        }
        if (g == t) {
            uint4 pk;
            pk.x = pack2h(acc[t][0].x, acc[t][0].y);
            pk.y = pack2h(acc[t][1].x, acc[t][1].y);
            pk.z = pack2h(acc[t][2].x, acc[t][2].y);
            pk.w = pack2h(acc[t][3].x, acc[t][3].y);
            g_p2u4[((size_t)(c * 4 + t) * NN + n) * 8 + sub] = pk;
        }
    }
}

// ---------------- dense layer 1: h1 = relu(BUFA(32) @ W1 + b1) -> fp16 ------
__global__ __launch_bounds__(256) void k_gemm1(const float* __restrict__ W,
                                               const float* __restrict__ b) {
    __shared__ float2 Wsm[32 * 32];
    int tid = threadIdx.x;
    for (int i = tid; i < 32 * 32; i += 256) {
        int f = i >> 5, p = i & 31;
        Wsm[i] = make_float2(W[f * 64 + p], W[f * 64 + p + 32]);
    }
    __syncthreads();
    int lane = tid & 31;
    float2 bias = make_float2(b[lane], b[lane + 32]);
    for (int tile = blockIdx.x * 8 + (tid >> 5); tile < ROWS / 8; tile += gridDim.x * 8) {
        int row0 = tile * 8;
        float xv[8];
        #pragma unroll
        for (int r = 0; r < 8; r++) xv[r] = BUFA[(size_t)(row0 + r) * FF + lane];
        float2 acc[8];
        #pragma unroll
        for (int r = 0; r < 8; r++) acc[r] = bias;
        #pragma unroll 8
        for (int f = 0; f < 32; f++) {
            float2 w = Wsm[f * 32 + lane];
            #pragma unroll
            for (int r = 0; r < 8; r++) {
                float s = __shfl_sync(0xffffffffu, xv[r], f);
                acc[r] = ffma2(make_float2(s, s), w, acc[r]);
            }
        }
        #pragma unroll
        for (int r = 0; r < 8; r++) {
            __half* o = H1H + (size_t)(row0 + r) * 64;
            o[lane] = __float2half_rn(fmaxf(acc[r].x, 0.f));
            o[lane + 32] = __float2half_rn(fmaxf(acc[r].y, 0.f));
        }
    }
}

// ---------------- fused HMMA: h2 = relu(P2@W2+b2); gi = h2@Wih^T+bih --------
__global__ __launch_bounds__(256) void k_h2gi_mma(const float* __restrict__ W2,
                                                  const float* __restrict__ b2,
                                                  const float* __restrict__ Wih,
                                                  const float* __restrict__ bih) {
    __shared__ unsigned int W2f[4 * 8 * 32 * 2];    //  8 KB
    __shared__ unsigned int Wihf[4 * 24 * 32 * 2];  // 24 KB
    __shared__ float2 B2f[8 * 32];                  //  2 KB
    __shared__ float2 Bihf[24 * 32];                //  6 KB
    int tid = threadIdx.x;
    for (int i = tid; i < 4 * 8 * 32; i += 256) {
        int lane = i & 31, nt = (i >> 5) & 7, kt = i >> 8;
        int gq = lane >> 2, tq = lane & 3;
        int n = nt * 8 + gq, ks = kt * 16 + tq * 2;
        W2f[i * 2 + 0] = pack2h(W2[ks * 64 + n], W2[(ks + 1) * 64 + n]);
        W2f[i * 2 + 1] = pack2h(W2[(ks + 8) * 64 + n], W2[(ks + 9) * 64 + n]);
    }
    for (int i = tid; i < 4 * 24 * 32; i += 256) {
        int lane = i & 31, nt = (i >> 5) % 24, kt = i / (24 * 32);
        int gq = lane >> 2, tq = lane & 3;
        int gcol = nt * 8 + gq, ks = kt * 16 + tq * 2;
        Wihf[i * 2 + 0] = pack2h(Wih[gcol * 64 + ks], Wih[gcol * 64 + ks + 1]);
        Wihf[i * 2 + 1] = pack2h(Wih[gcol * 64 + ks + 8], Wih[gcol * 64 + ks + 9]);
    }
    for (int i = tid; i < 8 * 32; i += 256) {
        int lane = i & 31, nt = i >> 5, tq = lane & 3;
        B2f[i] = make_float2(b2[nt * 8 + tq * 2], b2[nt * 8 + tq * 2 + 1]);
    }
    for (int i = tid; i < 24 * 32; i += 256) {
        int lane = i & 31, nt = i >> 5, tq = lane & 3;
        Bihf[i] = make_float2(bih[nt * 8 + tq * 2], bih[nt * 8 + tq * 2 + 1]);
    }
    __syncthreads();

    int lane = tid & 31;
    int tile = blockIdx.x * 8 + (tid >> 5);
    if (tile >= ROWS / 16) return;
    int row0 = tile * 16;
    int gq = lane >> 2, tq = lane & 3;

    unsigned int A[4][4];
    const unsigned int* base0 = (const unsigned int*)(P2H + (size_t)(row0 + gq) * 64);
    const unsigned int* base8 = (const unsigned int*)(P2H + (size_t)(row0 + gq + 8) * 64);
    #pragma unroll
    for (int kt = 0; kt < 4; kt++) {
        A[kt][0] = base0[kt * 8 + tq];
        A[kt][1] = base8[kt * 8 + tq];
        A[kt][2] = base0[kt * 8 + tq + 4];
        A[kt][3] = base8[kt * 8 + tq + 4];
    }

    float c[8][4];
    #pragma unroll
    for (int nt = 0; nt < 8; nt++) {
        float2 bb = B2f[nt * 32 + lane];
        c[nt][0] = bb.x; c[nt][1] = bb.y; c[nt][2] = bb.x; c[nt][3] = bb.y;
    }
    #pragma unroll
    for (int kt = 0; kt < 4; kt++)
        #pragma unroll
        for (int nt = 0; nt < 8; nt++)
            mma16816(c[nt], A[kt], &W2f[((kt * 8 + nt) * 32 + lane) * 2]);
    #pragma unroll
    for (int nt = 0; nt < 8; nt++)
        #pragma unroll
        for (int j = 0; j < 4; j++) c[nt][j] = fmaxf(c[nt][j], 0.f);

    unsigned int A2[4][4];
    #pragma unroll
    for (int kt = 0; kt < 4; kt++) {
        A2[kt][0] = pack2h(c[2 * kt][0], c[2 * kt][1]);
        A2[kt][1] = pack2h(c[2 * kt][2], c[2 * kt][3]);
        A2[kt][2] = pack2h(c[2 * kt + 1][0], c[2 * kt + 1][1]);
        A2[kt][3] = pack2h(c[2 * kt + 1][2], c[2 * kt + 1][3]);
    }

    unsigned int* gi0 = (unsigned int*)(GIH + (size_t)(row0 + gq) * 192);
    unsigned int* gi8 = (unsigned int*)(GIH + (size_t)(row0 + gq + 8) * 192);
    #pragma unroll
    for (int nt = 0; nt < 24; nt++) {
        float2 bb = Bihf[nt * 32 + lane];
        float d[4] = {bb.x, bb.y, bb.x, bb.y};
        #pragma unroll
        for (int kt = 0; kt < 4; kt++)
            mma16816(d, A2[kt], &Wihf[((kt * 24 + nt) * 32 + lane) * 2]);
        gi0[nt * 4 + tq] = pack2h(d[0], d[1]);
        gi8[nt * 4 + tq] = pack2h(d[2], d[3]);
    }
}

// ---------------- HMMA GRU: 12 steps, h fp32 in C-frag registers ------------
// warp = 16 nodes. gh = h @ Whh^T via m16n8k16 (h packed to fp16 per step);
// gi read in the exact fragment order k_h2gi_mma wrote it.
__global__ __launch_bounds__(256) void k_gru_mma(const float* __restrict__ Whh,
                                                 const float* __restrict__ bhh) {
    __shared__ unsigned int Wf[4 * 24 * 32 * 2];    // 24 KB B-frag table
    __shared__ float2 Bf[24 * 32];                  //  6 KB bias frags
    int tid = threadIdx.x;
    for (int i = tid; i < 4 * 24 * 32; i += 256) {
        int lane = i & 31, nt = (i >> 5) % 24, kt = i / (24 * 32);
        int gq = lane >> 2, tq = lane & 3;
        int gcol = nt * 8 + gq, ks = kt * 16 + tq * 2;
        Wf[i * 2 + 0] = pack2h(Whh[gcol * 64 + ks], Whh[gcol * 64 + ks + 1]);
        Wf[i * 2 + 1] = pack2h(Whh[gcol * 64 + ks + 8], Whh[gcol * 64 + ks + 9]);
    }
    for (int i = tid; i < 24 * 32; i += 256) {
        int lane = i & 31, nt = i >> 5, tq = lane & 3;
        Bf[i] = make_float2(bhh[nt * 8 + tq * 2], bhh[nt * 8 + tq * 2 + 1]);
    }
    __syncthreads();

    int lane = tid & 31;
    int tile = blockIdx.x * 8 + (tid >> 5);
    if (tile >= NN / 16) return;
    int row0 = tile * 16;
    int gq = lane >> 2, tq = lane & 3;

    float hc[8][4];                                  // h state, fp32 C-frags
    #pragma unroll
    for (int nt = 0; nt < 8; nt++)
        #pragma unroll
        for (int j = 0; j < 4; j++) hc[nt][j] = 0.f;

    const unsigned int* giu = (const unsigned int*)GIH;
    size_t base0 = (size_t)(row0 + gq) * 96;
    size_t base8 = (size_t)(row0 + gq + 8) * 96;

    for (int t = 0; t < TT; t++) {
        size_t toff = (size_t)t * NN * 96;
        // d = bhh (+ h @ Whh^T if t>0), 24 ntiles (r: 0-7, z: 8-15, n: 16-23)
        float d[24][4];
        #pragma unroll
        for (int nt = 0; nt < 24; nt++) {
            float2 bb = Bf[nt * 32 + lane];
            d[nt][0] = bb.x; d[nt][1] = bb.y; d[nt][2] = bb.x; d[nt][3] = bb.y;
        }
        if (t) {
            unsigned int A[4][4];
            #pragma unroll
            for (int kt = 0; kt < 4; kt++) {
                A[kt][0] = pack2h(hc[2 * kt][0], hc[2 * kt][1]);
                A[kt][1] = pack2h(hc[2 * kt][2], hc[2 * kt][3]);
                A[kt][2] = pack2h(hc[2 * kt + 1][0], hc[2 * kt + 1][1]);
                A[kt][3] = pack2h(hc[2 * kt + 1][2], hc[2 * kt + 1][3]);
            }
            #pragma unroll
            for (int kt = 0; kt < 4; kt++)
                #pragma unroll
                for (int nt = 0; nt < 24; nt++)
                    mma16816(d[nt], A[kt], &Wf[((kt * 24 + nt) * 32 + lane) * 2]);
        }
        // gates + state update, fragment-wise
        #pragma unroll
        for (int nt = 0; nt < 8; nt++) {
            float2 ir0 = h2f2(giu[toff + base0 + nt * 4 + tq]);
            float2 ir8 = h2f2(giu[toff + base8 + nt * 4 + tq]);
            float2 iz0 = h2f2(giu[toff + base0 + (nt + 8) * 4 + tq]);
            float2 iz8 = h2f2(giu[toff + base8 + (nt + 8) * 4 + tq]);
            float2 in0 = h2f2(giu[toff + base0 + (nt + 16) * 4 + tq]);
            float2 in8 = h2f2(giu[toff + base8 + (nt + 16) * 4 + tq]);
            float r0x = sigf(ir0.x + d[nt][0]), r0y = sigf(ir0.y + d[nt][1]);
            float r8x = sigf(ir8.x + d[nt][2]), r8y = sigf(ir8.y + d[nt][3]);
            float z0x = sigf(iz0.x + d[nt + 8][0]), z0y = sigf(iz0.y + d[nt + 8][1]);
            float z8x = sigf(iz8.x + d[nt + 8][2]), z8y = sigf(iz8.y + d[nt + 8][3]);
            float n0x = tanhf(in0.x + r0x * d[nt + 16][0]);
            float n0y = tanhf(in0.y + r0y * d[nt + 16][1]);
            float n8x = tanhf(in8.x + r8x * d[nt + 16][2]);
            float n8y = tanhf(in8.y + r8y * d[nt + 16][3]);
            hc[nt][0] = (1.f - z0x) * n0x + z0x * hc[nt][0];
            hc[nt][1] = (1.f - z0y) * n0y + z0y * hc[nt][1];
            hc[nt][2] = (1.f - z8x) * n8x + z8x * hc[nt][2];
            hc[nt][3] = (1.f - z8y) * n8y + z8y * hc[nt][3];
        }
    }
    // write h_last (fp32)
    float2* o0 = (float2*)(H0P + (size_t)(row0 + gq) * 64);
    float2* o8 = (float2*)(H0P + (size_t)(row0 + gq + 8) * 64);
    #pragma unroll
    for (int nt = 0; nt < 8; nt++) {
        o0[nt * 4 + tq] = make_float2(hc[nt][0], hc[nt][1]);
        o8[nt * 4 + tq] = make_float2(hc[nt][2], hc[nt][3]);
    }
}

// ---------------- classifier head + state cleanup ---------------------------
__global__ __launch_bounds__(256) void k_cls(const float* __restrict__ Wc1,
                                             const float* __restrict__ bc1,
                                             const float* __restrict__ Wc2,
                                             const float* __restrict__ bc2,
                                             float* __restrict__ out) {
    int gid = blockIdx.x * blockDim.x + threadIdx.x;
    if (gid < NN) { g_degi[gid] = 0; g_cursor[gid] = 0; }

    __shared__ float W1s[64 * 32];
    __shared__ float w2s[32], b1s[32];
    int tid = threadIdx.x;
    for (int i = tid; i < 2048; i += 256) W1s[i] = Wc1[i];
    if (tid < 32) { w2s[tid] = Wc2[tid]; b1s[tid] = bc1[tid]; }
    __syncthreads();
    int lane = tid & 31;
    int n = blockIdx.x * 8 + (tid >> 5);
    if (n >= NN) return;
    float h0 = H0P[(size_t)n * 64 + lane];
    float h1 = H0P[(size_t)n * 64 + 32 + lane];
    float acc = b1s[lane];
    #pragma unroll
    for (int h = 0; h < 32; h++) {
        float xv = __shfl_sync(0xffffffffu, h0, h);
        acc = fmaf(xv, W1s[h * 32 + lane], acc);
    }
    #pragma unroll
    for (int h = 0; h < 32; h++) {
        float xv = __shfl_sync(0xffffffffu, h1, h);
        acc = fmaf(xv, W1s[(h + 32) * 32 + lane], acc);
    }
    acc = fmaxf(acc, 0.f);
    float p = acc * w2s[lane];
    #pragma unroll
    for (int off = 16; off; off >>= 1) p += __shfl_xor_sync(0xffffffffu, p, off);
    if (lane == 0) out[n] = p + bc2[0];
}

// ---------------- launch ----------------------------------------------------
extern "C" void kernel_launch(void* const* d_in, const int* in_sizes, int n_in,
                              void* d_out, int out_size) {
    const float* x   = (const float*)d_in[0];
    const int*   ei  = (const int*)d_in[1];
    const float* W1  = (const float*)d_in[2];
    const float* b1  = (const float*)d_in[3];
    const float* W2  = (const float*)d_in[4];
    const float* b2  = (const float*)d_in[5];
    const float* Wih = (const float*)d_in[6];
    const float* Whh = (const float*)d_in[7];
    const float* bih = (const float*)d_in[8];
    const float* bhh = (const float*)d_in[9];
    const float* Wc1 = (const float*)d_in[10];
    const float* bc1 = (const float*)d_in[11];
    const float* Wc2 = (const float*)d_in[12];
    const float* bc2 = (const float*)d_in[13];
    float* out = (float*)d_out;

    int E = in_sizes[1] / 2;
    const int* src = ei;
    const int* dst = ei + E;

    // graph preprocessing
    k_count<<<(E + 255) / 256, 256>>>(dst, E);
    k_scan_norm<<<1, 1024>>>();
    k_fill<<<(E + 255) / 256, 256>>>(src, dst, E);

    // layer 1: P1 = Ahat * x (3 t-chunks) -> BUFA(32); h1 = relu(P1@W1+b1) -> fp16
    k_agg32<<<dim3(NN / 8, 3), 256>>>(x);
    k_gemm1<<<1184, 256>>>(W1, b1);

    // layer 2: P2 = Ahat * h1 (3 t-chunks) -> fp16 P2H
    k_agg64<<<dim3(NN / 8, 3), 256>>>();

    // HMMA fused: h2 = relu(P2 @ W2 + b2); gi = h2 @ W_ih^T + b_ih -> fp16 GIH
    k_h2gi_mma<<<(ROWS / 16 + 7) / 8, 256>>>(W2, b2, Wih, bih);

    // HMMA GRU: all 12 steps, h in C-frag registers
    k_gru_mma<<<(NN / 16 + 7) / 8, 256>>>(Whh, bhh);

    // classifier head (+ zero degi/cursor for next call)
    k_cls<<<(NN + 7) / 8, 256>>>(Wc1, bc1, Wc2, bc2, out);
}

// round 8
// speedup vs baseline: 2.7462x; 1.1145x over previous
#include <cuda_runtime.h>
#include <cuda_fp16.h>
#include <math.h>

// Problem constants
constexpr int TT = 12;
constexpr int NN = 50000;
constexpr int FF = 32;
constexpr int HH = 64;
constexpr int EE = 1600000;
constexpr int ROWS = TT * NN;     // 600000

// ---------------- static device scratch (zero-initialized at load) ---------
__device__ int     g_degi[NN];
__device__ int     g_cursor[NN];
__device__ float   g_dinv[NN];
__device__ float   g_invdeg[NN];
__device__ int     g_rowptr[NN + 1];
__device__ int2    g_epk[EE];                              // packed (src, w)
__device__ uint4   g_xhu4[(size_t)ROWS * FF / 8];          // 38.4 MB x fp16
__device__ float4  g_bufA4[(size_t)ROWS * FF / 4];         // 76.8 MB fp32 (P1)
__device__ uint4   g_h1u4[(size_t)ROWS * HH / 8];          // 76.8 MB h1 fp16
__device__ uint4   g_p2u4[(size_t)ROWS * HH / 8];          // 76.8 MB P2 fp16
__device__ float4  g_h0_4[(size_t)NN * HH / 4];

#define BUFA ((float*)g_bufA4)
#define H1H  ((__half*)g_h1u4)
#define P2H  ((__half*)g_p2u4)
#define H0P  ((float*)g_h0_4)

// ---------------- helpers ---------------------------------------------------
union F2U { float2 f; unsigned long long u; };
__device__ __forceinline__ float2 ffma2(float2 a, float2 b, float2 c) {
    F2U A, B, C, D; A.f = a; B.f = b; C.f = c;
    asm("fma.rn.f32x2 %0, %1, %2, %3;" : "=l"(D.u) : "l"(A.u), "l"(B.u), "l"(C.u));
    return D.f;
}
__device__ __forceinline__ float2 h2f2(unsigned int u) {
    __half2 h = *reinterpret_cast<const __half2*>(&u);
    return __half22float2(h);
}
__device__ __forceinline__ unsigned int pack2h(float a, float b) {
    __half2 h = __floats2half2_rn(a, b);
    return *reinterpret_cast<unsigned int*>(&h);
}
__device__ __forceinline__ float sigf(float x) { return 1.f / (1.f + expf(-x)); }

// m16n8k16 fp16 MMA, fp32 accumulate (A row-major, B col-major)
__device__ __forceinline__ void mma16816(float* c, const unsigned int* a, const unsigned int* b) {
    asm volatile(
        "mma.sync.aligned.m16n8k16.row.col.f32.f16.f16.f32 "
        "{%0,%1,%2,%3}, {%4,%5,%6,%7}, {%8,%9}, {%0,%1,%2,%3};\n"
        : "+f"(c[0]), "+f"(c[1]), "+f"(c[2]), "+f"(c[3])
        : "r"(a[0]), "r"(a[1]), "r"(a[2]), "r"(a[3]), "r"(b[0]), "r"(b[1]));
}

// ---------------- preprocessing --------------------------------------------
__global__ void k_count(const int* __restrict__ dst, int E) {
    int e = blockIdx.x * blockDim.x + threadIdx.x;
    if (e < E) atomicAdd(&g_degi[dst[e]], 1);
}

__global__ void k_scan_norm() {
    __shared__ int wsum[32];
    __shared__ int s_base;
    int t = threadIdx.x, lane = t & 31, wid = t >> 5;
    if (t == 0) s_base = 0;
    __syncthreads();
    for (int base = 0; base < NN; base += 1024) {
        int idx = base + t;
        int v = (idx < NN) ? g_degi[idx] : 0;
        int x = v;
        #pragma unroll
        for (int o = 1; o < 32; o <<= 1) {
            int y = __shfl_up_sync(0xffffffffu, x, o);
            if (lane >= o) x += y;
        }
        if (lane == 31) wsum[wid] = x;
        __syncthreads();
        if (wid == 0) {
            int w = wsum[lane];
            int xw = w;
            #pragma unroll
            for (int o = 1; o < 32; o <<= 1) {
                int y = __shfl_up_sync(0xffffffffu, xw, o);
                if (lane >= o) xw += y;
            }
            wsum[lane] = xw - w;
        }
        __syncthreads();
        int excl = s_base + wsum[wid] + x - v;
        if (idx < NN) {
            g_rowptr[idx] = excl;
            float deg = (float)v + 1.0f;
            g_dinv[idx] = rsqrtf(deg);
            g_invdeg[idx] = 1.0f / deg;
        }
        __syncthreads();
        if (t == 1023) s_base = excl + v;
        __syncthreads();
    }
    if (t == 0) g_rowptr[NN] = s_base;
}

__global__ void k_fill(const int* __restrict__ src, const int* __restrict__ dst, int E) {
    int e = blockIdx.x * blockDim.x + threadIdx.x;
    if (e < E) {
        int s = src[e], d = dst[e];
        float w = g_dinv[s] * g_dinv[d];
        int pos = g_rowptr[d] + atomicAdd(&g_cursor[d], 1);
        g_epk[pos] = make_int2(s, __float_as_int(w));
    }
}

// ---------------- convert x to fp16 -----------------------------------------
__global__ __launch_bounds__(256) void k_cvt(const float4* __restrict__ x4) {
    unsigned int i = blockIdx.x * blockDim.x + threadIdx.x;
    if (i < (unsigned int)(ROWS * FF / 4)) {
        float4 v = x4[i];
        ((uint2*)g_xhu4)[i] = make_uint2(pack2h(v.x, v.y), pack2h(v.z, v.w));
    }
}

// ---------------- aggregation layer 1: fp16 gather, 4 t per slice -----------
// warp per node. 8 groups of 4 lanes: group owns one edge; lane's uint4 = 8
// fp16 features of the 32-feature row. 8 edges per warp-batch.
__global__ __launch_bounds__(256) void k_agg32() {
    int lane = threadIdx.x & 31;
    int n = blockIdx.x * 8 + (threadIdx.x >> 5);
    if (n >= NN) return;
    int c = blockIdx.y;                                  // 0..2
    int g = lane >> 2, sub = lane & 3;
    const uint4* __restrict__ x4 = g_xhu4 + (size_t)(c * 4) * NN * 4 + sub;
    int r0 = g_rowptr[n], r1 = g_rowptr[n + 1];
    float2 acc[4][4];
    #pragma unroll
    for (int t = 0; t < 4; t++)
        #pragma unroll
        for (int j = 0; j < 4; j++) acc[t][j] = make_float2(0.f, 0.f);
    int2 ep = (r0 + lane < r1) ? g_epk[r0 + lane] : make_int2(0, 0);
    for (int tile = r0; tile < r1; tile += 32) {
        int2 epc = ep;
        int nxt = tile + 32;
        if (nxt < r1) ep = (nxt + lane < r1) ? g_epk[nxt + lane] : make_int2(0, 0);
        int nb = r1 - tile; if (nb > 32) nb = 32;
        for (int b = 0; b * 8 < nb; b++) {
            int ss = __shfl_sync(0xffffffffu, epc.x, b * 8 + g);
            float ww = __int_as_float(__shfl_sync(0xffffffffu, epc.y, b * 8 + g));
            float2 w2 = make_float2(ww, ww);
            const uint4* p = x4 + (size_t)ss * 4;
            #pragma unroll
            for (int t = 0; t < 4; t++) {
                uint4 v = p[(size_t)t * (NN * 4)];
                acc[t][0] = ffma2(w2, h2f2(v.x), acc[t][0]);
                acc[t][1] = ffma2(w2, h2f2(v.y), acc[t][1]);
                acc[t][2] = ffma2(w2, h2f2(v.z), acc[t][2]);
                acc[t][3] = ffma2(w2, h2f2(v.w), acc[t][3]);
            }
        }
    }
    if (g == 0) {   // self-loop, added once pre-reduction
        float id = g_invdeg[n];
        float2 w2 = make_float2(id, id);
        const uint4* p = x4 + (size_t)n * 4;
        #pragma unroll
        for (int t = 0; t < 4; t++) {
            uint4 v = p[(size_t)t * (NN * 4)];
            acc[t][0] = ffma2(w2, h2f2(v.x), acc[t][0]);
            acc[t][1] = ffma2(w2, h2f2(v.y), acc[t][1]);
            acc[t][2] = ffma2(w2, h2f2(v.z), acc[t][2]);
            acc[t][3] = ffma2(w2, h2f2(v.w), acc[t][3]);
        }
    }
    float4* o4 = (float4*)BUFA + (size_t)(c * 4) * NN * 8;
    #pragma unroll
    for (int t = 0; t < 4; t++) {
        #pragma unroll
        for (int j = 0; j < 4; j++) {
            float2 a = acc[t][j];
            #pragma unroll
            for (int off = 4; off <= 16; off <<= 1) {
                a.x += __shfl_xor_sync(0xffffffffu, a.x, off);
                a.y += __shfl_xor_sync(0xffffffffu, a.y, off);
            }
            acc[t][j] = a;
        }
        if (g == t) {
            size_t base = (size_t)t * (NN * 8) + (size_t)n * 8 + sub * 2;
            o4[base]     = make_float4(acc[t][0].x, acc[t][0].y, acc[t][1].x, acc[t][1].y);
            o4[base + 1] = make_float4(acc[t][2].x, acc[t][2].y, acc[t][3].x, acc[t][3].y);
        }
    }
}

// ---------------- aggregation layer 2: fp16 in/out, 4 t per slice -----------
__global__ __launch_bounds__(256) void k_agg64() {
    int lane = threadIdx.x & 31;
    int n = blockIdx.x * 8 + (threadIdx.x >> 5);
    if (n >= NN) return;
    int c = blockIdx.y;                                  // 0..2
    int g = lane >> 3, sub = lane & 7;
    int r0 = g_rowptr[n], r1 = g_rowptr[n + 1];
    const uint4* __restrict__ hb = g_h1u4 + (size_t)(c * 4) * NN * 8 + sub;
    float2 acc[4][4];
    #pragma unroll
    for (int t = 0; t < 4; t++)
        #pragma unroll
        for (int j = 0; j < 4; j++) acc[t][j] = make_float2(0.f, 0.f);
    int2 ep = (r0 + lane < r1) ? g_epk[r0 + lane] : make_int2(0, 0);
    for (int tile = r0; tile < r1; tile += 32) {
        int2 epc = ep;
        int nxt = tile + 32;
        if (nxt < r1) ep = (nxt + lane < r1) ? g_epk[nxt + lane] : make_int2(0, 0);
        int nb = r1 - tile; if (nb > 32) nb = 32;
        for (int b = 0; b * 4 < nb; b++) {
            int ss = __shfl_sync(0xffffffffu, epc.x, b * 4 + g);
            float ww = __int_as_float(__shfl_sync(0xffffffffu, epc.y, b * 4 + g));
            float2 w2 = make_float2(ww, ww);
            const uint4* p = hb + (size_t)ss * 8;
            #pragma unroll
            for (int t = 0; t < 4; t++) {
                uint4 hv = p[(size_t)t * (NN * 8)];
                acc[t][0] = ffma2(w2, h2f2(hv.x), acc[t][0]);
                acc[t][1] = ffma2(w2, h2f2(hv.y), acc[t][1]);
                acc[t][2] = ffma2(w2, h2f2(hv.z), acc[t][2]);
                acc[t][3] = ffma2(w2, h2f2(hv.w), acc[t][3]);
            }
        }
    }
    if (g == 0) {
        float id = g_invdeg[n];
        float2 w2 = make_float2(id, id);
        const uint4* p = hb + (size_t)n * 8;
        #pragma unroll
        for (int t = 0; t < 4; t++) {
            uint4 hv = p[(size_t)t * (NN * 8)];
            acc[t][0] = ffma2(w2, h2f2(hv.x), acc[t][0]);
            acc[t][1] = ffma2(w2, h2f2(hv.y), acc[t][1]);
            acc[t][2] = ffma2(w2, h2f2(hv.z), acc[t][2]);
            acc[t][3] = ffma2(w2, h2f2(hv.w), acc[t][3]);
        }
    }
    #pragma unroll
    for (int t = 0; t < 4; t++) {
        #pragma unroll
        for (int j = 0; j < 4; j++) {
            float2 a = acc[t][j];
            #pragma unroll
            for (int off = 8; off <= 16; off <<= 1) {
                a.x += __shfl_xor_sync(0xffffffffu, a.x, off);
                a.y += __shfl_xor_sync(0xffffffffu, a.y, off);
            }
            acc[t][j] = a;
        }
        if (g == t) {
            uint4 pk;
            pk.x = pack2h(acc[t][0].x, acc[t][0].y);
            pk.y = pack2h(acc[t][1].x, acc[t][1].y);
            pk.z = pack2h(acc[t][2].x, acc[t][2].y);
            pk.w = pack2h(acc[t][3].x, acc[t][3].y);
            g_p2u4[((size_t)(c * 4 + t) * NN + n) * 8 + sub] = pk;
        }
    }
}

// ---------------- dense layer 1: h1 = relu(BUFA(32) @ W1 + b1) -> fp16 ------
__global__ __launch_bounds__(256) void k_gemm1(const float* __restrict__ W,
                                               const float* __restrict__ b) {
    __shared__ float2 Wsm[32 * 32];
    int tid = threadIdx.x;
    for (int i = tid; i < 32 * 32; i += 256) {
        int f = i >> 5, p = i & 31;
        Wsm[i] = make_float2(W[f * 64 + p], W[f * 64 + p + 32]);
    }
    __syncthreads();
    int lane = tid & 31;
    float2 bias = make_float2(b[lane], b[lane + 32]);
    for (int tile = blockIdx.x * 8 + (tid >> 5); tile < ROWS / 8; tile += gridDim.x * 8) {
        int row0 = tile * 8;
        float xv[8];
        #pragma unroll
        for (int r = 0; r < 8; r++) xv[r] = BUFA[(size_t)(row0 + r) * FF + lane];
        float2 acc[8];
        #pragma unroll
        for (int r = 0; r < 8; r++) acc[r] = bias;
        #pragma unroll 8
        for (int f = 0; f < 32; f++) {
            float2 w = Wsm[f * 32 + lane];
            #pragma unroll
            for (int r = 0; r < 8; r++) {
                float s = __shfl_sync(0xffffffffu, xv[r], f);
                acc[r] = ffma2(make_float2(s, s), w, acc[r]);
            }
        }
        #pragma unroll
        for (int r = 0; r < 8; r++) {
            __half* o = H1H + (size_t)(row0 + r) * 64;
            o[lane] = __float2half_rn(fmaxf(acc[r].x, 0.f));
            o[lane + 32] = __float2half_rn(fmaxf(acc[r].y, 0.f));
        }
    }
}

// ---------------- fused HMMA: h2+gi+GRU, no gi materialization --------------
// warp = 16 nodes. Per t: gh = h@Whh^T (t>0), h2 = relu(P2@W2+b2),
// gi = h2@Wih^T; r/z gates accumulate gi+gh in ONE fragment (bias combined),
// n gate keeps split accumulators (tanh(i_n + r*h_n) semantics).
__global__ __launch_bounds__(256) void k_fused(const float* __restrict__ W2,
                                               const float* __restrict__ b2,
                                               const float* __restrict__ Wih,
                                               const float* __restrict__ bih,
                                               const float* __restrict__ Whh,
                                               const float* __restrict__ bhh) {
    extern __shared__ unsigned int smu[];
    unsigned int* W2f  = smu;                  // 2048 u32 (8 KB)
    unsigned int* Wihf = smu + 2048;           // 6144 u32 (24 KB)
    unsigned int* Whhf = smu + 8192;           // 6144 u32 (24 KB)
    float2* B2f = (float2*)(smu + 14336);      // 256 f2
    float2* Brz = (float2*)(smu + 14848);      // 512 f2 (bih+bhh, gates r,z)
    float2* Bin = (float2*)(smu + 15872);      // 256 f2 (bih n)
    float2* Bhn = (float2*)(smu + 16384);      // 256 f2 (bhh n)
    int tid = threadIdx.x;
    for (int i = tid; i < 4 * 8 * 32; i += 256) {
        int lane = i & 31, nt = (i >> 5) & 7, kt = i >> 8;
        int gq = lane >> 2, tq = lane & 3;
        int n = nt * 8 + gq, ks = kt * 16 + tq * 2;
        W2f[i * 2 + 0] = pack2h(W2[ks * 64 + n], W2[(ks + 1) * 64 + n]);
        W2f[i * 2 + 1] = pack2h(W2[(ks + 8) * 64 + n], W2[(ks + 9) * 64 + n]);
    }
    for (int i = tid; i < 4 * 24 * 32; i += 256) {
        int lane = i & 31, nt = (i >> 5) % 24, kt = i / (24 * 32);
        int gq = lane >> 2, tq = lane & 3;
        int gcol = nt * 8 + gq, ks = kt * 16 + tq * 2;
        Wihf[i * 2 + 0] = pack2h(Wih[gcol * 64 + ks], Wih[gcol * 64 + ks + 1]);
        Wihf[i * 2 + 1] = pack2h(Wih[gcol * 64 + ks + 8], Wih[gcol * 64 + ks + 9]);
        Whhf[i * 2 + 0] = pack2h(Whh[gcol * 64 + ks], Whh[gcol * 64 + ks + 1]);
        Whhf[i * 2 + 1] = pack2h(Whh[gcol * 64 + ks + 8], Whh[gcol * 64 + ks + 9]);
    }
    for (int i = tid; i < 8 * 32; i += 256) {
        int lane = i & 31, nt = i >> 5, tq = lane & 3;
        B2f[i] = make_float2(b2[nt * 8 + tq * 2], b2[nt * 8 + tq * 2 + 1]);
        Bin[i] = make_float2(bih[128 + nt * 8 + tq * 2], bih[128 + nt * 8 + tq * 2 + 1]);
        Bhn[i] = make_float2(bhh[128 + nt * 8 + tq * 2], bhh[128 + nt * 8 + tq * 2 + 1]);
    }
    for (int i = tid; i < 16 * 32; i += 256) {
        int lane = i & 31, nt = i >> 5, tq = lane & 3;
        int k0 = nt * 8 + tq * 2;
        Brz[i] = make_float2(bih[k0] + bhh[k0], bih[k0 + 1] + bhh[k0 + 1]);
    }
    __syncthreads();

    int lane = tid & 31;
    int tile = blockIdx.x * 8 + (tid >> 5);
    if (tile >= NN / 16) return;
    int row0 = tile * 16;
    int gq = lane >> 2, tq = lane & 3;

    float hc[8][4];                                  // h state, fp32 C-frags
    #pragma unroll
    for (int nt = 0; nt < 8; nt++)
        #pragma unroll
        for (int j = 0; j < 4; j++) hc[nt][j] = 0.f;

    for (int t = 0; t < TT; t++) {
        // dall: ntiles 0-15 = r,z (gi+gh combined); 16-23 = h_n (gh part only)
        float dall[24][4];
        #pragma unroll
        for (int nt = 0; nt < 16; nt++) {
            float2 bb = Brz[nt * 32 + lane];
            dall[nt][0] = bb.x; dall[nt][1] = bb.y; dall[nt][2] = bb.x; dall[nt][3] = bb.y;
        }
        #pragma unroll
        for (int nt = 0; nt < 8; nt++) {
            float2 bb = Bhn[nt * 32 + lane];
            dall[16 + nt][0] = bb.x; dall[16 + nt][1] = bb.y;
            dall[16 + nt][2] = bb.x; dall[16 + nt][3] = bb.y;
        }
        if (t) {   // gh = h @ Whh^T into all 24 ntiles
            unsigned int Ah[4][4];
            #pragma unroll
            for (int kt = 0; kt < 4; kt++) {
                Ah[kt][0] = pack2h(hc[2 * kt][0], hc[2 * kt][1]);
                Ah[kt][1] = pack2h(hc[2 * kt][2], hc[2 * kt][3]);
                Ah[kt][2] = pack2h(hc[2 * kt + 1][0], hc[2 * kt + 1][1]);
                Ah[kt][3] = pack2h(hc[2 * kt + 1][2], hc[2 * kt + 1][3]);
            }
            #pragma unroll
            for (int kt = 0; kt < 4; kt++)
                #pragma unroll
                for (int nt = 0; nt < 24; nt++)
                    mma16816(dall[nt], Ah[kt], &Whhf[((kt * 24 + nt) * 32 + lane) * 2]);
        }
        // h2 = relu(P2[t] @ W2 + b2)
        unsigned int A[4][4];
        {
            const unsigned int* base0 = (const unsigned int*)(P2H + ((size_t)t * NN + row0 + gq) * 64);
            const unsigned int* base8 = base0 + 8 * 32;
            #pragma unroll
            for (int kt = 0; kt < 4; kt++) {
                A[kt][0] = base0[kt * 8 + tq];
                A[kt][1] = base8[kt * 8 + tq];
                A[kt][2] = base0[kt * 8 + tq + 4];
                A[kt][3] = base8[kt * 8 + tq + 4];
            }
        }
        float c[8][4];
        #pragma unroll
        for (int nt = 0; nt < 8; nt++) {
            float2 bb = B2f[nt * 32 + lane];
            c[nt][0] = bb.x; c[nt][1] = bb.y; c[nt][2] = bb.x; c[nt][3] = bb.y;
        }
        #pragma unroll
        for (int kt = 0; kt < 4; kt++)
            #pragma unroll
            for (int nt = 0; nt < 8; nt++)
                mma16816(c[nt], A[kt], &W2f[((kt * 8 + nt) * 32 + lane) * 2]);
        unsigned int A2[4][4];
        #pragma unroll
        for (int kt = 0; kt < 4; kt++) {
            A2[kt][0] = pack2h(fmaxf(c[2 * kt][0], 0.f), fmaxf(c[2 * kt][1], 0.f));
            A2[kt][1] = pack2h(fmaxf(c[2 * kt][2], 0.f), fmaxf(c[2 * kt][3], 0.f));
            A2[kt][2] = pack2h(fmaxf(c[2 * kt + 1][0], 0.f), fmaxf(c[2 * kt + 1][1], 0.f));
            A2[kt][3] = pack2h(fmaxf(c[2 * kt + 1][2], 0.f), fmaxf(c[2 * kt + 1][3], 0.f));
        }
        // gi r,z into dall[0..15]
        #pragma unroll
        for (int kt = 0; kt < 4; kt++)
            #pragma unroll
            for (int nt = 0; nt < 16; nt++)
                mma16816(dall[nt], A2[kt], &Wihf[((kt * 24 + nt) * 32 + lane) * 2]);
        // i_n separate
        float din[8][4];
        #pragma unroll
        for (int nt = 0; nt < 8; nt++) {
            float2 bb = Bin[nt * 32 + lane];
            din[nt][0] = bb.x; din[nt][1] = bb.y; din[nt][2] = bb.x; din[nt][3] = bb.y;
        }
        #pragma unroll
        for (int kt = 0; kt < 4; kt++)
            #pragma unroll
            for (int nt = 0; nt < 8; nt++)
                mma16816(din[nt], A2[kt], &Wihf[((kt * 24 + 16 + nt) * 32 + lane) * 2]);
        // gates
        #pragma unroll
        for (int nt = 0; nt < 8; nt++) {
            #pragma unroll
            for (int j = 0; j < 4; j++) {
                float r = sigf(dall[nt][j]);
                float z = sigf(dall[nt + 8][j]);
                float n = tanhf(din[nt][j] + r * dall[nt + 16][j]);
                hc[nt][j] = (1.f - z) * n + z * hc[nt][j];
            }
        }
    }
    // write h_last (fp32)
    float2* o0 = (float2*)(H0P + (size_t)(row0 + gq) * 64);
    float2* o8 = (float2*)(H0P + (size_t)(row0 + gq + 8) * 64);
    #pragma unroll
    for (int nt = 0; nt < 8; nt++) {
        o0[nt * 4 + tq] = make_float2(hc[nt][0], hc[nt][1]);
        o8[nt * 4 + tq] = make_float2(hc[nt][2], hc[nt][3]);
    }
}

// ---------------- classifier head + state cleanup ---------------------------
__global__ __launch_bounds__(256) void k_cls(const float* __restrict__ Wc1,
                                             const float* __restrict__ bc1,
                                             const float* __restrict__ Wc2,
                                             const float* __restrict__ bc2,
                                             float* __restrict__ out) {
    int gid = blockIdx.x * blockDim.x + threadIdx.x;
    if (gid < NN) { g_degi[gid] = 0; g_cursor[gid] = 0; }

    __shared__ float W1s[64 * 32];
    __shared__ float w2s[32], b1s[32];
    int tid = threadIdx.x;
    for (int i = tid; i < 2048; i += 256) W1s[i] = Wc1[i];
    if (tid < 32) { w2s[tid] = Wc2[tid]; b1s[tid] = bc1[tid]; }
    __syncthreads();
    int lane = tid & 31;
    int n = blockIdx.x * 8 + (tid >> 5);
    if (n >= NN) return;
    float h0 = H0P[(size_t)n * 64 + lane];
    float h1 = H0P[(size_t)n * 64 + 32 + lane];
    float acc = b1s[lane];
    #pragma unroll
    for (int h = 0; h < 32; h++) {
        float xv = __shfl_sync(0xffffffffu, h0, h);
        acc = fmaf(xv, W1s[h * 32 + lane], acc);
    }
    #pragma unroll
    for (int h = 0; h < 32; h++) {
        float xv = __shfl_sync(0xffffffffu, h1, h);
        acc = fmaf(xv, W1s[(h + 32) * 32 + lane], acc);
    }
    acc = fmaxf(acc, 0.f);
    float p = acc * w2s[lane];
    #pragma unroll
    for (int off = 16; off; off >>= 1) p += __shfl_xor_sync(0xffffffffu, p, off);
    if (lane == 0) out[n] = p + bc2[0];
}

// ---------------- launch ----------------------------------------------------
extern "C" void kernel_launch(void* const* d_in, const int* in_sizes, int n_in,
                              void* d_out, int out_size) {
    const float* x   = (const float*)d_in[0];
    const int*   ei  = (const int*)d_in[1];
    const float* W1  = (const float*)d_in[2];
    const float* b1  = (const float*)d_in[3];
    const float* W2  = (const float*)d_in[4];
    const float* b2  = (const float*)d_in[5];
    const float* Wih = (const float*)d_in[6];
    const float* Whh = (const float*)d_in[7];
    const float* bih = (const float*)d_in[8];
    const float* bhh = (const float*)d_in[9];
    const float* Wc1 = (const float*)d_in[10];
    const float* bc1 = (const float*)d_in[11];
    const float* Wc2 = (const float*)d_in[12];
    const float* bc2 = (const float*)d_in[13];
    float* out = (float*)d_out;

    int E = in_sizes[1] / 2;
    const int* src = ei;
    const int* dst = ei + E;

    cudaFuncSetAttribute(k_fused, cudaFuncAttributeMaxDynamicSharedMemorySize, 69632);

    // graph preprocessing + x fp16 conversion
    k_count<<<(E + 255) / 256, 256>>>(dst, E);
    k_scan_norm<<<1, 1024>>>();
    k_fill<<<(E + 255) / 256, 256>>>(src, dst, E);
    k_cvt<<<(ROWS * FF / 4 + 255) / 256, 256>>>((const float4*)x);

    // layer 1: P1 = Ahat * x (fp16 gather, 3 t-chunks) -> BUFA(32)
    k_agg32<<<dim3(NN / 8, 3), 256>>>();
    k_gemm1<<<1184, 256>>>(W1, b1);

    // layer 2: P2 = Ahat * h1 (3 t-chunks) -> fp16 P2H
    k_agg64<<<dim3(NN / 8, 3), 256>>>();

    // fused HMMA: h2 + gi + full 12-step GRU, no gi materialization
    k_fused<<<(NN / 16 + 7) / 8, 256, 69632>>>(W2, b2, Wih, bih, Whh, bhh);

    // classifier head (+ zero degi/cursor for next call)
    k_cls<<<(NN + 7) / 8, 256>>>(Wc1, bc1, Wc2, bc2, out);
}

// round 9
// speedup vs baseline: 3.1736x; 1.1556x over previous
#include <cuda_runtime.h>
#include <cuda_fp16.h>
#include <math.h>

// Problem constants
constexpr int TT = 12;
constexpr int NN = 50000;
constexpr int FF = 32;
constexpr int HH = 64;
constexpr int EE = 1600000;
constexpr int ROWS = TT * NN;     // 600000
constexpr int NB = (NN + 1023) / 1024;   // 49 scan blocks

// ---------------- static device scratch (zero-initialized at load) ---------
__device__ int     g_degi[NN];
__device__ int     g_cursor[NN];
__device__ float   g_dinv[NN];
__device__ float   g_invdeg[NN];
__device__ int     g_rowptr[NN + 1];     // local (per-scan-block) prefix
__device__ int     g_bsum[64];
__device__ int     g_boff[64];
__device__ int2    g_epk[EE];                              // packed (src, w)
__device__ uint4   g_xhu4[(size_t)ROWS * FF / 8];          // 38.4 MB x fp16
__device__ uint4   g_p1u4[(size_t)ROWS * FF / 8];          // 38.4 MB P1 fp16
__device__ uint4   g_h1u4[(size_t)ROWS * HH / 8];          // 76.8 MB h1 fp16
__device__ uint4   g_p2u4[(size_t)ROWS * HH / 8];          // 76.8 MB P2 fp16
__device__ float4  g_h0_4[(size_t)NN * HH / 4];

#define P1H  ((__half*)g_p1u4)
#define H1H  ((__half*)g_h1u4)
#define P2H  ((__half*)g_p2u4)
#define H0P  ((float*)g_h0_4)

// ---------------- helpers ---------------------------------------------------
union F2U { float2 f; unsigned long long u; };
__device__ __forceinline__ float2 ffma2(float2 a, float2 b, float2 c) {
    F2U A, B, C, D; A.f = a; B.f = b; C.f = c;
    asm("fma.rn.f32x2 %0, %1, %2, %3;" : "=l"(D.u) : "l"(A.u), "l"(B.u), "l"(C.u));
    return D.f;
}
__device__ __forceinline__ float2 h2f2(unsigned int u) {
    __half2 h = *reinterpret_cast<const __half2*>(&u);
    return __half22float2(h);
}
__device__ __forceinline__ unsigned int pack2h(float a, float b) {
    __half2 h = __floats2half2_rn(a, b);
    return *reinterpret_cast<unsigned int*>(&h);
}
__device__ __forceinline__ float sigf(float x) { return 1.f / (1.f + expf(-x)); }

// m16n8k16 fp16 MMA, fp32 accumulate (A row-major, B col-major)
__device__ __forceinline__ void mma16816(float* c, const unsigned int* a, const unsigned int* b) {
    asm volatile(
        "mma.sync.aligned.m16n8k16.row.col.f32.f16.f16.f32 "
        "{%0,%1,%2,%3}, {%4,%5,%6,%7}, {%8,%9}, {%0,%1,%2,%3};\n"
        : "+f"(c[0]), "+f"(c[1]), "+f"(c[2]), "+f"(c[3])
        : "r"(a[0]), "r"(a[1]), "r"(a[2]), "r"(a[3]), "r"(b[0]), "r"(b[1]));
}

// ---------------- preprocessing --------------------------------------------
// degree count + x fp16 conversion, one grid (independent work, overlapped)
__global__ __launch_bounds__(256) void k_countcvt(const int* __restrict__ dst, int E,
                                                  const float4* __restrict__ x4) {
    unsigned int i = blockIdx.x * blockDim.x + threadIdx.x;
    if (i < (unsigned int)E) atomicAdd(&g_degi[dst[i]], 1);
    if (i < (unsigned int)(ROWS * FF / 4)) {
        float4 v = x4[i];
        ((uint2*)g_xhu4)[i] = make_uint2(pack2h(v.x, v.y), pack2h(v.z, v.w));
    }
}

// hierarchical scan stage 1: per-block local exclusive scan + norm + block sum
__global__ void k_pre1() {
    __shared__ int wsum[32];
    int b = blockIdx.x, tid = threadIdx.x, lane = tid & 31, wid = tid >> 5;
    int idx = b * 1024 + tid;
    int v = (idx < NN) ? g_degi[idx] : 0;
    int x = v;
    #pragma unroll
    for (int o = 1; o < 32; o <<= 1) {
        int y = __shfl_up_sync(0xffffffffu, x, o);
        if (lane >= o) x += y;
    }
    if (lane == 31) wsum[wid] = x;
    __syncthreads();
    if (wid == 0) {
        int w = wsum[lane];
        int xw = w;
        #pragma unroll
        for (int o = 1; o < 32; o <<= 1) {
            int y = __shfl_up_sync(0xffffffffu, xw, o);
            if (lane >= o) xw += y;
        }
        wsum[lane] = xw - w;   // exclusive warp offsets
    }
    __syncthreads();
    int excl = wsum[wid] + x - v;
    if (idx < NN) {
        g_rowptr[idx] = excl;
        float deg = (float)v + 1.0f;
        g_dinv[idx] = rsqrtf(deg);
        g_invdeg[idx] = 1.0f / deg;
    }
    if (tid == 1023) g_bsum[b] = excl + v;
}

// stage 2: one warp scans the NB block sums -> g_boff; sets rowptr[NN] local
__global__ void k_pre2() {
    int l = threadIdx.x;   // 32 threads
    int a = (l < NB) ? g_bsum[l] : 0;
    int xa = a;
    #pragma unroll
    for (int o = 1; o < 32; o <<= 1) {
        int y = __shfl_up_sync(0xffffffffu, xa, o);
        if (l >= o) xa += y;
    }
    int totalA = __shfl_sync(0xffffffffu, xa, 31);
    int b2 = (l + 32 < NB) ? g_bsum[l + 32] : 0;
    int xb = b2;
    #pragma unroll
    for (int o = 1; o < 32; o <<= 1) {
        int y = __shfl_up_sync(0xffffffffu, xb, o);
        if (l >= o) xb += y;
    }
    g_boff[l] = xa - a;
    if (l + 32 < NB + 1) g_boff[l + 32] = totalA + xb - b2;
    if (l == 0) g_rowptr[NN] = g_bsum[NB - 1];  // final[NN] = rowptr[NN]+boff[(NN)>>10]
}

__global__ void k_fill(const int* __restrict__ src, const int* __restrict__ dst, int E) {
    int e = blockIdx.x * blockDim.x + threadIdx.x;
    if (e < E) {
        int s = src[e], d = dst[e];
        float w = g_dinv[s] * g_dinv[d];
        int pos = g_rowptr[d] + g_boff[d >> 10] + atomicAdd(&g_cursor[d], 1);
        g_epk[pos] = make_int2(s, __float_as_int(w));
    }
}

// ---------------- aggregation layer 1: fp16 gather, 4 t per slice -----------
// warp per node. 8 groups of 4 lanes: group owns one edge; lane's uint4 = 8
// fp16 features of the 32-feature row. P1 written fp16.
__global__ __launch_bounds__(256) void k_agg32() {
    int lane = threadIdx.x & 31;
    int n = blockIdx.x * 8 + (threadIdx.x >> 5);
    if (n >= NN) return;
    int c = blockIdx.y;                                  // 0..2
    int g = lane >> 2, sub = lane & 3;
    const uint4* __restrict__ x4 = g_xhu4 + (size_t)(c * 4) * NN * 4 + sub;
    int r0 = g_rowptr[n] + g_boff[n >> 10];
    int r1 = g_rowptr[n + 1] + g_boff[(n + 1) >> 10];
    float2 acc[4][4];
    #pragma unroll
    for (int t = 0; t < 4; t++)
        #pragma unroll
        for (int j = 0; j < 4; j++) acc[t][j] = make_float2(0.f, 0.f);
    int2 ep = (r0 + lane < r1) ? g_epk[r0 + lane] : make_int2(0, 0);
    for (int tile = r0; tile < r1; tile += 32) {
        int2 epc = ep;
        int nxt = tile + 32;
        if (nxt < r1) ep = (nxt + lane < r1) ? g_epk[nxt + lane] : make_int2(0, 0);
        int nb = r1 - tile; if (nb > 32) nb = 32;
        for (int b = 0; b * 8 < nb; b++) {
            int ss = __shfl_sync(0xffffffffu, epc.x, b * 8 + g);
            float ww = __int_as_float(__shfl_sync(0xffffffffu, epc.y, b * 8 + g));
            float2 w2 = make_float2(ww, ww);
            const uint4* p = x4 + (size_t)ss * 4;
            #pragma unroll
            for (int t = 0; t < 4; t++) {
                uint4 v = p[(size_t)t * (NN * 4)];
                acc[t][0] = ffma2(w2, h2f2(v.x), acc[t][0]);
                acc[t][1] = ffma2(w2, h2f2(v.y), acc[t][1]);
                acc[t][2] = ffma2(w2, h2f2(v.z), acc[t][2]);
                acc[t][3] = ffma2(w2, h2f2(v.w), acc[t][3]);
            }
        }
    }
    if (g == 0) {   // self-loop, added once pre-reduction
        float id = g_invdeg[n];
        float2 w2 = make_float2(id, id);
        const uint4* p = x4 + (size_t)n * 4;
        #pragma unroll
        for (int t = 0; t < 4; t++) {
            uint4 v = p[(size_t)t * (NN * 4)];
            acc[t][0] = ffma2(w2, h2f2(v.x), acc[t][0]);
            acc[t][1] = ffma2(w2, h2f2(v.y), acc[t][1]);
            acc[t][2] = ffma2(w2, h2f2(v.z), acc[t][2]);
            acc[t][3] = ffma2(w2, h2f2(v.w), acc[t][3]);
        }
    }
    #pragma unroll
    for (int t = 0; t < 4; t++) {
        #pragma unroll
        for (int j = 0; j < 4; j++) {
            float2 a = acc[t][j];
            #pragma unroll
            for (int off = 4; off <= 16; off <<= 1) {
                a.x += __shfl_xor_sync(0xffffffffu, a.x, off);
                a.y += __shfl_xor_sync(0xffffffffu, a.y, off);
            }
            acc[t][j] = a;
        }
        if (g == t) {
            uint4 pk;
            pk.x = pack2h(acc[t][0].x, acc[t][0].y);
            pk.y = pack2h(acc[t][1].x, acc[t][1].y);
            pk.z = pack2h(acc[t][2].x, acc[t][2].y);
            pk.w = pack2h(acc[t][3].x, acc[t][3].y);
            g_p1u4[((size_t)(c * 4 + t) * NN + n) * 4 + sub] = pk;
        }
    }
}

// ---------------- aggregation layer 2: fp16 in/out, 4 t per slice -----------
__global__ __launch_bounds__(256) void k_agg64() {
    int lane = threadIdx.x & 31;
    int n = blockIdx.x * 8 + (threadIdx.x >> 5);
    if (n >= NN) return;
    int c = blockIdx.y;                                  // 0..2
    int g = lane >> 3, sub = lane & 7;
    int r0 = g_rowptr[n] + g_boff[n >> 10];
    int r1 = g_rowptr[n + 1] + g_boff[(n + 1) >> 10];
    const uint4* __restrict__ hb = g_h1u4 + (size_t)(c * 4) * NN * 8 + sub;
    float2 acc[4][4];
    #pragma unroll
    for (int t = 0; t < 4; t++)
        #pragma unroll
        for (int j = 0; j < 4; j++) acc[t][j] = make_float2(0.f, 0.f);
    int2 ep = (r0 + lane < r1) ? g_epk[r0 + lane] : make_int2(0, 0);
    for (int tile = r0; tile < r1; tile += 32) {
        int2 epc = ep;
        int nxt = tile + 32;
        if (nxt < r1) ep = (nxt + lane < r1) ? g_epk[nxt + lane] : make_int2(0, 0);
        int nb = r1 - tile; if (nb > 32) nb = 32;
        for (int b = 0; b * 4 < nb; b++) {
            int ss = __shfl_sync(0xffffffffu, epc.x, b * 4 + g);
            float ww = __int_as_float(__shfl_sync(0xffffffffu, epc.y, b * 4 + g));
            float2 w2 = make_float2(ww, ww);
            const uint4* p = hb + (size_t)ss * 8;
            #pragma unroll
            for (int t = 0; t < 4; t++) {
                uint4 hv = p[(size_t)t * (NN * 8)];
                acc[t][0] = ffma2(w2, h2f2(hv.x), acc[t][0]);
                acc[t][1] = ffma2(w2, h2f2(hv.y), acc[t][1]);
                acc[t][2] = ffma2(w2, h2f2(hv.z), acc[t][2]);
                acc[t][3] = ffma2(w2, h2f2(hv.w), acc[t][3]);
            }
        }
    }
    if (g == 0) {
        float id = g_invdeg[n];
        float2 w2 = make_float2(id, id);
        const uint4* p = hb + (size_t)n * 8;
        #pragma unroll
        for (int t = 0; t < 4; t++) {
            uint4 hv = p[(size_t)t * (NN * 8)];
            acc[t][0] = ffma2(w2, h2f2(hv.x), acc[t][0]);
            acc[t][1] = ffma2(w2, h2f2(hv.y), acc[t][1]);
            acc[t][2] = ffma2(w2, h2f2(hv.z), acc[t][2]);
            acc[t][3] = ffma2(w2, h2f2(hv.w), acc[t][3]);
        }
    }
    #pragma unroll
    for (int t = 0; t < 4; t++) {
        #pragma unroll
        for (int j = 0; j < 4; j++) {
            float2 a = acc[t][j];
            #pragma unroll
            for (int off = 8; off <= 16; off <<= 1) {
                a.x += __shfl_xor_sync(0xffffffffu, a.x, off);
                a.y += __shfl_xor_sync(0xffffffffu, a.y, off);
            }
            acc[t][j] = a;
        }
        if (g == t) {
            uint4 pk;
            pk.x = pack2h(acc[t][0].x, acc[t][0].y);
            pk.y = pack2h(acc[t][1].x, acc[t][1].y);
            pk.z = pack2h(acc[t][2].x, acc[t][2].y);
            pk.w = pack2h(acc[t][3].x, acc[t][3].y);
            g_p2u4[((size_t)(c * 4 + t) * NN + n) * 8 + sub] = pk;
        }
    }
}

// ---------------- HMMA dense layer 1: h1 = relu(P1 @ W1 + b1) -> fp16 -------
__global__ __launch_bounds__(256) void k_gemm1h(const float* __restrict__ W,
                                                const float* __restrict__ b) {
    __shared__ unsigned int Wf[2 * 8 * 32 * 2];   // 4 KB
    __shared__ float2 Bf[8 * 32];                 // 2 KB
    int tid = threadIdx.x;
    for (int i = tid; i < 2 * 8 * 32; i += 256) {
        int lane = i & 31, nt = (i >> 5) & 7, kt = i >> 8;
        int gq = lane >> 2, tq = lane & 3;
        int n = nt * 8 + gq, ks = kt * 16 + tq * 2;
        Wf[i * 2 + 0] = pack2h(W[ks * 64 + n], W[(ks + 1) * 64 + n]);
        Wf[i * 2 + 1] = pack2h(W[(ks + 8) * 64 + n], W[(ks + 9) * 64 + n]);
    }
    for (int i = tid; i < 8 * 32; i += 256) {
        int lane = i & 31, nt = i >> 5, tq = lane & 3;
        Bf[i] = make_float2(b[nt * 8 + tq * 2], b[nt * 8 + tq * 2 + 1]);
    }
    __syncthreads();
    int lane = tid & 31;
    int tile = blockIdx.x * 8 + (tid >> 5);
    if (tile >= ROWS / 16) return;
    int row0 = tile * 16;
    int gq = lane >> 2, tq = lane & 3;

    unsigned int A[2][4];
    const unsigned int* base0 = (const unsigned int*)(P1H + (size_t)(row0 + gq) * 32);
    const unsigned int* base8 = (const unsigned int*)(P1H + (size_t)(row0 + gq + 8) * 32);
    #pragma unroll
    for (int kt = 0; kt < 2; kt++) {
        A[kt][0] = base0[kt * 8 + tq];
        A[kt][1] = base8[kt * 8 + tq];
        A[kt][2] = base0[kt * 8 + tq + 4];
        A[kt][3] = base8[kt * 8 + tq + 4];
    }
    float c[8][4];
    #pragma unroll
    for (int nt = 0; nt < 8; nt++) {
        float2 bb = Bf[nt * 32 + lane];
        c[nt][0] = bb.x; c[nt][1] = bb.y; c[nt][2] = bb.x; c[nt][3] = bb.y;
    }
    #pragma unroll
    for (int kt = 0; kt < 2; kt++)
        #pragma unroll
        for (int nt = 0; nt < 8; nt++)
            mma16816(c[nt], A[kt], &Wf[((kt * 8 + nt) * 32 + lane) * 2]);
    unsigned int* o0 = (unsigned int*)(H1H + (size_t)(row0 + gq) * 64);
    unsigned int* o8 = (unsigned int*)(H1H + (size_t)(row0 + gq + 8) * 64);
    #pragma unroll
    for (int nt = 0; nt < 8; nt++) {
        o0[nt * 4 + tq] = pack2h(fmaxf(c[nt][0], 0.f), fmaxf(c[nt][1], 0.f));
        o8[nt * 4 + tq] = pack2h(fmaxf(c[nt][2], 0.f), fmaxf(c[nt][3], 0.f));
    }
}

// ---------------- fused HMMA: h2+gi+GRU, no gi materialization --------------
__global__ __launch_bounds__(256) void k_fused(const float* __restrict__ W2,
                                               const float* __restrict__ b2,
                                               const float* __restrict__ Wih,
                                               const float* __restrict__ bih,
                                               const float* __restrict__ Whh,
                                               const float* __restrict__ bhh) {
    extern __shared__ unsigned int smu[];
    unsigned int* W2f  = smu;                  // 2048 u32 (8 KB)
    unsigned int* Wihf = smu + 2048;           // 6144 u32 (24 KB)
    unsigned int* Whhf = smu + 8192;           // 6144 u32 (24 KB)
    float2* B2f = (float2*)(smu + 14336);      // 256 f2
    float2* Brz = (float2*)(smu + 14848);      // 512 f2 (bih+bhh, gates r,z)
    float2* Bin = (float2*)(smu + 15872);      // 256 f2 (bih n)
    float2* Bhn = (float2*)(smu + 16384);      // 256 f2 (bhh n)
    int tid = threadIdx.x;
    for (int i = tid; i < 4 * 8 * 32; i += 256) {
        int lane = i & 31, nt = (i >> 5) & 7, kt = i >> 8;
        int gq = lane >> 2, tq = lane & 3;
        int n = nt * 8 + gq, ks = kt * 16 + tq * 2;
        W2f[i * 2 + 0] = pack2h(W2[ks * 64 + n], W2[(ks + 1) * 64 + n]);
        W2f[i * 2 + 1] = pack2h(W2[(ks + 8) * 64 + n], W2[(ks + 9) * 64 + n]);
    }
    for (int i = tid; i < 4 * 24 * 32; i += 256) {
        int lane = i & 31, nt = (i >> 5) % 24, kt = i / (24 * 32);
        int gq = lane >> 2, tq = lane & 3;
        int gcol = nt * 8 + gq, ks = kt * 16 + tq * 2;
        Wihf[i * 2 + 0] = pack2h(Wih[gcol * 64 + ks], Wih[gcol * 64 + ks + 1]);
        Wihf[i * 2 + 1] = pack2h(Wih[gcol * 64 + ks + 8], Wih[gcol * 64 + ks + 9]);
        Whhf[i * 2 + 0] = pack2h(Whh[gcol * 64 + ks], Whh[gcol * 64 + ks + 1]);
        Whhf[i * 2 + 1] = pack2h(Whh[gcol * 64 + ks + 8], Whh[gcol * 64 + ks + 9]);
    }
    for (int i = tid; i < 8 * 32; i += 256) {
        int lane = i & 31, nt = i >> 5, tq = lane & 3;
        B2f[i] = make_float2(b2[nt * 8 + tq * 2], b2[nt * 8 + tq * 2 + 1]);
        Bin[i] = make_float2(bih[128 + nt * 8 + tq * 2], bih[128 + nt * 8 + tq * 2 + 1]);
        Bhn[i] = make_float2(bhh[128 + nt * 8 + tq * 2], bhh[128 + nt * 8 + tq * 2 + 1]);
    }
    for (int i = tid; i < 16 * 32; i += 256) {
        int lane = i & 31, nt = i >> 5, tq = lane & 3;
        int k0 = nt * 8 + tq * 2;
        Brz[i] = make_float2(bih[k0] + bhh[k0], bih[k0 + 1] + bhh[k0 + 1]);
    }
    __syncthreads();

    int lane = tid & 31;
    int tile = blockIdx.x * 8 + (tid >> 5);
    if (tile >= NN / 16) return;
    int row0 = tile * 16;
    int gq = lane >> 2, tq = lane & 3;

    float hc[8][4];
    #pragma unroll
    for (int nt = 0; nt < 8; nt++)
        #pragma unroll
        for (int j = 0; j < 4; j++) hc[nt][j] = 0.f;

    for (int t = 0; t < TT; t++) {
        float dall[24][4];
        #pragma unroll
        for (int nt = 0; nt < 16; nt++) {
            float2 bb = Brz[nt * 32 + lane];
            dall[nt][0] = bb.x; dall[nt][1] = bb.y; dall[nt][2] = bb.x; dall[nt][3] = bb.y;
        }
        #pragma unroll
        for (int nt = 0; nt < 8; nt++) {
            float2 bb = Bhn[nt * 32 + lane];
            dall[16 + nt][0] = bb.x; dall[16 + nt][1] = bb.y;
            dall[16 + nt][2] = bb.x; dall[16 + nt][3] = bb.y;
        }
        if (t) {
            unsigned int Ah[4][4];
            #pragma unroll
            for (int kt = 0; kt < 4; kt++) {
                Ah[kt][0] = pack2h(hc[2 * kt][0], hc[2 * kt][1]);
                Ah[kt][1] = pack2h(hc[2 * kt][2], hc[2 * kt][3]);
                Ah[kt][2] = pack2h(hc[2 * kt + 1][0], hc[2 * kt + 1][1]);
                Ah[kt][3] = pack2h(hc[2 * kt + 1][2], hc[2 * kt + 1][3]);
            }
            #pragma unroll
            for (int kt = 0; kt < 4; kt++)
                #pragma unroll
                for (int nt = 0; nt < 24; nt++)
                    mma16816(dall[nt], Ah[kt], &Whhf[((kt * 24 + nt) * 32 + lane) * 2]);
        }
        unsigned int A[4][4];
        {
            const unsigned int* base0 = (const unsigned int*)(P2H + ((size_t)t * NN + row0 + gq) * 64);
            const unsigned int* base8 = base0 + 8 * 32;
            #pragma unroll
            for (int kt = 0; kt < 4; kt++) {
                A[kt][0] = base0[kt * 8 + tq];
                A[kt][1] = base8[kt * 8 + tq];
                A[kt][2] = base0[kt * 8 + tq + 4];
                A[kt][3] = base8[kt * 8 + tq + 4];
            }
        }
        float c[8][4];
        #pragma unroll
        for (int nt = 0; nt < 8; nt++) {
            float2 bb = B2f[nt * 32 + lane];
            c[nt][0] = bb.x; c[nt][1] = bb.y; c[nt][2] = bb.x; c[nt][3] = bb.y;
        }
        #pragma unroll
        for (int kt = 0; kt < 4; kt++)
            #pragma unroll
            for (int nt = 0; nt < 8; nt++)
                mma16816(c[nt], A[kt], &W2f[((kt * 8 + nt) * 32 + lane) * 2]);
        unsigned int A2[4][4];
        #pragma unroll
        for (int kt = 0; kt < 4; kt++) {
            A2[kt][0] = pack2h(fmaxf(c[2 * kt][0], 0.f), fmaxf(c[2 * kt][1], 0.f));
            A2[kt][1] = pack2h(fmaxf(c[2 * kt][2], 0.f), fmaxf(c[2 * kt][3], 0.f));
            A2[kt][2] = pack2h(fmaxf(c[2 * kt + 1][0], 0.f), fmaxf(c[2 * kt + 1][1], 0.f));
            A2[kt][3] = pack2h(fmaxf(c[2 * kt + 1][2], 0.f), fmaxf(c[2 * kt + 1][3], 0.f));
        }
        #pragma unroll
        for (int kt = 0; kt < 4; kt++)
            #pragma unroll
            for (int nt = 0; nt < 16; nt++)
                mma16816(dall[nt], A2[kt], &Wihf[((kt * 24 + nt) * 32 + lane) * 2]);
        float din[8][4];
        #pragma unroll
        for (int nt = 0; nt < 8; nt++) {
            float2 bb = Bin[nt * 32 + lane];
            din[nt][0] = bb.x; din[nt][1] = bb.y; din[nt][2] = bb.x; din[nt][3] = bb.y;
        }
        #pragma unroll
        for (int kt = 0; kt < 4; kt++)
            #pragma unroll
            for (int nt = 0; nt < 8; nt++)
                mma16816(din[nt], A2[kt], &Wihf[((kt * 24 + 16 + nt) * 32 + lane) * 2]);
        #pragma unroll
        for (int nt = 0; nt < 8; nt++) {
            #pragma unroll
            for (int j = 0; j < 4; j++) {
                float r = sigf(dall[nt][j]);
                float z = sigf(dall[nt + 8][j]);
                float n = tanhf(din[nt][j] + r * dall[nt + 16][j]);
                hc[nt][j] = (1.f - z) * n + z * hc[nt][j];
            }
        }
    }
    float2* o0 = (float2*)(H0P + (size_t)(row0 + gq) * 64);
    float2* o8 = (float2*)(H0P + (size_t)(row0 + gq + 8) * 64);
    #pragma unroll
    for (int nt = 0; nt < 8; nt++) {
        o0[nt * 4 + tq] = make_float2(hc[nt][0], hc[nt][1]);
        o8[nt * 4 + tq] = make_float2(hc[nt][2], hc[nt][3]);
    }
}

// ---------------- classifier head + state cleanup ---------------------------
__global__ __launch_bounds__(256) void k_cls(const float* __restrict__ Wc1,
                                             const float* __restrict__ bc1,
                                             const float* __restrict__ Wc2,
                                             const float* __restrict__ bc2,
                                             float* __restrict__ out) {
    int gid = blockIdx.x * blockDim.x + threadIdx.x;
    if (gid < NN) { g_degi[gid] = 0; g_cursor[gid] = 0; }

    __shared__ float W1s[64 * 32];
    __shared__ float w2s[32], b1s[32];
    int tid = threadIdx.x;
    for (int i = tid; i < 2048; i += 256) W1s[i] = Wc1[i];
    if (tid < 32) { w2s[tid] = Wc2[tid]; b1s[tid] = bc1[tid]; }
    __syncthreads();
    int lane = tid & 31;
    int n = blockIdx.x * 8 + (tid >> 5);
    if (n >= NN) return;
    float h0 = H0P[(size_t)n * 64 + lane];
    float h1 = H0P[(size_t)n * 64 + 32 + lane];
    float acc = b1s[lane];
    #pragma unroll
    for (int h = 0; h < 32; h++) {
        float xv = __shfl_sync(0xffffffffu, h0, h);
        acc = fmaf(xv, W1s[h * 32 + lane], acc);
    }
    #pragma unroll
    for (int h = 0; h < 32; h++) {
        float xv = __shfl_sync(0xffffffffu, h1, h);
        acc = fmaf(xv, W1s[(h + 32) * 32 + lane], acc);
    }
    acc = fmaxf(acc, 0.f);
    float p = acc * w2s[lane];
    #pragma unroll
    for (int off = 16; off; off >>= 1) p += __shfl_xor_sync(0xffffffffu, p, off);
    if (lane == 0) out[n] = p + bc2[0];
}

// ---------------- launch ----------------------------------------------------
extern "C" void kernel_launch(void* const* d_in, const int* in_sizes, int n_in,
                              void* d_out, int out_size) {
    const float* x   = (const float*)d_in[0];
    const int*   ei  = (const int*)d_in[1];
    const float* W1  = (const float*)d_in[2];
    const float* b1  = (const float*)d_in[3];
    const float* W2  = (const float*)d_in[4];
    const float* b2  = (const float*)d_in[5];
    const float* Wih = (const float*)d_in[6];
    const float* Whh = (const float*)d_in[7];
    const float* bih = (const float*)d_in[8];
    const float* bhh = (const float*)d_in[9];
    const float* Wc1 = (const float*)d_in[10];
    const float* bc1 = (const float*)d_in[11];
    const float* Wc2 = (const float*)d_in[12];
    const float* bc2 = (const float*)d_in[13];
    float* out = (float*)d_out;

    int E = in_sizes[1] / 2;
    const int* src = ei;
    const int* dst = ei + E;

    cudaFuncSetAttribute(k_fused, cudaFuncAttributeMaxDynamicSharedMemorySize, 69632);

    // preprocessing: degree count + x fp16 cvt (merged), hierarchical scan, CSR fill
    k_countcvt<<<(ROWS * FF / 4 + 255) / 256, 256>>>(dst, E, (const float4*)x);
    k_pre1<<<NB, 1024>>>();
    k_pre2<<<1, 32>>>();
    k_fill<<<(E + 255) / 256, 256>>>(src, dst, E);

    // layer 1: P1 = Ahat * x (fp16 gather, 3 t-chunks) -> fp16 P1H
    k_agg32<<<dim3(NN / 8, 3), 256>>>();
    // h1 = relu(P1 @ W1 + b1) via HMMA -> fp16 H1H
    k_gemm1h<<<(ROWS / 16 + 7) / 8, 256>>>(W1, b1);

    // layer 2: P2 = Ahat * h1 (3 t-chunks) -> fp16 P2H
    k_agg64<<<dim3(NN / 8, 3), 256>>>();

    // fused HMMA: h2 + gi + full 12-step GRU, no gi materialization
    k_fused<<<(NN / 16 + 7) / 8, 256, 69632>>>(W2, b2, Wih, bih, Whh, bhh);

    // classifier head (+ zero degi/cursor for next call)
    k_cls<<<(NN + 7) / 8, 256>>>(Wc1, bc1, Wc2, bc2, out);
}

// round 10
// speedup vs baseline: 3.2739x; 1.0316x over previous
#include <cuda_runtime.h>
#include <cuda_fp16.h>
#include <math.h>

// Problem constants
constexpr int TT = 12;
constexpr int NN = 50000;
constexpr int FF = 32;
constexpr int HH = 64;
constexpr int EE = 1600000;
constexpr int ROWS = TT * NN;     // 600000
constexpr int NB = (NN + 1023) / 1024;   // 49 scan blocks

// ---------------- static device scratch (zero-initialized at load) ---------
__device__ int     g_degi[NN];
__device__ int     g_cursor[NN];
__device__ float   g_dinv[NN];
__device__ float   g_invdeg[NN];
__device__ int     g_rowptr[NN + 1];     // local (per-scan-block) prefix
__device__ int     g_bsum[64];
__device__ int     g_boff[64];
__device__ int2    g_epk[EE];                              // packed (src, w)
__device__ uint4   g_xhu4[(size_t)ROWS * FF / 8];          // 38.4 MB x fp16
__device__ uint4   g_h1u4[(size_t)ROWS * HH / 8];          // 76.8 MB h1 fp16
__device__ uint4   g_p2u4[(size_t)ROWS * HH / 8];          // 76.8 MB P2 fp16

#define H1H  ((__half*)g_h1u4)
#define P2H  ((__half*)g_p2u4)

// ---------------- helpers ---------------------------------------------------
union F2U { float2 f; unsigned long long u; };
__device__ __forceinline__ float2 ffma2(float2 a, float2 b, float2 c) {
    F2U A, B, C, D; A.f = a; B.f = b; C.f = c;
    asm("fma.rn.f32x2 %0, %1, %2, %3;" : "=l"(D.u) : "l"(A.u), "l"(B.u), "l"(C.u));
    return D.f;
}
__device__ __forceinline__ float2 h2f2(unsigned int u) {
    __half2 h = *reinterpret_cast<const __half2*>(&u);
    return __half22float2(h);
}
__device__ __forceinline__ unsigned int pack2h(float a, float b) {
    __half2 h = __floats2half2_rn(a, b);
    return *reinterpret_cast<unsigned int*>(&h);
}
__device__ __forceinline__ float sigf(float x) { return 1.f / (1.f + expf(-x)); }

// m16n8k16 fp16 MMA, fp32 accumulate (A row-major, B col-major)
__device__ __forceinline__ void mma16816(float* c, const unsigned int* a, const unsigned int* b) {
    asm volatile(
        "mma.sync.aligned.m16n8k16.row.col.f32.f16.f16.f32 "
        "{%0,%1,%2,%3}, {%4,%5,%6,%7}, {%8,%9}, {%0,%1,%2,%3};\n"
        : "+f"(c[0]), "+f"(c[1]), "+f"(c[2]), "+f"(c[3])
        : "r"(a[0]), "r"(a[1]), "r"(a[2]), "r"(a[3]), "r"(b[0]), "r"(b[1]));
}

// ---------------- preprocessing --------------------------------------------
__global__ __launch_bounds__(256) void k_countcvt(const int* __restrict__ dst, int E,
                                                  const float4* __restrict__ x4) {
    unsigned int i = blockIdx.x * blockDim.x + threadIdx.x;
    if (i < (unsigned int)E) atomicAdd(&g_degi[dst[i]], 1);
    if (i < (unsigned int)(ROWS * FF / 4)) {
        float4 v = x4[i];
        ((uint2*)g_xhu4)[i] = make_uint2(pack2h(v.x, v.y), pack2h(v.z, v.w));
    }
}

__global__ void k_pre1() {
    __shared__ int wsum[32];
    int b = blockIdx.x, tid = threadIdx.x, lane = tid & 31, wid = tid >> 5;
    int idx = b * 1024 + tid;
    int v = (idx < NN) ? g_degi[idx] : 0;
    int x = v;
    #pragma unroll
    for (int o = 1; o < 32; o <<= 1) {
        int y = __shfl_up_sync(0xffffffffu, x, o);
        if (lane >= o) x += y;
    }
    if (lane == 31) wsum[wid] = x;
    __syncthreads();
    if (wid == 0) {
        int w = wsum[lane];
        int xw = w;
        #pragma unroll
        for (int o = 1; o < 32; o <<= 1) {
            int y = __shfl_up_sync(0xffffffffu, xw, o);
            if (lane >= o) xw += y;
        }
        wsum[lane] = xw - w;
    }
    __syncthreads();
    int excl = wsum[wid] + x - v;
    if (idx < NN) {
        g_rowptr[idx] = excl;
        float deg = (float)v + 1.0f;
        g_dinv[idx] = rsqrtf(deg);
        g_invdeg[idx] = 1.0f / deg;
    }
    if (tid == 1023) g_bsum[b] = excl + v;
}

__global__ void k_pre2() {
    int l = threadIdx.x;   // 32 threads
    int a = (l < NB) ? g_bsum[l] : 0;
    int xa = a;
    #pragma unroll
    for (int o = 1; o < 32; o <<= 1) {
        int y = __shfl_up_sync(0xffffffffu, xa, o);
        if (l >= o) xa += y;
    }
    int totalA = __shfl_sync(0xffffffffu, xa, 31);
    int b2 = (l + 32 < NB) ? g_bsum[l + 32] : 0;
    int xb = b2;
    #pragma unroll
    for (int o = 1; o < 32; o <<= 1) {
        int y = __shfl_up_sync(0xffffffffu, xb, o);
        if (l >= o) xb += y;
    }
    g_boff[l] = xa - a;
    if (l + 32 < NB + 1) g_boff[l + 32] = totalA + xb - b2;
    if (l == 0) g_rowptr[NN] = g_bsum[NB - 1];
}

__global__ void k_fill(const int* __restrict__ src, const int* __restrict__ dst, int E) {
    int e = blockIdx.x * blockDim.x + threadIdx.x;
    if (e < E) {
        int s = src[e], d = dst[e];
        float w = g_dinv[s] * g_dinv[d];
        int pos = g_rowptr[d] + g_boff[d >> 10] + atomicAdd(&g_cursor[d], 1);
        g_epk[pos] = make_int2(s, __float_as_int(w));
    }
}

// ---------------- fused agg32 + gemm1: h1 = relu((Ahat x) @ W1 + b1) --------
// warp = 4 nodes x 4 t (one m16 tile). Edge gather per node, xor-reduce,
// park rows in smem, one HMMA pass with W1, write h1 fp16 directly.
__global__ __launch_bounds__(256) void k_agg32f(const float* __restrict__ W,
                                                const float* __restrict__ b) {
    __shared__ unsigned int Wf[2 * 8 * 32 * 2];      // 4 KB  W1 B-frags
    __shared__ float2 Bf[8 * 32];                    // 2 KB  b1 frags
    __shared__ unsigned int Arows[8][16][16];        // 8 KB  16 rows x 32 fp16 per warp
    int tid = threadIdx.x;
    for (int i = tid; i < 2 * 8 * 32; i += 256) {
        int lane = i & 31, nt = (i >> 5) & 7, kt = i >> 8;
        int gq = lane >> 2, tq = lane & 3;
        int n = nt * 8 + gq, ks = kt * 16 + tq * 2;
        Wf[i * 2 + 0] = pack2h(W[ks * 64 + n], W[(ks + 1) * 64 + n]);
        Wf[i * 2 + 1] = pack2h(W[(ks + 8) * 64 + n], W[(ks + 9) * 64 + n]);
    }
    for (int i = tid; i < 8 * 32; i += 256) {
        int lane = i & 31, nt = i >> 5, tq = lane & 3;
        Bf[i] = make_float2(b[nt * 8 + tq * 2], b[nt * 8 + tq * 2 + 1]);
    }
    __syncthreads();

    int lane = tid & 31, wid = tid >> 5;
    int c = blockIdx.y;                              // t-chunk 0..2
    int quad = blockIdx.x * 8 + wid;
    if (quad >= NN / 4) return;
    int n0 = quad * 4;
    int g = lane >> 2, sub = lane & 3;
    const uint4* __restrict__ x4 = g_xhu4 + (size_t)(c * 4) * NN * 4 + sub;

    for (int r = 0; r < 4; r++) {
        int n = n0 + r;
        int r0 = g_rowptr[n] + g_boff[n >> 10];
        int r1 = g_rowptr[n + 1] + g_boff[(n + 1) >> 10];
        float2 acc[4][4];
        #pragma unroll
        for (int t = 0; t < 4; t++)
            #pragma unroll
            for (int j = 0; j < 4; j++) acc[t][j] = make_float2(0.f, 0.f);
        int2 ep = (r0 + lane < r1) ? g_epk[r0 + lane] : make_int2(0, 0);
        for (int tile = r0; tile < r1; tile += 32) {
            int2 epc = ep;
            int nxt = tile + 32;
            if (nxt < r1) ep = (nxt + lane < r1) ? g_epk[nxt + lane] : make_int2(0, 0);
            int nb = r1 - tile; if (nb > 32) nb = 32;
            for (int bb = 0; bb * 8 < nb; bb++) {
                int ss = __shfl_sync(0xffffffffu, epc.x, bb * 8 + g);
                float ww = __int_as_float(__shfl_sync(0xffffffffu, epc.y, bb * 8 + g));
                float2 w2 = make_float2(ww, ww);
                const uint4* p = x4 + (size_t)ss * 4;
                #pragma unroll
                for (int t = 0; t < 4; t++) {
                    uint4 v = p[(size_t)t * (NN * 4)];
                    acc[t][0] = ffma2(w2, h2f2(v.x), acc[t][0]);
                    acc[t][1] = ffma2(w2, h2f2(v.y), acc[t][1]);
                    acc[t][2] = ffma2(w2, h2f2(v.z), acc[t][2]);
                    acc[t][3] = ffma2(w2, h2f2(v.w), acc[t][3]);
                }
            }
        }
        if (g == 0) {   // self-loop
            float id = g_invdeg[n];
            float2 w2 = make_float2(id, id);
            const uint4* p = x4 + (size_t)n * 4;
            #pragma unroll
            for (int t = 0; t < 4; t++) {
                uint4 v = p[(size_t)t * (NN * 4)];
                acc[t][0] = ffma2(w2, h2f2(v.x), acc[t][0]);
                acc[t][1] = ffma2(w2, h2f2(v.y), acc[t][1]);
                acc[t][2] = ffma2(w2, h2f2(v.z), acc[t][2]);
                acc[t][3] = ffma2(w2, h2f2(v.w), acc[t][3]);
            }
        }
        #pragma unroll
        for (int t = 0; t < 4; t++) {
            #pragma unroll
            for (int j = 0; j < 4; j++) {
                float2 a = acc[t][j];
                #pragma unroll
                for (int off = 4; off <= 16; off <<= 1) {
                    a.x += __shfl_xor_sync(0xffffffffu, a.x, off);
                    a.y += __shfl_xor_sync(0xffffffffu, a.y, off);
                }
                if (g == t) Arows[wid][t * 4 + r][sub * 4 + j] = pack2h(a.x, a.y);
            }
        }
    }
    __syncwarp();

    // HMMA: h1 = relu(A @ W1 + b1), A = 16 rows x 32 feats from smem
    int gq = lane >> 2, tq = lane & 3;
    unsigned int A[2][4];
    #pragma unroll
    for (int kt = 0; kt < 2; kt++) {
        A[kt][0] = Arows[wid][gq][kt * 8 + tq];
        A[kt][1] = Arows[wid][gq + 8][kt * 8 + tq];
        A[kt][2] = Arows[wid][gq][kt * 8 + tq + 4];
        A[kt][3] = Arows[wid][gq + 8][kt * 8 + tq + 4];
    }
    float cc[8][4];
    #pragma unroll
    for (int nt = 0; nt < 8; nt++) {
        float2 bb = Bf[nt * 32 + lane];
        cc[nt][0] = bb.x; cc[nt][1] = bb.y; cc[nt][2] = bb.x; cc[nt][3] = bb.y;
    }
    #pragma unroll
    for (int kt = 0; kt < 2; kt++)
        #pragma unroll
        for (int nt = 0; nt < 8; nt++)
            mma16816(cc[nt], A[kt], &Wf[((kt * 8 + nt) * 32 + lane) * 2]);
    // row gq -> (t = gq>>2, node n0 + (gq&3)); row gq+8 -> (t = 2 + (gq>>2), same node)
    int t0 = gq >> 2, ri = gq & 3;
    unsigned int* o0 = (unsigned int*)(H1H + ((size_t)(c * 4 + t0) * NN + n0 + ri) * 64);
    unsigned int* o8 = (unsigned int*)(H1H + ((size_t)(c * 4 + t0 + 2) * NN + n0 + ri) * 64);
    #pragma unroll
    for (int nt = 0; nt < 8; nt++) {
        o0[nt * 4 + tq] = pack2h(fmaxf(cc[nt][0], 0.f), fmaxf(cc[nt][1], 0.f));
        o8[nt * 4 + tq] = pack2h(fmaxf(cc[nt][2], 0.f), fmaxf(cc[nt][3], 0.f));
    }
}

// ---------------- aggregation layer 2: fp16 in/out, 4 t per slice -----------
__global__ __launch_bounds__(256) void k_agg64() {
    int lane = threadIdx.x & 31;
    int n = blockIdx.x * 8 + (threadIdx.x >> 5);
    if (n >= NN) return;
    int c = blockIdx.y;                                  // 0..2
    int g = lane >> 3, sub = lane & 7;
    int r0 = g_rowptr[n] + g_boff[n >> 10];
    int r1 = g_rowptr[n + 1] + g_boff[(n + 1) >> 10];
    const uint4* __restrict__ hb = g_h1u4 + (size_t)(c * 4) * NN * 8 + sub;
    float2 acc[4][4];
    #pragma unroll
    for (int t = 0; t < 4; t++)
        #pragma unroll
        for (int j = 0; j < 4; j++) acc[t][j] = make_float2(0.f, 0.f);
    int2 ep = (r0 + lane < r1) ? g_epk[r0 + lane] : make_int2(0, 0);
    for (int tile = r0; tile < r1; tile += 32) {
        int2 epc = ep;
        int nxt = tile + 32;
        if (nxt < r1) ep = (nxt + lane < r1) ? g_epk[nxt + lane] : make_int2(0, 0);
        int nb = r1 - tile; if (nb > 32) nb = 32;
        for (int b = 0; b * 4 < nb; b++) {
            int ss = __shfl_sync(0xffffffffu, epc.x, b * 4 + g);
            float ww = __int_as_float(__shfl_sync(0xffffffffu, epc.y, b * 4 + g));
            float2 w2 = make_float2(ww, ww);
            const uint4* p = hb + (size_t)ss * 8;
            #pragma unroll
            for (int t = 0; t < 4; t++) {
                uint4 hv = p[(size_t)t * (NN * 8)];
                acc[t][0] = ffma2(w2, h2f2(hv.x), acc[t][0]);
                acc[t][1] = ffma2(w2, h2f2(hv.y), acc[t][1]);
                acc[t][2] = ffma2(w2, h2f2(hv.z), acc[t][2]);
                acc[t][3] = ffma2(w2, h2f2(hv.w), acc[t][3]);
            }
        }
    }
    if (g == 0) {
        float id = g_invdeg[n];
        float2 w2 = make_float2(id, id);
        const uint4* p = hb + (size_t)n * 8;
        #pragma unroll
        for (int t = 0; t < 4; t++) {
            uint4 hv = p[(size_t)t * (NN * 8)];
            acc[t][0] = ffma2(w2, h2f2(hv.x), acc[t][0]);
            acc[t][1] = ffma2(w2, h2f2(hv.y), acc[t][1]);
            acc[t][2] = ffma2(w2, h2f2(hv.z), acc[t][2]);
            acc[t][3] = ffma2(w2, h2f2(hv.w), acc[t][3]);
        }
    }
    #pragma unroll
    for (int t = 0; t < 4; t++) {
        #pragma unroll
        for (int j = 0; j < 4; j++) {
            float2 a = acc[t][j];
            #pragma unroll
            for (int off = 8; off <= 16; off <<= 1) {
                a.x += __shfl_xor_sync(0xffffffffu, a.x, off);
                a.y += __shfl_xor_sync(0xffffffffu, a.y, off);
            }
            acc[t][j] = a;
        }
        if (g == t) {
            uint4 pk;
            pk.x = pack2h(acc[t][0].x, acc[t][0].y);
            pk.y = pack2h(acc[t][1].x, acc[t][1].y);
            pk.z = pack2h(acc[t][2].x, acc[t][2].y);
            pk.w = pack2h(acc[t][3].x, acc[t][3].y);
            g_p2u4[((size_t)(c * 4 + t) * NN + n) * 8 + sub] = pk;
        }
    }
}

// ---------------- fused HMMA: h2+gi+GRU+classifier --------------------------
__global__ __launch_bounds__(256) void k_fused(const float* __restrict__ W2,
                                               const float* __restrict__ b2,
                                               const float* __restrict__ Wih,
                                               const float* __restrict__ bih,
                                               const float* __restrict__ Whh,
                                               const float* __restrict__ bhh,
                                               const float* __restrict__ Wc1,
                                               const float* __restrict__ bc1,
                                               const float* __restrict__ Wc2,
                                               const float* __restrict__ bc2,
                                               float* __restrict__ out) {
    extern __shared__ unsigned int smu[];
    unsigned int* W2f  = smu;                  // [0,2048)
    unsigned int* Wihf = smu + 2048;           // [2048,8192)
    unsigned int* Whhf = smu + 8192;           // [8192,14336)
    float2* B2f = (float2*)(smu + 14336);      // 256 f2 -> [14336,14848)
    float2* Brz = (float2*)(smu + 14848);      // 512 f2 -> [14848,15872)
    float2* Bin = (float2*)(smu + 15872);      // 256 f2 -> [15872,16384)
    float2* Bhn = (float2*)(smu + 16384);      // 256 f2 -> [16384,16896)
    unsigned int* Wc1f = smu + 16896;          // 1024 u32 -> [16896,17920)
    float2* Bc1f = (float2*)(smu + 17920);     // 128 f2 -> [17920,18176)
    float* w2s = (float*)(smu + 18176);        // 32 f  -> [18176,18208)
    int tid = threadIdx.x;

    // cleanup for next call (deterministic re-run)
    int gid = blockIdx.x * 256 + tid;
    if (gid < NN) { g_degi[gid] = 0; g_cursor[gid] = 0; }

    for (int i = tid; i < 4 * 8 * 32; i += 256) {
        int lane = i & 31, nt = (i >> 5) & 7, kt = i >> 8;
        int gq = lane >> 2, tq = lane & 3;
        int n = nt * 8 + gq, ks = kt * 16 + tq * 2;
        W2f[i * 2 + 0] = pack2h(W2[ks * 64 + n], W2[(ks + 1) * 64 + n]);
        W2f[i * 2 + 1] = pack2h(W2[(ks + 8) * 64 + n], W2[(ks + 9) * 64 + n]);
    }
    for (int i = tid; i < 4 * 24 * 32; i += 256) {
        int lane = i & 31, nt = (i >> 5) % 24, kt = i / (24 * 32);
        int gq = lane >> 2, tq = lane & 3;
        int gcol = nt * 8 + gq, ks = kt * 16 + tq * 2;
        Wihf[i * 2 + 0] = pack2h(Wih[gcol * 64 + ks], Wih[gcol * 64 + ks + 1]);
        Wihf[i * 2 + 1] = pack2h(Wih[gcol * 64 + ks + 8], Wih[gcol * 64 + ks + 9]);
        Whhf[i * 2 + 0] = pack2h(Whh[gcol * 64 + ks], Whh[gcol * 64 + ks + 1]);
        Whhf[i * 2 + 1] = pack2h(Whh[gcol * 64 + ks + 8], Whh[gcol * 64 + ks + 9]);
    }
    // Wc1 (64x32 row-major) B-frags: 4 ktiles x 4 ntiles
    for (int i = tid; i < 4 * 4 * 32; i += 256) {
        int lane = i & 31, nt = (i >> 5) & 3, kt = i >> 7;
        int gq = lane >> 2, tq = lane & 3;
        int n = nt * 8 + gq, ks = kt * 16 + tq * 2;
        Wc1f[i * 2 + 0] = pack2h(Wc1[ks * 32 + n], Wc1[(ks + 1) * 32 + n]);
        Wc1f[i * 2 + 1] = pack2h(Wc1[(ks + 8) * 32 + n], Wc1[(ks + 9) * 32 + n]);
    }
    for (int i = tid; i < 8 * 32; i += 256) {
        int lane = i & 31, nt = i >> 5, tq = lane & 3;
        B2f[i] = make_float2(b2[nt * 8 + tq * 2], b2[nt * 8 + tq * 2 + 1]);
        Bin[i] = make_float2(bih[128 + nt * 8 + tq * 2], bih[128 + nt * 8 + tq * 2 + 1]);
        Bhn[i] = make_float2(bhh[128 + nt * 8 + tq * 2], bhh[128 + nt * 8 + tq * 2 + 1]);
    }
    for (int i = tid; i < 16 * 32; i += 256) {
        int lane = i & 31, nt = i >> 5, tq = lane & 3;
        int k0 = nt * 8 + tq * 2;
        Brz[i] = make_float2(bih[k0] + bhh[k0], bih[k0 + 1] + bhh[k0 + 1]);
    }
    for (int i = tid; i < 4 * 32; i += 256) {
        int lane = i & 31, nt = i >> 5, tq = lane & 3;
        Bc1f[i] = make_float2(bc1[nt * 8 + tq * 2], bc1[nt * 8 + tq * 2 + 1]);
    }
    if (tid < 32) w2s[tid] = Wc2[tid];
    __syncthreads();

    int lane = tid & 31;
    int tile = blockIdx.x * 8 + (tid >> 5);
    if (tile >= NN / 16) return;
    int row0 = tile * 16;
    int gq = lane >> 2, tq = lane & 3;

    float hc[8][4];
    #pragma unroll
    for (int nt = 0; nt < 8; nt++)
        #pragma unroll
        for (int j = 0; j < 4; j++) hc[nt][j] = 0.f;

    for (int t = 0; t < TT; t++) {
        float dall[24][4];
        #pragma unroll
        for (int nt = 0; nt < 16; nt++) {
            float2 bb = Brz[nt * 32 + lane];
            dall[nt][0] = bb.x; dall[nt][1] = bb.y; dall[nt][2] = bb.x; dall[nt][3] = bb.y;
        }
        #pragma unroll
        for (int nt = 0; nt < 8; nt++) {
            float2 bb = Bhn[nt * 32 + lane];
            dall[16 + nt][0] = bb.x; dall[16 + nt][1] = bb.y;
            dall[16 + nt][2] = bb.x; dall[16 + nt][3] = bb.y;
        }
        if (t) {
            unsigned int Ah[4][4];
            #pragma unroll
            for (int kt = 0; kt < 4; kt++) {
                Ah[kt][0] = pack2h(hc[2 * kt][0], hc[2 * kt][1]);
                Ah[kt][1] = pack2h(hc[2 * kt][2], hc[2 * kt][3]);
                Ah[kt][2] = pack2h(hc[2 * kt + 1][0], hc[2 * kt + 1][1]);
                Ah[kt][3] = pack2h(hc[2 * kt + 1][2], hc[2 * kt + 1][3]);
            }
            #pragma unroll
            for (int kt = 0; kt < 4; kt++)
                #pragma unroll
                for (int nt = 0; nt < 24; nt++)
                    mma16816(dall[nt], Ah[kt], &Whhf[((kt * 24 + nt) * 32 + lane) * 2]);
        }
        unsigned int A[4][4];
        {
            const unsigned int* base0 = (const unsigned int*)(P2H + ((size_t)t * NN + row0 + gq) * 64);
            const unsigned int* base8 = base0 + 8 * 32;
            #pragma unroll
            for (int kt = 0; kt < 4; kt++) {
                A[kt][0] = base0[kt * 8 + tq];
                A[kt][1] = base8[kt * 8 + tq];
                A[kt][2] = base0[kt * 8 + tq + 4];
                A[kt][3] = base8[kt * 8 + tq + 4];
            }
        }
        float c[8][4];
        #pragma unroll
        for (int nt = 0; nt < 8; nt++) {
            float2 bb = B2f[nt * 32 + lane];
            c[nt][0] = bb.x; c[nt][1] = bb.y; c[nt][2] = bb.x; c[nt][3] = bb.y;
        }
        #pragma unroll
        for (int kt = 0; kt < 4; kt++)
            #pragma unroll
            for (int nt = 0; nt < 8; nt++)
                mma16816(c[nt], A[kt], &W2f[((kt * 8 + nt) * 32 + lane) * 2]);
        unsigned int A2[4][4];
        #pragma unroll
        for (int kt = 0; kt < 4; kt++) {
            A2[kt][0] = pack2h(fmaxf(c[2 * kt][0], 0.f), fmaxf(c[2 * kt][1], 0.f));
            A2[kt][1] = pack2h(fmaxf(c[2 * kt][2], 0.f), fmaxf(c[2 * kt][3], 0.f));
            A2[kt][2] = pack2h(fmaxf(c[2 * kt + 1][0], 0.f), fmaxf(c[2 * kt + 1][1], 0.f));
            A2[kt][3] = pack2h(fmaxf(c[2 * kt + 1][2], 0.f), fmaxf(c[2 * kt + 1][3], 0.f));
        }
        #pragma unroll
        for (int kt = 0; kt < 4; kt++)
            #pragma unroll
            for (int nt = 0; nt < 16; nt++)
                mma16816(dall[nt], A2[kt], &Wihf[((kt * 24 + nt) * 32 + lane) * 2]);
        float din[8][4];
        #pragma unroll
        for (int nt = 0; nt < 8; nt++) {
            float2 bb = Bin[nt * 32 + lane];
            din[nt][0] = bb.x; din[nt][1] = bb.y; din[nt][2] = bb.x; din[nt][3] = bb.y;
        }
        #pragma unroll
        for (int kt = 0; kt < 4; kt++)
            #pragma unroll
            for (int nt = 0; nt < 8; nt++)
                mma16816(din[nt], A2[kt], &Wihf[((kt * 24 + 16 + nt) * 32 + lane) * 2]);
        #pragma unroll
        for (int nt = 0; nt < 8; nt++) {
            #pragma unroll
            for (int j = 0; j < 4; j++) {
                float r = sigf(dall[nt][j]);
                float z = sigf(dall[nt + 8][j]);
                float n = tanhf(din[nt][j] + r * dall[nt + 16][j]);
                hc[nt][j] = (1.f - z) * n + z * hc[nt][j];
            }
        }
    }

    // ---- classifier: hidden = relu(h @ Wc1 + bc1); out = hidden @ Wc2 + bc2
    unsigned int Ah[4][4];
    #pragma unroll
    for (int kt = 0; kt < 4; kt++) {
        Ah[kt][0] = pack2h(hc[2 * kt][0], hc[2 * kt][1]);
        Ah[kt][1] = pack2h(hc[2 * kt][2], hc[2 * kt][3]);
        Ah[kt][2] = pack2h(hc[2 * kt + 1][0], hc[2 * kt + 1][1]);
        Ah[kt][3] = pack2h(hc[2 * kt + 1][2], hc[2 * kt + 1][3]);
    }
    float hid[4][4];
    #pragma unroll
    for (int nt = 0; nt < 4; nt++) {
        float2 bb = Bc1f[nt * 32 + lane];
        hid[nt][0] = bb.x; hid[nt][1] = bb.y; hid[nt][2] = bb.x; hid[nt][3] = bb.y;
    }
    #pragma unroll
    for (int kt = 0; kt < 4; kt++)
        #pragma unroll
        for (int nt = 0; nt < 4; nt++)
            mma16816(hid[nt], Ah[kt], &Wc1f[((kt * 4 + nt) * 32 + lane) * 2]);
    float p0 = 0.f, p8 = 0.f;
    #pragma unroll
    for (int nt = 0; nt < 4; nt++) {
        float w0 = w2s[nt * 8 + tq * 2], w1 = w2s[nt * 8 + tq * 2 + 1];
        p0 += fmaxf(hid[nt][0], 0.f) * w0 + fmaxf(hid[nt][1], 0.f) * w1;
        p8 += fmaxf(hid[nt][2], 0.f) * w0 + fmaxf(hid[nt][3], 0.f) * w1;
    }
    p0 += __shfl_xor_sync(0xffffffffu, p0, 1);
    p0 += __shfl_xor_sync(0xffffffffu, p0, 2);
    p8 += __shfl_xor_sync(0xffffffffu, p8, 1);
    p8 += __shfl_xor_sync(0xffffffffu, p8, 2);
    if (tq == 0) {
        float bv = bc2[0];
        out[row0 + gq] = p0 + bv;
        out[row0 + gq + 8] = p8 + bv;
    }
}

// ---------------- launch ----------------------------------------------------
extern "C" void kernel_launch(void* const* d_in, const int* in_sizes, int n_in,
                              void* d_out, int out_size) {
    const float* x   = (const float*)d_in[0];
    const int*   ei  = (const int*)d_in[1];
    const float* W1  = (const float*)d_in[2];
    const float* b1  = (const float*)d_in[3];
    const float* W2  = (const float*)d_in[4];
    const float* b2  = (const float*)d_in[5];
    const float* Wih = (const float*)d_in[6];
    const float* Whh = (const float*)d_in[7];
    const float* bih = (const float*)d_in[8];
    const float* bhh = (const float*)d_in[9];
    const float* Wc1 = (const float*)d_in[10];
    const float* bc1 = (const float*)d_in[11];
    const float* Wc2 = (const float*)d_in[12];
    const float* bc2 = (const float*)d_in[13];
    float* out = (float*)d_out;

    int E = in_sizes[1] / 2;
    const int* src = ei;
    const int* dst = ei + E;

    cudaFuncSetAttribute(k_fused, cudaFuncAttributeMaxDynamicSharedMemorySize, 73728);

    // preprocessing: degree count + x fp16 cvt (merged), hierarchical scan, CSR fill
    k_countcvt<<<(ROWS * FF / 4 + 255) / 256, 256>>>(dst, E, (const float4*)x);
    k_pre1<<<NB, 1024>>>();
    k_pre2<<<1, 32>>>();
    k_fill<<<(E + 255) / 256, 256>>>(src, dst, E);

    // fused agg32 + gemm1: h1 = relu((Ahat x) @ W1 + b1) -> fp16 H1H
    k_agg32f<<<dim3((NN / 4 + 7) / 8, 3), 256>>>(W1, b1);

    // layer 2: P2 = Ahat * h1 (3 t-chunks) -> fp16 P2H
    k_agg64<<<dim3(NN / 8, 3), 256>>>();

    // fused HMMA: h2 + gi + 12-step GRU + classifier -> out
    k_fused<<<(NN / 16 + 7) / 8, 256, 73728>>>(W2, b2, Wih, bih, Whh, bhh,
                                               Wc1, bc1, Wc2, bc2, out);
}

// round 11
// speedup vs baseline: 3.3743x; 1.0307x over previous
#include <cuda_runtime.h>
#include <cuda_fp16.h>
#include <math.h>

// Problem constants
constexpr int TT = 12;
constexpr int NN = 50000;
constexpr int FF = 32;
constexpr int HH = 64;
constexpr int EE = 1600000;
constexpr int ROWS = TT * NN;     // 600000
constexpr int NB = (NN + 1023) / 1024;   // 49 scan blocks

// ---------------- static device scratch (zero-initialized at load) ---------
__device__ int     g_degi[NN];
__device__ int     g_cursor[NN];
__device__ float   g_dinv[NN];
__device__ float   g_invdeg[NN];
__device__ int     g_rowptr[NN + 1];     // local (per-scan-block) prefix
__device__ int     g_bsum[64];
__device__ int     g_boff[64];
__device__ unsigned int g_epku[EE];                        // packed src:16 | w:fp16
__device__ uint4   g_xhu4[(size_t)ROWS * FF / 8];          // 38.4 MB x fp16
__device__ uint4   g_h1u4[(size_t)ROWS * HH / 8];          // 76.8 MB h1 fp16
__device__ uint4   g_p2u4[(size_t)ROWS * HH / 8];          // 76.8 MB P2 fp16

#define H1H  ((__half*)g_h1u4)
#define P2H  ((__half*)g_p2u4)

// ---------------- helpers ---------------------------------------------------
union F2U { float2 f; unsigned long long u; };
__device__ __forceinline__ float2 ffma2(float2 a, float2 b, float2 c) {
    F2U A, B, C, D; A.f = a; B.f = b; C.f = c;
    asm("fma.rn.f32x2 %0, %1, %2, %3;" : "=l"(D.u) : "l"(A.u), "l"(B.u), "l"(C.u));
    return D.f;
}
__device__ __forceinline__ float2 h2f2(unsigned int u) {
    __half2 h = *reinterpret_cast<const __half2*>(&u);
    return __half22float2(h);
}
__device__ __forceinline__ unsigned int pack2h(float a, float b) {
    __half2 h = __floats2half2_rn(a, b);
    return *reinterpret_cast<unsigned int*>(&h);
}
__device__ __forceinline__ float sigf(float x) { return 1.f / (1.f + expf(-x)); }

// m16n8k16 fp16 MMA, fp32 accumulate (A row-major, B col-major)
__device__ __forceinline__ void mma16816(float* c, const unsigned int* a, const unsigned int* b) {
    asm volatile(
        "mma.sync.aligned.m16n8k16.row.col.f32.f16.f16.f32 "
        "{%0,%1,%2,%3}, {%4,%5,%6,%7}, {%8,%9}, {%0,%1,%2,%3};\n"
        : "+f"(c[0]), "+f"(c[1]), "+f"(c[2]), "+f"(c[3])
        : "r"(a[0]), "r"(a[1]), "r"(a[2]), "r"(a[3]), "r"(b[0]), "r"(b[1]));
}

// ---------------- preprocessing --------------------------------------------
__global__ __launch_bounds__(256) void k_countcvt(const int* __restrict__ dst, int E,
                                                  const float4* __restrict__ x4) {
    unsigned int i = blockIdx.x * blockDim.x + threadIdx.x;
    if (i < (unsigned int)E) atomicAdd(&g_degi[dst[i]], 1);
    if (i < (unsigned int)(ROWS * FF / 4)) {
        float4 v = x4[i];
        ((uint2*)g_xhu4)[i] = make_uint2(pack2h(v.x, v.y), pack2h(v.z, v.w));
    }
}

__global__ void k_pre1() {
    __shared__ int wsum[32];
    int b = blockIdx.x, tid = threadIdx.x, lane = tid & 31, wid = tid >> 5;
    int idx = b * 1024 + tid;
    int v = (idx < NN) ? g_degi[idx] : 0;
    int x = v;
    #pragma unroll
    for (int o = 1; o < 32; o <<= 1) {
        int y = __shfl_up_sync(0xffffffffu, x, o);
        if (lane >= o) x += y;
    }
    if (lane == 31) wsum[wid] = x;
    __syncthreads();
    if (wid == 0) {
        int w = wsum[lane];
        int xw = w;
        #pragma unroll
        for (int o = 1; o < 32; o <<= 1) {
            int y = __shfl_up_sync(0xffffffffu, xw, o);
            if (lane >= o) xw += y;
        }
        wsum[lane] = xw - w;
    }
    __syncthreads();
    int excl = wsum[wid] + x - v;
    if (idx < NN) {
        g_rowptr[idx] = excl;
        float deg = (float)v + 1.0f;
        g_dinv[idx] = rsqrtf(deg);
        g_invdeg[idx] = 1.0f / deg;
    }
    if (tid == 1023) g_bsum[b] = excl + v;
}

__global__ void k_pre2() {
    int l = threadIdx.x;   // 32 threads
    int a = (l < NB) ? g_bsum[l] : 0;
    int xa = a;
    #pragma unroll
    for (int o = 1; o < 32; o <<= 1) {
        int y = __shfl_up_sync(0xffffffffu, xa, o);
        if (l >= o) xa += y;
    }
    int totalA = __shfl_sync(0xffffffffu, xa, 31);
    int b2 = (l + 32 < NB) ? g_bsum[l + 32] : 0;
    int xb = b2;
    #pragma unroll
    for (int o = 1; o < 32; o <<= 1) {
        int y = __shfl_up_sync(0xffffffffu, xb, o);
        if (l >= o) xb += y;
    }
    g_boff[l] = xa - a;
    if (l + 32 < NB + 1) g_boff[l + 32] = totalA + xb - b2;
    if (l == 0) g_rowptr[NN] = g_bsum[NB - 1];
}

__global__ void k_fill(const int* __restrict__ src, const int* __restrict__ dst, int E) {
    int e = blockIdx.x * blockDim.x + threadIdx.x;
    if (e < E) {
        int s = src[e], d = dst[e];
        float w = g_dinv[s] * g_dinv[d];
        int pos = g_rowptr[d] + g_boff[d >> 10] + atomicAdd(&g_cursor[d], 1);
        unsigned short ws = __half_as_ushort(__float2half_rn(w));
        g_epku[pos] = (unsigned int)s | ((unsigned int)ws << 16);
    }
}

__device__ __forceinline__ void decode_edge(unsigned int e, int& ss, float& ww) {
    ss = (int)(e & 0xFFFFu);
    ww = __half2float(__ushort_as_half((unsigned short)(e >> 16)));
}

// ---------------- fused agg32 + gemm1: h1 = relu((Ahat x) @ W1 + b1) --------
// warp = 4 nodes x 4 t (one m16 tile). Edge gather per node, xor-reduce,
// park rows in smem, one HMMA pass with W1, write h1 fp16 directly.
__global__ __launch_bounds__(256) void k_agg32f(const float* __restrict__ W,
                                                const float* __restrict__ b) {
    __shared__ unsigned int Wf[2 * 8 * 32 * 2];      // 4 KB  W1 B-frags
    __shared__ float2 Bf[8 * 32];                    // 2 KB  b1 frags
    __shared__ unsigned int Arows[8][16][16];        // 8 KB  16 rows x 32 fp16 per warp
    int tid = threadIdx.x;
    for (int i = tid; i < 2 * 8 * 32; i += 256) {
        int lane = i & 31, nt = (i >> 5) & 7, kt = i >> 8;
        int gq = lane >> 2, tq = lane & 3;
        int n = nt * 8 + gq, ks = kt * 16 + tq * 2;
        Wf[i * 2 + 0] = pack2h(W[ks * 64 + n], W[(ks + 1) * 64 + n]);
        Wf[i * 2 + 1] = pack2h(W[(ks + 8) * 64 + n], W[(ks + 9) * 64 + n]);
    }
    for (int i = tid; i < 8 * 32; i += 256) {
        int lane = i & 31, nt = i >> 5, tq = lane & 3;
        Bf[i] = make_float2(b[nt * 8 + tq * 2], b[nt * 8 + tq * 2 + 1]);
    }
    __syncthreads();

    int lane = tid & 31, wid = tid >> 5;
    int c = blockIdx.y;                              // t-chunk 0..2
    int quad = blockIdx.x * 8 + wid;
    if (quad >= NN / 4) return;
    int n0 = quad * 4;
    int g = lane >> 2, sub = lane & 3;
    const uint4* __restrict__ x4 = g_xhu4 + (size_t)(c * 4) * NN * 4 + sub;

    for (int r = 0; r < 4; r++) {
        int n = n0 + r;
        int r0 = g_rowptr[n] + g_boff[n >> 10];
        int r1 = g_rowptr[n + 1] + g_boff[(n + 1) >> 10];
        float2 acc[4][4];
        #pragma unroll
        for (int t = 0; t < 4; t++)
            #pragma unroll
            for (int j = 0; j < 4; j++) acc[t][j] = make_float2(0.f, 0.f);
        unsigned int ep = (r0 + lane < r1) ? g_epku[r0 + lane] : 0u;
        for (int tile = r0; tile < r1; tile += 32) {
            unsigned int epc = ep;
            int nxt = tile + 32;
            if (nxt < r1) ep = (nxt + lane < r1) ? g_epku[nxt + lane] : 0u;
            int nb = r1 - tile; if (nb > 32) nb = 32;
            for (int bb = 0; bb * 8 < nb; bb++) {
                unsigned int e = __shfl_sync(0xffffffffu, epc, bb * 8 + g);
                int ss; float ww; decode_edge(e, ss, ww);
                float2 w2 = make_float2(ww, ww);
                const uint4* p = x4 + (size_t)ss * 4;
                #pragma unroll
                for (int t = 0; t < 4; t++) {
                    uint4 v = p[(size_t)t * (NN * 4)];
                    acc[t][0] = ffma2(w2, h2f2(v.x), acc[t][0]);
                    acc[t][1] = ffma2(w2, h2f2(v.y), acc[t][1]);
                    acc[t][2] = ffma2(w2, h2f2(v.z), acc[t][2]);
                    acc[t][3] = ffma2(w2, h2f2(v.w), acc[t][3]);
                }
            }
        }
        if (g == 0) {   // self-loop
            float id = g_invdeg[n];
            float2 w2 = make_float2(id, id);
            const uint4* p = x4 + (size_t)n * 4;
            #pragma unroll
            for (int t = 0; t < 4; t++) {
                uint4 v = p[(size_t)t * (NN * 4)];
                acc[t][0] = ffma2(w2, h2f2(v.x), acc[t][0]);
                acc[t][1] = ffma2(w2, h2f2(v.y), acc[t][1]);
                acc[t][2] = ffma2(w2, h2f2(v.z), acc[t][2]);
                acc[t][3] = ffma2(w2, h2f2(v.w), acc[t][3]);
            }
        }
        #pragma unroll
        for (int t = 0; t < 4; t++) {
            #pragma unroll
            for (int j = 0; j < 4; j++) {
                float2 a = acc[t][j];
                #pragma unroll
                for (int off = 4; off <= 16; off <<= 1) {
                    a.x += __shfl_xor_sync(0xffffffffu, a.x, off);
                    a.y += __shfl_xor_sync(0xffffffffu, a.y, off);
                }
                if (g == t) Arows[wid][t * 4 + r][sub * 4 + j] = pack2h(a.x, a.y);
            }
        }
    }
    __syncwarp();

    // HMMA: h1 = relu(A @ W1 + b1), A = 16 rows x 32 feats from smem
    int gq = lane >> 2, tq = lane & 3;
    unsigned int A[2][4];
    #pragma unroll
    for (int kt = 0; kt < 2; kt++) {
        A[kt][0] = Arows[wid][gq][kt * 8 + tq];
        A[kt][1] = Arows[wid][gq + 8][kt * 8 + tq];
        A[kt][2] = Arows[wid][gq][kt * 8 + tq + 4];
        A[kt][3] = Arows[wid][gq + 8][kt * 8 + tq + 4];
    }
    float cc[8][4];
    #pragma unroll
    for (int nt = 0; nt < 8; nt++) {
        float2 bb = Bf[nt * 32 + lane];
        cc[nt][0] = bb.x; cc[nt][1] = bb.y; cc[nt][2] = bb.x; cc[nt][3] = bb.y;
    }
    #pragma unroll
    for (int kt = 0; kt < 2; kt++)
        #pragma unroll
        for (int nt = 0; nt < 8; nt++)
            mma16816(cc[nt], A[kt], &Wf[((kt * 8 + nt) * 32 + lane) * 2]);
    int t0 = gq >> 2, ri = gq & 3;
    unsigned int* o0 = (unsigned int*)(H1H + ((size_t)(c * 4 + t0) * NN + n0 + ri) * 64);
    unsigned int* o8 = (unsigned int*)(H1H + ((size_t)(c * 4 + t0 + 2) * NN + n0 + ri) * 64);
    #pragma unroll
    for (int nt = 0; nt < 8; nt++) {
        o0[nt * 4 + tq] = pack2h(fmaxf(cc[nt][0], 0.f), fmaxf(cc[nt][1], 0.f));
        o8[nt * 4 + tq] = pack2h(fmaxf(cc[nt][2], 0.f), fmaxf(cc[nt][3], 0.f));
    }
}

// ---------------- aggregation layer 2: fp16 in/out, 2 t per slice -----------
// 6 chunks: fewer regs, 2x warps in flight vs 4t version.
__global__ __launch_bounds__(256) void k_agg64() {
    int lane = threadIdx.x & 31;
    int n = blockIdx.x * 8 + (threadIdx.x >> 5);
    if (n >= NN) return;
    int c = blockIdx.y;                                  // 0..5
    int g = lane >> 3, sub = lane & 7;
    int r0 = g_rowptr[n] + g_boff[n >> 10];
    int r1 = g_rowptr[n + 1] + g_boff[(n + 1) >> 10];
    const uint4* __restrict__ hb = g_h1u4 + (size_t)(c * 2) * NN * 8 + sub;
    float2 acc[2][4];
    #pragma unroll
    for (int t = 0; t < 2; t++)
        #pragma unroll
        for (int j = 0; j < 4; j++) acc[t][j] = make_float2(0.f, 0.f);
    unsigned int ep = (r0 + lane < r1) ? g_epku[r0 + lane] : 0u;
    for (int tile = r0; tile < r1; tile += 32) {
        unsigned int epc = ep;
        int nxt = tile + 32;
        if (nxt < r1) ep = (nxt + lane < r1) ? g_epku[nxt + lane] : 0u;
        int nb = r1 - tile; if (nb > 32) nb = 32;
        for (int b = 0; b * 4 < nb; b++) {
            unsigned int e = __shfl_sync(0xffffffffu, epc, b * 4 + g);
            int ss; float ww; decode_edge(e, ss, ww);
            float2 w2 = make_float2(ww, ww);
            const uint4* p = hb + (size_t)ss * 8;
            #pragma unroll
            for (int t = 0; t < 2; t++) {
                uint4 hv = p[(size_t)t * (NN * 8)];
                acc[t][0] = ffma2(w2, h2f2(hv.x), acc[t][0]);
                acc[t][1] = ffma2(w2, h2f2(hv.y), acc[t][1]);
                acc[t][2] = ffma2(w2, h2f2(hv.z), acc[t][2]);
                acc[t][3] = ffma2(w2, h2f2(hv.w), acc[t][3]);
            }
        }
    }
    if (g == 0) {
        float id = g_invdeg[n];
        float2 w2 = make_float2(id, id);
        const uint4* p = hb + (size_t)n * 8;
        #pragma unroll
        for (int t = 0; t < 2; t++) {
            uint4 hv = p[(size_t)t * (NN * 8)];
            acc[t][0] = ffma2(w2, h2f2(hv.x), acc[t][0]);
            acc[t][1] = ffma2(w2, h2f2(hv.y), acc[t][1]);
            acc[t][2] = ffma2(w2, h2f2(hv.z), acc[t][2]);
            acc[t][3] = ffma2(w2, h2f2(hv.w), acc[t][3]);
        }
    }
    #pragma unroll
    for (int t = 0; t < 2; t++) {
        #pragma unroll
        for (int j = 0; j < 4; j++) {
            float2 a = acc[t][j];
            #pragma unroll
            for (int off = 8; off <= 16; off <<= 1) {
                a.x += __shfl_xor_sync(0xffffffffu, a.x, off);
                a.y += __shfl_xor_sync(0xffffffffu, a.y, off);
            }
            acc[t][j] = a;
        }
        if (g == t) {
            uint4 pk;
            pk.x = pack2h(acc[t][0].x, acc[t][0].y);
            pk.y = pack2h(acc[t][1].x, acc[t][1].y);
            pk.z = pack2h(acc[t][2].x, acc[t][2].y);
            pk.w = pack2h(acc[t][3].x, acc[t][3].y);
            g_p2u4[((size_t)(c * 2 + t) * NN + n) * 8 + sub] = pk;
        }
    }
}

// ---------------- fused HMMA: h2+gi+GRU+classifier --------------------------
__global__ __launch_bounds__(256) void k_fused(const float* __restrict__ W2,
                                               const float* __restrict__ b2,
                                               const float* __restrict__ Wih,
                                               const float* __restrict__ bih,
                                               const float* __restrict__ Whh,
                                               const float* __restrict__ bhh,
                                               const float* __restrict__ Wc1,
                                               const float* __restrict__ bc1,
                                               const float* __restrict__ Wc2,
                                               const float* __restrict__ bc2,
                                               float* __restrict__ out) {
    extern __shared__ unsigned int smu[];
    unsigned int* W2f  = smu;                  // [0,2048)
    unsigned int* Wihf = smu + 2048;           // [2048,8192)
    unsigned int* Whhf = smu + 8192;           // [8192,14336)
    float2* B2f = (float2*)(smu + 14336);      // [14336,14848)
    float2* Brz = (float2*)(smu + 14848);      // [14848,15872)
    float2* Bin = (float2*)(smu + 15872);      // [15872,16384)
    float2* Bhn = (float2*)(smu + 16384);      // [16384,16896)
    unsigned int* Wc1f = smu + 16896;          // [16896,17920)
    float2* Bc1f = (float2*)(smu + 17920);     // [17920,18176)
    float* w2s = (float*)(smu + 18176);        // [18176,18208)
    int tid = threadIdx.x;

    int gid = blockIdx.x * 256 + tid;
    if (gid < NN) { g_degi[gid] = 0; g_cursor[gid] = 0; }

    for (int i = tid; i < 4 * 8 * 32; i += 256) {
        int lane = i & 31, nt = (i >> 5) & 7, kt = i >> 8;
        int gq = lane >> 2, tq = lane & 3;
        int n = nt * 8 + gq, ks = kt * 16 + tq * 2;
        W2f[i * 2 + 0] = pack2h(W2[ks * 64 + n], W2[(ks + 1) * 64 + n]);
        W2f[i * 2 + 1] = pack2h(W2[(ks + 8) * 64 + n], W2[(ks + 9) * 64 + n]);
    }
    for (int i = tid; i < 4 * 24 * 32; i += 256) {
        int lane = i & 31, nt = (i >> 5) % 24, kt = i / (24 * 32);
        int gq = lane >> 2, tq = lane & 3;
        int gcol = nt * 8 + gq, ks = kt * 16 + tq * 2;
        Wihf[i * 2 + 0] = pack2h(Wih[gcol * 64 + ks], Wih[gcol * 64 + ks + 1]);
        Wihf[i * 2 + 1] = pack2h(Wih[gcol * 64 + ks + 8], Wih[gcol * 64 + ks + 9]);
        Whhf[i * 2 + 0] = pack2h(Whh[gcol * 64 + ks], Whh[gcol * 64 + ks + 1]);
        Whhf[i * 2 + 1] = pack2h(Whh[gcol * 64 + ks + 8], Whh[gcol * 64 + ks + 9]);
    }
    for (int i = tid; i < 4 * 4 * 32; i += 256) {
        int lane = i & 31, nt = (i >> 5) & 3, kt = i >> 7;
        int gq = lane >> 2, tq = lane & 3;
        int n = nt * 8 + gq, ks = kt * 16 + tq * 2;
        Wc1f[i * 2 + 0] = pack2h(Wc1[ks * 32 + n], Wc1[(ks + 1) * 32 + n]);
        Wc1f[i * 2 + 1] = pack2h(Wc1[(ks + 8) * 32 + n], Wc1[(ks + 9) * 32 + n]);
    }
    for (int i = tid; i < 8 * 32; i += 256) {
        int lane = i & 31, nt = i >> 5, tq = lane & 3;
        B2f[i] = make_float2(b2[nt * 8 + tq * 2], b2[nt * 8 + tq * 2 + 1]);
        Bin[i] = make_float2(bih[128 + nt * 8 + tq * 2], bih[128 + nt * 8 + tq * 2 + 1]);
        Bhn[i] = make_float2(bhh[128 + nt * 8 + tq * 2], bhh[128 + nt * 8 + tq * 2 + 1]);
    }
    for (int i = tid; i < 16 * 32; i += 256) {
        int lane = i & 31, nt = i >> 5, tq = lane & 3;
        int k0 = nt * 8 + tq * 2;
        Brz[i] = make_float2(bih[k0] + bhh[k0], bih[k0 + 1] + bhh[k0 + 1]);
    }
    for (int i = tid; i < 4 * 32; i += 256) {
        int lane = i & 31, nt = i >> 5, tq = lane & 3;
        Bc1f[i] = make_float2(bc1[nt * 8 + tq * 2], bc1[nt * 8 + tq * 2 + 1]);
    }
    if (tid < 32) w2s[tid] = Wc2[tid];
    __syncthreads();

    int lane = tid & 31;
    int tile = blockIdx.x * 8 + (tid >> 5);
    if (tile >= NN / 16) return;
    int row0 = tile * 16;
    int gq = lane >> 2, tq = lane & 3;

    float hc[8][4];
    #pragma unroll
    for (int nt = 0; nt < 8; nt++)
        #pragma unroll
        for (int j = 0; j < 4; j++) hc[nt][j] = 0.f;

    for (int t = 0; t < TT; t++) {
        float dall[24][4];
        #pragma unroll
        for (int nt = 0; nt < 16; nt++) {
            float2 bb = Brz[nt * 32 + lane];
            dall[nt][0] = bb.x; dall[nt][1] = bb.y; dall[nt][2] = bb.x; dall[nt][3] = bb.y;
        }
        #pragma unroll
        for (int nt = 0; nt < 8; nt++) {
            float2 bb = Bhn[nt * 32 + lane];
            dall[16 + nt][0] = bb.x; dall[16 + nt][1] = bb.y;
            dall[16 + nt][2] = bb.x; dall[16 + nt][3] = bb.y;
        }
        if (t) {
            unsigned int Ah[4][4];
            #pragma unroll
            for (int kt = 0; kt < 4; kt++) {
                Ah[kt][0] = pack2h(hc[2 * kt][0], hc[2 * kt][1]);
                Ah[kt][1] = pack2h(hc[2 * kt][2], hc[2 * kt][3]);
                Ah[kt][2] = pack2h(hc[2 * kt + 1][0], hc[2 * kt + 1][1]);
                Ah[kt][3] = pack2h(hc[2 * kt + 1][2], hc[2 * kt + 1][3]);
            }
            #pragma unroll
            for (int kt = 0; kt < 4; kt++)
                #pragma unroll
                for (int nt = 0; nt < 24; nt++)
                    mma16816(dall[nt], Ah[kt], &Whhf[((kt * 24 + nt) * 32 + lane) * 2]);
        }
        unsigned int A[4][4];
        {
            const unsigned int* base0 = (const unsigned int*)(P2H + ((size_t)t * NN + row0 + gq) * 64);
            const unsigned int* base8 = base0 + 8 * 32;
            #pragma unroll
            for (int kt = 0; kt < 4; kt++) {
                A[kt][0] = base0[kt * 8 + tq];
                A[kt][1] = base8[kt * 8 + tq];
                A[kt][2] = base0[kt * 8 + tq + 4];
                A[kt][3] = base8[kt * 8 + tq + 4];
            }
        }
        float c[8][4];
        #pragma unroll
        for (int nt = 0; nt < 8; nt++) {
            float2 bb = B2f[nt * 32 + lane];
            c[nt][0] = bb.x; c[nt][1] = bb.y; c[nt][2] = bb.x; c[nt][3] = bb.y;
        }
        #pragma unroll
        for (int kt = 0; kt < 4; kt++)
            #pragma unroll
            for (int nt = 0; nt < 8; nt++)
                mma16816(c[nt], A[kt], &W2f[((kt * 8 + nt) * 32 + lane) * 2]);
        unsigned int A2[4][4];
        #pragma unroll
        for (int kt = 0; kt < 4; kt++) {
            A2[kt][0] = pack2h(fmaxf(c[2 * kt][0], 0.f), fmaxf(c[2 * kt][1], 0.f));
            A2[kt][1] = pack2h(fmaxf(c[2 * kt][2], 0.f), fmaxf(c[2 * kt][3], 0.f));
            A2[kt][2] = pack2h(fmaxf(c[2 * kt + 1][0], 0.f), fmaxf(c[2 * kt + 1][1], 0.f));
            A2[kt][3] = pack2h(fmaxf(c[2 * kt + 1][2], 0.f), fmaxf(c[2 * kt + 1][3], 0.f));
        }
        #pragma unroll
        for (int kt = 0; kt < 4; kt++)
            #pragma unroll
            for (int nt = 0; nt < 16; nt++)
                mma16816(dall[nt], A2[kt], &Wihf[((kt * 24 + nt) * 32 + lane) * 2]);
        float din[8][4];
        #pragma unroll
        for (int nt = 0; nt < 8; nt++) {
            float2 bb = Bin[nt * 32 + lane];
            din[nt][0] = bb.x; din[nt][1] = bb.y; din[nt][2] = bb.x; din[nt][3] = bb.y;
        }
        #pragma unroll
        for (int kt = 0; kt < 4; kt++)
            #pragma unroll
            for (int nt = 0; nt < 8; nt++)
                mma16816(din[nt], A2[kt], &Wihf[((kt * 24 + 16 + nt) * 32 + lane) * 2]);
        #pragma unroll
        for (int nt = 0; nt < 8; nt++) {
            #pragma unroll
            for (int j = 0; j < 4; j++) {
                float r = sigf(dall[nt][j]);
                float z = sigf(dall[nt + 8][j]);
                float n = tanhf(din[nt][j] + r * dall[nt + 16][j]);
                hc[nt][j] = (1.f - z) * n + z * hc[nt][j];
            }
        }
    }

    // ---- classifier
    unsigned int Ah[4][4];
    #pragma unroll
    for (int kt = 0; kt < 4; kt++) {
        Ah[kt][0] = pack2h(hc[2 * kt][0], hc[2 * kt][1]);
        Ah[kt][1] = pack2h(hc[2 * kt][2], hc[2 * kt][3]);
        Ah[kt][2] = pack2h(hc[2 * kt + 1][0], hc[2 * kt + 1][1]);
        Ah[kt][3] = pack2h(hc[2 * kt + 1][2], hc[2 * kt + 1][3]);
    }
    float hid[4][4];
    #pragma unroll
    for (int nt = 0; nt < 4; nt++) {
        float2 bb = Bc1f[nt * 32 + lane];
        hid[nt][0] = bb.x; hid[nt][1] = bb.y; hid[nt][2] = bb.x; hid[nt][3] = bb.y;
    }
    #pragma unroll
    for (int kt = 0; kt < 4; kt++)
        #pragma unroll
        for (int nt = 0; nt < 4; nt++)
            mma16816(hid[nt], Ah[kt], &Wc1f[((kt * 4 + nt) * 32 + lane) * 2]);
    float p0 = 0.f, p8 = 0.f;
    #pragma unroll
    for (int nt = 0; nt < 4; nt++) {
        float w0 = w2s[nt * 8 + tq * 2], w1 = w2s[nt * 8 + tq * 2 + 1];
        p0 += fmaxf(hid[nt][0], 0.f) * w0 + fmaxf(hid[nt][1], 0.f) * w1;
        p8 += fmaxf(hid[nt][2], 0.f) * w0 + fmaxf(hid[nt][3], 0.f) * w1;
    }
    p0 += __shfl_xor_sync(0xffffffffu, p0, 1);
    p0 += __shfl_xor_sync(0xffffffffu, p0, 2);
    p8 += __shfl_xor_sync(0xffffffffu, p8, 1);
    p8 += __shfl_xor_sync(0xffffffffu, p8, 2);
    if (tq == 0) {
        float bv = bc2[0];
        out[row0 + gq] = p0 + bv;
        out[row0 + gq + 8] = p8 + bv;
    }
}

// ---------------- launch ----------------------------------------------------
extern "C" void kernel_launch(void* const* d_in, const int* in_sizes, int n_in,
                              void* d_out, int out_size) {
    const float* x   = (const float*)d_in[0];
    const int*   ei  = (const int*)d_in[1];
    const float* W1  = (const float*)d_in[2];
    const float* b1  = (const float*)d_in[3];
    const float* W2  = (const float*)d_in[4];
    const float* b2  = (const float*)d_in[5];
    const float* Wih = (const float*)d_in[6];
    const float* Whh = (const float*)d_in[7];
    const float* bih = (const float*)d_in[8];
    const float* bhh = (const float*)d_in[9];
    const float* Wc1 = (const float*)d_in[10];
    const float* bc1 = (const float*)d_in[11];
    const float* Wc2 = (const float*)d_in[12];
    const float* bc2 = (const float*)d_in[13];
    float* out = (float*)d_out;

    int E = in_sizes[1] / 2;
    const int* src = ei;
    const int* dst = ei + E;

    cudaFuncSetAttribute(k_fused, cudaFuncAttributeMaxDynamicSharedMemorySize, 73728);

    // preprocessing: degree count + x fp16 cvt (merged), hierarchical scan, CSR fill
    k_countcvt<<<(ROWS * FF / 4 + 255) / 256, 256>>>(dst, E, (const float4*)x);
    k_pre1<<<NB, 1024>>>();
    k_pre2<<<1, 32>>>();
    k_fill<<<(E + 255) / 256, 256>>>(src, dst, E);

    // fused agg32 + gemm1: h1 = relu((Ahat x) @ W1 + b1) -> fp16 H1H
    k_agg32f<<<dim3((NN / 4 + 7) / 8, 3), 256>>>(W1, b1);

    // layer 2: P2 = Ahat * h1 (6 chunks of 2 t) -> fp16 P2H
    k_agg64<<<dim3(NN / 8, 6), 256>>>();

    // fused HMMA: h2 + gi + 12-step GRU + classifier -> out
    k_fused<<<(NN / 16 + 7) / 8, 256, 73728>>>(W2, b2, Wih, bih, Whh, bhh,
                                               Wc1, bc1, Wc2, bc2, out);
}